// round 7
// baseline (speedup 1.0000x reference)
#include <cuda_runtime.h>
#include <cstdint>
#include <math.h>

// ---------------- constants ----------------
#define PI_F      3.14159265358979323846f
#define PI2_F     9.86960440108935861883f
#define THIRD_F   2.09439510239319549231f
#define DEVPI_F   0.003183098861837907f
#define SQRTD_F   22.62741699796952f

constexpr int S  = 512;
constexpr int D  = 512;
constexpr int H  = 8;
constexpr int DH = 64;
constexpr int L  = 6;
constexpr int F  = 2048;
constexpr int BB = 16;
constexpr int MT = BB * S;   // 8192 tokens
constexpr int BH = BB * H;   // 128
constexpr int NSLOT = 18;
constexpr size_t SLOT_STRIDE = 1048576;
constexpr int VMAX = 10240;

// Feature gate: tcgen05 only exists on arch-specific (sm_103a) / family (sm_103f) targets.
#if !defined(__CUDA_ARCH__) || defined(__CUDA_ARCH_FEAT_SM103_ALL) || defined(__CUDA_ARCH_SPECIFIC__) || defined(__CUDA_ARCH_FAMILY_SPECIFIC__)
#define TC_AVAIL 1
#else
#define TC_AVAIL 0
#endif

// ---------------- device scratch ----------------
__device__ __align__(128) float d_x   [MT * D];
__device__ __align__(128) float d_xtf [MT * D];
__device__ __align__(128) float d_qkv [MT * 3 * D];
__device__ __align__(128) float d_ao  [MT * D];
__device__ __align__(128) float d_ff  [MT * F];
__device__ __align__(128) float d_tmp [MT * D];
__device__ __align__(128) float d_wp  [NSLOT * SLOT_STRIDE];
__device__ __align__(128) float d_wr  [L * D * D];
__device__ __align__(128) float d_owr [VMAX * D];
__device__ __align__(128) float d_abs_all[NSLOT * SLOT_STRIDE];
__device__ unsigned d_h1g[NSLOT * 4096];
__device__ unsigned d_h2g[NSLOT * 2 * 65536];
__device__ unsigned d_h3g[NSLOT * 32];
__device__ unsigned d_selg[NSLOT * 8];
__device__ float d_thrg[NSLOT];

// ---------------- helpers ----------------
__device__ __forceinline__ float tf32r(float f) {
    uint32_t u;
    asm("cvt.rna.tf32.f32 %0, %1;" : "=r"(u) : "f"(f));
    return __uint_as_float(u);
}

__device__ __forceinline__ void mma_tf32(float c[4],
    uint32_t a0, uint32_t a1, uint32_t a2, uint32_t a3,
    uint32_t b0, uint32_t b1)
{
    asm volatile(
        "mma.sync.aligned.m16n8k8.row.col.f32.tf32.tf32.f32 "
        "{%0,%1,%2,%3}, {%4,%5,%6,%7}, {%8,%9}, {%0,%1,%2,%3};"
        : "+f"(c[0]), "+f"(c[1]), "+f"(c[2]), "+f"(c[3])
        : "r"(a0), "r"(a1), "r"(a2), "r"(a3), "r"(b0), "r"(b1));
}

__device__ __forceinline__ void cp16(void* d, const void* s) {
    uint32_t a = (uint32_t)__cvta_generic_to_shared(d);
    asm volatile("cp.async.cg.shared.global [%0], [%1], 16;" :: "r"(a), "l"(s));
}
__device__ __forceinline__ void cp16p(void* d, const void* s, bool p) {
    uint32_t a = (uint32_t)__cvta_generic_to_shared(d);
    int sz = p ? 16 : 0;
    asm volatile("cp.async.cg.shared.global [%0], [%1], 16, %2;" :: "r"(a), "l"(s), "r"(sz));
}
#define CP_COMMIT() asm volatile("cp.async.commit_group;")
#define CP_WAIT0()  asm volatile("cp.async.wait_group 0;")
#define CP_WAIT1()  asm volatile("cp.async.wait_group 1;")
#define CP_WAIT2()  asm volatile("cp.async.wait_group 2;")

// ================= tcgen05 2CTA tf32 GEMM (guarded) =================
// Cluster pair computes a 256(M) x 256(N) tile; each CTA holds 128 A-rows and
// 128 B-rows; tcgen05.mma.cta_group::2 reads both CTAs' smem halves.
constexpr int T2_NS  = 4;
constexpr int T2_ASZ = 128 * 32 * 4;   // 16 KB per stage
constexpr int T2_BSZ = 128 * 32 * 4;   // 16 KB per stage
constexpr int T2_AOFF = 1024;
constexpr int T2_BOFF = 1024 + T2_NS * T2_ASZ;   // 66560
constexpr int T2_SMEM = T2_BOFF + T2_NS * T2_BSZ; // 132096

#if TC_AVAIL
__device__ __forceinline__ uint32_t elect1() {
    uint32_t pred;
    asm volatile("{\n\t.reg .pred p;\n\telect.sync _|p, 0xFFFFFFFF;\n\t"
                 "selp.b32 %0, 1, 0, p;\n\t}" : "=r"(pred));
    return pred;
}
__device__ __forceinline__ uint32_t ctarank() {
    uint32_t r;
    asm("mov.u32 %0, %%cluster_ctarank;" : "=r"(r));
    return r;
}
#define MBAR_INIT(addr, cnt) \
    asm volatile("mbarrier.init.shared.b64 [%0], %1;" :: "r"(addr), "r"(cnt) : "memory")
#define MBAR_WAIT(addr, par) do { \
    asm volatile("{\n\t.reg .pred P1;\n\tWL%=:\n\t" \
        "mbarrier.try_wait.parity.acquire.cta.shared::cta.b64 P1, [%0], %1, 0x989680;\n\t" \
        "@P1 bra.uni WD%=;\n\tbra.uni WL%=;\n\tWD%=:\n\t}" \
        :: "r"(addr), "r"(par) : "memory"); \
} while (0)
#define MBAR_WAIT_CL(addr, par) do { \
    asm volatile("{\n\t.reg .pred P1;\n\tWL%=:\n\t" \
        "mbarrier.try_wait.parity.acquire.cluster.shared::cta.b64 P1, [%0], %1, 0x989680;\n\t" \
        "@P1 bra.uni WD%=;\n\tbra.uni WL%=;\n\tWD%=:\n\t}" \
        :: "r"(addr), "r"(par) : "memory"); \
} while (0)
#define MBAR_ARRIVE_RANK(addr, rnk) \
    asm volatile("{\n\t.reg .b32 ra;\n\tmapa.shared::cluster.u32 ra, %0, %1;\n\t" \
        "mbarrier.arrive.release.cluster.shared::cluster.b64 _, [ra];\n\t}" \
        :: "r"(addr), "r"(rnk) : "memory")
#define CLUSTER_SYNC() do { \
    asm volatile("barrier.cluster.arrive.aligned;" ::: "memory"); \
    asm volatile("barrier.cluster.wait.aligned;" ::: "memory"); \
} while (0)
#define TC_ALLOC_CG2(sm, n)  asm volatile("tcgen05.alloc.cta_group::2.sync.aligned.shared::cta.b32 [%0], %1;" :: "r"(sm), "r"(n) : "memory")
#define TC_DEALLOC_CG2(t, n) asm volatile("tcgen05.dealloc.cta_group::2.sync.aligned.b32 %0, %1;" :: "r"(t), "r"(n))
#define TC_RELQ_CG2()        asm volatile("tcgen05.relinquish_alloc_permit.cta_group::2.sync.aligned;")
#define TC_COMMIT_MC_CG2(mb, mask) \
    asm volatile("tcgen05.commit.cta_group::2.mbarrier::arrive::one.shared::cluster.multicast::cluster.b64 [%0], %1;" \
        :: "r"(mb), "h"((uint16_t)(mask)) : "memory")
#define TC_FENCE_AFTER()  asm volatile("tcgen05.fence::after_thread_sync;" ::: "memory")
#define TC_FENCE_BEFORE() asm volatile("tcgen05.fence::before_thread_sync;" ::: "memory")
#define TC_WAIT_LD()      asm volatile("tcgen05.wait::ld.sync.aligned;" ::: "memory")
#define FENCE_PROXY()     asm volatile("fence.proxy.async.shared::cta;" ::: "memory")

#define TC_LD_X32(r, addr) \
    asm volatile("tcgen05.ld.sync.aligned.32x32b.x32.b32 " \
        "{%0, %1, %2, %3, %4, %5, %6, %7, %8, %9, %10, %11, %12, %13, %14, %15, " \
        " %16, %17, %18, %19, %20, %21, %22, %23, %24, %25, %26, %27, %28, %29, %30, %31}, [%32];" \
        : "=r"((r)[0]),  "=r"((r)[1]),  "=r"((r)[2]),  "=r"((r)[3]), \
          "=r"((r)[4]),  "=r"((r)[5]),  "=r"((r)[6]),  "=r"((r)[7]), \
          "=r"((r)[8]),  "=r"((r)[9]),  "=r"((r)[10]), "=r"((r)[11]), \
          "=r"((r)[12]), "=r"((r)[13]), "=r"((r)[14]), "=r"((r)[15]), \
          "=r"((r)[16]), "=r"((r)[17]), "=r"((r)[18]), "=r"((r)[19]), \
          "=r"((r)[20]), "=r"((r)[21]), "=r"((r)[22]), "=r"((r)[23]), \
          "=r"((r)[24]), "=r"((r)[25]), "=r"((r)[26]), "=r"((r)[27]), \
          "=r"((r)[28]), "=r"((r)[29]), "=r"((r)[30]), "=r"((r)[31]) \
        : "r"(addr))

static constexpr uint64_t SMEM_DESC_BASE =
    (uint64_t(2) << 61) | (uint64_t(1) << 46) | (uint64_t(64) << 32) | (uint64_t(1) << 16);
#define MK_DESC(a) (SMEM_DESC_BASE | ((uint64_t)((a) >> 4) & 0x3FFF))

__device__ __forceinline__ void mma_tc2(uint32_t d, uint64_t ad, uint64_t bd,
                                        uint32_t idesc, bool en)
{
    uint32_t e = en ? 1 : 0;
    asm volatile(
        "{\n\t.reg .pred p;\n\tsetp.ne.u32 p, %4, 0;\n\t"
        "tcgen05.mma.cta_group::2.kind::tf32 [%0], %1, %2, %3, "
        "{%5,%5,%5,%5,%5,%5,%5,%5}, p;\n\t}"
        :: "r"(d), "l"(ad), "l"(bd), "r"(idesc), "r"(e), "r"(0u) : "memory");
}
#endif  // TC_AVAIL

// idesc: dtype=F32, a/b=tf32, N=256, M=256 (cg2)
constexpr uint32_t T2_IDESC =
    (1u << 4) | (2u << 7) | (2u << 10) | ((256 / 8) << 17) | ((256 / 16) << 24);

// C[m,n] = sum_k A[m,k]*B[n,k] + bias[n]; operands pre-rounded to tf32 values.
// grid: (2 * ceil(N/256), M/256), cluster (2,1,1). BK=32 floats, K % 32 == 0.
template<bool RELU, bool GN, bool TFO>
__global__ void __launch_bounds__(256, 1) __cluster_dims__(2, 1, 1)
k_tc2(int N, int K,
      const float* __restrict__ A, int lda,
      const float* __restrict__ B, int ldb,
      float* __restrict__ C, int ldc,
      const float* __restrict__ bias)
{
#if TC_AVAIL
    extern __shared__ char smem[];
    uint32_t sbase = (uint32_t)__cvta_generic_to_shared(smem);
    const int tid = threadIdx.x, lane = tid & 31, warp = tid >> 5;
    const uint32_t rank = ctarank();
    const int n0  = (blockIdx.x >> 1) * 256;          // tile col base
    const int m0  = blockIdx.y * 256 + rank * 128;    // this CTA's A/D rows
    const int nb0 = n0 + rank * 128;                  // this CTA's B rows

    if (warp == 0) TC_ALLOC_CG2(sbase, 256);
    if (tid == 0) {
        #pragma unroll
        for (int s = 0; s < T2_NS; s++) {
            MBAR_INIT(sbase + 16 + 8 * s, 2);   // ready (leader-side, 2 arrivals)
            MBAR_INIT(sbase + 64 + 8 * s, 1);   // done  (multicast commit)
        }
    }
    __syncthreads();
    CLUSTER_SYNC();
    uint32_t tmem;
    asm volatile("ld.shared.b32 %0, [%1];" : "=r"(tmem) : "r"(sbase));

    auto loadStage = [&](int st, int k0) {
        char* pa = smem + T2_AOFF + st * T2_ASZ;
        char* pb = smem + T2_BOFF + st * T2_BSZ;
        #pragma unroll
        for (int r = 0; r < 4; r++) {
            int i = tid + r * 256;
            int m = i >> 3, c = i & 7;
            int cs = c ^ (m & 7);     // SW128
            cp16(pa + m * 128 + cs * 16, &A[(size_t)(m0 + m) * lda + k0 + c * 4]);
        }
        #pragma unroll
        for (int r = 0; r < 4; r++) {
            int i = tid + r * 256;
            int n = i >> 3, c = i & 7;
            int cs = c ^ (n & 7);
            int gn = nb0 + n;
            if (GN) {
                bool ok = gn < N;
                cp16p(pb + n * 128 + cs * 16,
                      ok ? &B[(size_t)gn * ldb + k0 + c * 4] : (const float*)B, ok);
            } else {
                cp16(pb + n * 128 + cs * 16, &B[(size_t)gn * ldb + k0 + c * 4]);
            }
        }
    };

    const int nk = K / 32;

    #pragma unroll
    for (int s = 0; s < 3; s++) { loadStage(s, s * 32); CP_COMMIT(); }

    for (int kt = 0; kt < nk; kt++) {
        int cur = kt & 3;
        CP_WAIT2();               // this CTA's stage-kt data arrived
        __syncthreads();
        FENCE_PROXY();
        if (tid == 0) MBAR_ARRIVE_RANK(sbase + 16 + 8 * cur, 0);  // signal leader
        if (rank == 0 && warp == 0 && elect1()) {
            MBAR_WAIT_CL(sbase + 16 + 8 * cur, (kt / 4) & 1);     // both halves ready
            uint64_t ad = MK_DESC(sbase + T2_AOFF + cur * T2_ASZ);
            uint64_t bd = MK_DESC(sbase + T2_BOFF + cur * T2_BSZ);
            #pragma unroll
            for (int j = 0; j < 4; j++)
                mma_tc2(tmem, ad + j * 2, bd + j * 2, T2_IDESC, (kt > 0) || (j > 0));
            TC_COMMIT_MC_CG2(sbase + 64 + 8 * cur, 0x3);
        }
        if (kt >= 1) MBAR_WAIT(sbase + 64 + 8 * ((kt - 1) & 3), ((kt - 1) / 4) & 1);
        int kn = kt + 3;
        if (kn < nk) loadStage(kn & 3, kn * 32);
        CP_COMMIT();
    }
    MBAR_WAIT(sbase + 64 + 8 * ((nk - 1) & 3), ((nk - 1) / 4) & 1);

    __syncthreads();
    TC_FENCE_AFTER();

    // epilogue: this CTA's TMEM holds its 128 rows x 256 cols
    float* myep = (float*)(smem + 1024) + warp * (32 * 33);
    int rbase = m0 + (warp & 3) * 32;
    int cbase = (warp >> 2) * 128;

    #pragma unroll
    for (int ch = 0; ch < 4; ch++) {
        int c0 = cbase + ch * 32;
        uint32_t regs[32];
        TC_LD_X32(regs, tmem + c0);
        TC_WAIT_LD();
        #pragma unroll
        for (int c = 0; c < 32; c++) {
            float v = __uint_as_float(regs[c]);
            if (!GN || (n0 + c0 + c) < N) {
                v += bias[n0 + c0 + c];
                if (RELU) v = fmaxf(v, 0.f);
                if (TFO)  v = tf32r(v);
            }
            myep[lane * 33 + c] = v;
        }
        __syncwarp();
        int col = n0 + c0 + lane;
        #pragma unroll
        for (int i = 0; i < 32; i++) {
            if (!GN || col < N)
                C[(size_t)(rbase + i) * ldc + col] = myep[i * 33 + lane];
        }
        __syncwarp();
    }

    __syncthreads();
    if (warp == 0) { TC_FENCE_BEFORE(); TC_RELQ_CG2(); TC_DEALLOC_CG2(tmem, 256); }
    CLUSTER_SYNC();
#endif  // TC_AVAIL (else: empty stub — host detects via numRegs and falls back)
}

// ================= fused flash attention (mma.sync tf32) =================
constexpr int AT_SMEM = 174080;

__global__ void __launch_bounds__(256, 1)
k_attn(const float* __restrict__ qkv, float* __restrict__ ao)
{
    extern __shared__ float sm_[];
    float* Qs   = sm_;               // [128][68]
    float* Ks   = Qs + 128 * 68;
    float* Vs   = Ks + 128 * 68;
    float* Ps   = Vs + 128 * 68;     // [128][132]
    float* rmx  = Ps + 128 * 132;
    float* rsm  = rmx + 256;

    const int tid = threadIdx.x, lane = tid & 31, warp = tid >> 5;
    const int wm = warp >> 1, wn = warp & 1;
    const int g = lane >> 2, t4 = lane & 3;
    const int bh = blockIdx.y, b = bh >> 3, h = bh & 7;
    const int qrow0 = b * 512 + blockIdx.x * 128;
    const int kvbase = b * 512;

    #pragma unroll
    for (int r = 0; r < 8; r++) {
        int i = tid + r * 256;
        int row = i >> 4, c = (i & 15) << 2;
        float4 v = *(const float4*)&qkv[(size_t)(qrow0 + row) * 1536 + h * 64 + c];
        Qs[row * 68 + c]     = v.x * 0.125f;
        Qs[row * 68 + c + 1] = v.y * 0.125f;
        Qs[row * 68 + c + 2] = v.z * 0.125f;
        Qs[row * 68 + c + 3] = v.w * 0.125f;
    }

    float m_i[2][2], l_i[2][2];
    float oa[2][4][4];
    #pragma unroll
    for (int i = 0; i < 2; i++)
        #pragma unroll
        for (int hf = 0; hf < 2; hf++) { m_i[i][hf] = -1e30f; l_i[i][hf] = 0.f; }
    #pragma unroll
    for (int i = 0; i < 2; i++)
        #pragma unroll
        for (int j = 0; j < 4; j++)
            #pragma unroll
            for (int q = 0; q < 4; q++) oa[i][j][q] = 0.f;

    for (int kc = 0; kc < 4; kc++) {
        __syncthreads();
        int kvrow0 = kvbase + kc * 128;
        #pragma unroll
        for (int r = 0; r < 8; r++) {
            int i = tid + r * 256;
            int row = i >> 4, c = (i & 15) << 2;
            cp16(&Ks[row * 68 + c], &qkv[(size_t)(kvrow0 + row) * 1536 + 512 + h * 64 + c]);
        }
        #pragma unroll
        for (int r = 0; r < 8; r++) {
            int i = tid + r * 256;
            int row = i >> 4, c = (i & 15) << 2;
            cp16(&Vs[row * 68 + c], &qkv[(size_t)(kvrow0 + row) * 1536 + 1024 + h * 64 + c]);
        }
        CP_COMMIT();
        CP_WAIT0();
        __syncthreads();

        float s[2][8][4];
        #pragma unroll
        for (int i = 0; i < 2; i++)
            #pragma unroll
            for (int j = 0; j < 8; j++)
                #pragma unroll
                for (int q = 0; q < 4; q++) s[i][j][q] = 0.f;

        #pragma unroll
        for (int ks = 0; ks < 8; ks++) {
            uint32_t af[2][4], bf[8][2];
            #pragma unroll
            for (int i = 0; i < 2; i++) {
                int row = wm * 32 + i * 16 + g;
                af[i][0] = __float_as_uint(Qs[row * 68 + ks * 8 + t4]);
                af[i][1] = __float_as_uint(Qs[(row + 8) * 68 + ks * 8 + t4]);
                af[i][2] = __float_as_uint(Qs[row * 68 + ks * 8 + t4 + 4]);
                af[i][3] = __float_as_uint(Qs[(row + 8) * 68 + ks * 8 + t4 + 4]);
            }
            #pragma unroll
            for (int j = 0; j < 8; j++) {
                int nc = wn * 64 + j * 8 + g;
                bf[j][0] = __float_as_uint(Ks[nc * 68 + ks * 8 + t4]);
                bf[j][1] = __float_as_uint(Ks[nc * 68 + ks * 8 + t4 + 4]);
            }
            #pragma unroll
            for (int i = 0; i < 2; i++)
                #pragma unroll
                for (int j = 0; j < 8; j++)
                    mma_tf32(s[i][j], af[i][0], af[i][1], af[i][2], af[i][3],
                             bf[j][0], bf[j][1]);
        }

        float mn[2][2];
        #pragma unroll
        for (int i = 0; i < 2; i++)
            #pragma unroll
            for (int hf = 0; hf < 2; hf++) {
                float v = -1e30f;
                #pragma unroll
                for (int j = 0; j < 8; j++)
                    v = fmaxf(v, fmaxf(s[i][j][2 * hf], s[i][j][2 * hf + 1]));
                v = fmaxf(v, __shfl_xor_sync(0xFFFFFFFF, v, 1));
                v = fmaxf(v, __shfl_xor_sync(0xFFFFFFFF, v, 2));
                mn[i][hf] = v;
            }
        if (t4 == 0) {
            #pragma unroll
            for (int i = 0; i < 2; i++)
                #pragma unroll
                for (int hf = 0; hf < 2; hf++)
                    rmx[(wm * 32 + i * 16 + g + 8 * hf) * 2 + wn] = mn[i][hf];
        }
        __syncthreads();
        float sc[2][2];
        #pragma unroll
        for (int i = 0; i < 2; i++)
            #pragma unroll
            for (int hf = 0; hf < 2; hf++) {
                int row = wm * 32 + i * 16 + g + 8 * hf;
                float cm = fmaxf(rmx[row * 2], rmx[row * 2 + 1]);
                float nm = fmaxf(m_i[i][hf], cm);
                sc[i][hf] = __expf(m_i[i][hf] - nm);
                mn[i][hf] = nm;
            }
        #pragma unroll
        for (int i = 0; i < 2; i++)
            #pragma unroll
            for (int j = 0; j < 4; j++) {
                oa[i][j][0] *= sc[i][0]; oa[i][j][1] *= sc[i][0];
                oa[i][j][2] *= sc[i][1]; oa[i][j][3] *= sc[i][1];
            }
        float smv[2][2] = {{0.f, 0.f}, {0.f, 0.f}};
        #pragma unroll
        for (int i = 0; i < 2; i++) {
            int row = wm * 32 + i * 16 + g;
            #pragma unroll
            for (int j = 0; j < 8; j++) {
                int col = wn * 64 + j * 8 + 2 * t4;
                float p0 = __expf(s[i][j][0] - mn[i][0]);
                float p1 = __expf(s[i][j][1] - mn[i][0]);
                float p2 = __expf(s[i][j][2] - mn[i][1]);
                float p3 = __expf(s[i][j][3] - mn[i][1]);
                smv[i][0] += p0 + p1;
                smv[i][1] += p2 + p3;
                Ps[row * 132 + col]           = tf32r(p0);
                Ps[row * 132 + col + 1]       = tf32r(p1);
                Ps[(row + 8) * 132 + col]     = tf32r(p2);
                Ps[(row + 8) * 132 + col + 1] = tf32r(p3);
            }
        }
        #pragma unroll
        for (int i = 0; i < 2; i++)
            #pragma unroll
            for (int hf = 0; hf < 2; hf++) {
                float v = smv[i][hf];
                v += __shfl_xor_sync(0xFFFFFFFF, v, 1);
                v += __shfl_xor_sync(0xFFFFFFFF, v, 2);
                smv[i][hf] = v;
            }
        if (t4 == 0) {
            #pragma unroll
            for (int i = 0; i < 2; i++)
                #pragma unroll
                for (int hf = 0; hf < 2; hf++)
                    rsm[(wm * 32 + i * 16 + g + 8 * hf) * 2 + wn] = smv[i][hf];
        }
        __syncthreads();
        #pragma unroll
        for (int i = 0; i < 2; i++)
            #pragma unroll
            for (int hf = 0; hf < 2; hf++) {
                int row = wm * 32 + i * 16 + g + 8 * hf;
                l_i[i][hf] = l_i[i][hf] * sc[i][hf] + rsm[row * 2] + rsm[row * 2 + 1];
                m_i[i][hf] = mn[i][hf];
            }

        #pragma unroll
        for (int ks = 0; ks < 16; ks++) {
            uint32_t af[2][4], bf[4][2];
            #pragma unroll
            for (int i = 0; i < 2; i++) {
                int row = wm * 32 + i * 16 + g;
                af[i][0] = __float_as_uint(Ps[row * 132 + ks * 8 + t4]);
                af[i][1] = __float_as_uint(Ps[(row + 8) * 132 + ks * 8 + t4]);
                af[i][2] = __float_as_uint(Ps[row * 132 + ks * 8 + t4 + 4]);
                af[i][3] = __float_as_uint(Ps[(row + 8) * 132 + ks * 8 + t4 + 4]);
            }
            #pragma unroll
            for (int j = 0; j < 4; j++) {
                int nc = wn * 32 + j * 8 + g;
                bf[j][0] = __float_as_uint(Vs[(ks * 8 + t4) * 68 + nc]);
                bf[j][1] = __float_as_uint(Vs[(ks * 8 + t4 + 4) * 68 + nc]);
            }
            #pragma unroll
            for (int i = 0; i < 2; i++)
                #pragma unroll
                for (int j = 0; j < 4; j++)
                    mma_tf32(oa[i][j], af[i][0], af[i][1], af[i][2], af[i][3],
                             bf[j][0], bf[j][1]);
        }
    }

    #pragma unroll
    for (int i = 0; i < 2; i++) {
        float r0 = 1.f / l_i[i][0], r1 = 1.f / l_i[i][1];
        int row = qrow0 + wm * 32 + i * 16 + g;
        #pragma unroll
        for (int j = 0; j < 4; j++) {
            int col = h * 64 + wn * 32 + j * 8 + 2 * t4;
            *(float2*)&ao[(size_t)row * 512 + col] =
                make_float2(tf32r(oa[i][j][0] * r0), tf32r(oa[i][j][1] * r0));
            *(float2*)&ao[(size_t)(row + 8) * 512 + col] =
                make_float2(tf32r(oa[i][j][2] * r1), tf32r(oa[i][j][3] * r1));
        }
    }
}

// ================= mma.sync GEMM (fallback path) =================
template<int BM,int BN,int WARPS_M,int WARPS_N,bool TB,bool RELU,bool GN,bool TFO>
__global__ void __launch_bounds__(WARPS_M*WARPS_N*32)
k_mma(int M, int N, int K,
      const float* __restrict__ Ag, int lda, long long sA1, long long sA2,
      const float* __restrict__ Bg, int ldb, long long sB1, long long sB2,
      float* __restrict__ Cg, int ldc, long long sC1, long long sC2,
      int zdiv, const float* __restrict__ bias, float alpha)
{
    constexpr int BK = 16;
    constexpr int NT = WARPS_M * WARPS_N * 32;
    constexpr int WM = BM / WARPS_M, WN = BN / WARPS_N;
    constexpr int MI = WM / 16, NI = WN / 8;
    constexpr int AST = BK + 4;
    constexpr int BROWS = TB ? BN : BK;
    constexpr int BCOLS = TB ? (BK + 4) : (BN + 8);

    __shared__ __align__(16) float As[2][BM][AST];
    __shared__ __align__(16) float Bs[2][BROWS][BCOLS];

    const int bz = blockIdx.z;
    const int z1 = bz / zdiv, z2 = bz - z1 * zdiv;
    const float* A  = Ag + z1 * sA1 + z2 * sA2;
    const float* Bp = Bg + z1 * sB1 + z2 * sB2;
    float* C        = Cg + z1 * sC1 + z2 * sC2;

    const int m0 = blockIdx.y * BM, n0 = blockIdx.x * BN;
    const int tid  = threadIdx.x;
    const int lane = tid & 31, warp = tid >> 5;
    const int wm = warp / WARPS_N, wn = warp - wm * WARPS_N;
    const int g = lane >> 2, t4 = lane & 3;

    float acc[MI][NI][4];
    #pragma unroll
    for (int i = 0; i < MI; i++)
        #pragma unroll
        for (int j = 0; j < NI; j++)
            #pragma unroll
            for (int q = 0; q < 4; q++) acc[i][j][q] = 0.f;

    auto loadTiles = [&](int st, int k0) {
        #pragma unroll
        for (int r = 0; r < (BM * (BK/4)) / NT; r++) {
            int i = tid + r * NT;
            int m = i >> 2;
            int c = (i & 3) << 2;
            cp16(&As[st][m][c], &A[(size_t)(m0 + m) * lda + k0 + c]);
        }
        if (TB) {
            #pragma unroll
            for (int r = 0; r < (BN * (BK/4)) / NT; r++) {
                int i = tid + r * NT;
                int n = i >> 2;
                int c = (i & 3) << 2;
                int gn = n0 + n;
                if (GN) {
                    bool ok = gn < N;
                    cp16p(&Bs[st][n][c], ok ? &Bp[(size_t)gn * ldb + k0 + c] : (const float*)Bp, ok);
                } else {
                    cp16(&Bs[st][n][c], &Bp[(size_t)gn * ldb + k0 + c]);
                }
            }
        } else {
            #pragma unroll
            for (int r = 0; r < (BK * (BN/4)) / NT; r++) {
                int i = tid + r * NT;
                int kk = i / (BN/4);
                int c  = (i - kk * (BN/4)) << 2;
                cp16(&Bs[st][kk][c], &Bp[(size_t)(k0 + kk) * ldb + n0 + c]);
            }
        }
    };

    const int nk = K / BK;
    loadTiles(0, 0);
    CP_COMMIT();

    for (int kt = 0; kt < nk; kt++) {
        int cur = kt & 1;
        if (kt + 1 < nk) loadTiles(cur ^ 1, (kt + 1) * BK);
        CP_COMMIT();
        CP_WAIT1();
        __syncthreads();

        #pragma unroll
        for (int ks = 0; ks < 2; ks++) {
            uint32_t af[MI][4], bf[NI][2];
            #pragma unroll
            for (int i = 0; i < MI; i++) {
                int mr = wm * WM + i * 16 + g;
                af[i][0] = __float_as_uint(As[cur][mr    ][ks*8 + t4    ]);
                af[i][1] = __float_as_uint(As[cur][mr + 8][ks*8 + t4    ]);
                af[i][2] = __float_as_uint(As[cur][mr    ][ks*8 + t4 + 4]);
                af[i][3] = __float_as_uint(As[cur][mr + 8][ks*8 + t4 + 4]);
            }
            #pragma unroll
            for (int j = 0; j < NI; j++) {
                int nc = wn * WN + j * 8 + g;
                if (TB) {
                    bf[j][0] = __float_as_uint(Bs[cur][nc][ks*8 + t4    ]);
                    bf[j][1] = __float_as_uint(Bs[cur][nc][ks*8 + t4 + 4]);
                } else {
                    bf[j][0] = __float_as_uint(Bs[cur][ks*8 + t4    ][nc]);
                    bf[j][1] = __float_as_uint(Bs[cur][ks*8 + t4 + 4][nc]);
                }
            }
            #pragma unroll
            for (int i = 0; i < MI; i++)
                #pragma unroll
                for (int j = 0; j < NI; j++)
                    mma_tf32(acc[i][j], af[i][0], af[i][1], af[i][2], af[i][3],
                             bf[j][0], bf[j][1]);
        }
        __syncthreads();
    }

    #pragma unroll
    for (int i = 0; i < MI; i++) {
        int r0 = m0 + wm * WM + i * 16 + g;
        #pragma unroll
        for (int j = 0; j < NI; j++) {
            int col = n0 + wn * WN + j * 8 + t4 * 2;
            if (GN && col >= N) continue;
            float b0v = 0.f, b1v = 0.f;
            if (bias) { b0v = bias[col]; b1v = bias[col + 1]; }
            float v0 = acc[i][j][0] * alpha + b0v;
            float v1 = acc[i][j][1] * alpha + b1v;
            float v2 = acc[i][j][2] * alpha + b0v;
            float v3 = acc[i][j][3] * alpha + b1v;
            if (RELU) {
                v0 = fmaxf(v0, 0.f); v1 = fmaxf(v1, 0.f);
                v2 = fmaxf(v2, 0.f); v3 = fmaxf(v3, 0.f);
            }
            if (TFO) {
                v0 = tf32r(v0); v1 = tf32r(v1); v2 = tf32r(v2); v3 = tf32r(v3);
            }
            *reinterpret_cast<float2*>(&C[(size_t)r0 * ldc + col])       = make_float2(v0, v1);
            *reinterpret_cast<float2*>(&C[(size_t)(r0 + 8) * ldc + col]) = make_float2(v2, v3);
        }
    }
}

// ---------------- residual add + layernorm ----------------
__global__ void k_add_ln(const float* __restrict__ xin, const float* __restrict__ res,
                         const float* __restrict__ g, const float* __restrict__ b,
                         float* __restrict__ xout, float* __restrict__ xtf)
{
    int row = blockIdx.x, t = threadIdx.x;
    long long base = (long long)row * D;
    float v0 = xin[base + t]       + res[base + t];
    float v1 = xin[base + t + 256] + res[base + t + 256];
    __shared__ float red[256];
    red[t] = v0 + v1; __syncthreads();
    for (int o = 128; o > 0; o >>= 1) { if (t < o) red[t] += red[t+o]; __syncthreads(); }
    float mean = red[0] * (1.f / D); __syncthreads();
    red[t] = v0*v0 + v1*v1; __syncthreads();
    for (int o = 128; o > 0; o >>= 1) { if (t < o) red[t] += red[t+o]; __syncthreads(); }
    float var = red[0] * (1.f / D) - mean*mean;
    float rs = rsqrtf(var + 1e-5f);
    float o0 = (v0 - mean) * rs * g[t]       + b[t];
    float o1 = (v1 - mean) * rs * g[t + 256] + b[t + 256];
    xout[base + t]       = o0;
    xout[base + t + 256] = o1;
    xtf [base + t]       = tf32r(o0);
    xtf [base + t + 256] = tf32r(o1);
}

// ---------------- embedding ----------------
__global__ void k_embed(const int* __restrict__ src, const float* __restrict__ emb,
                        const float* __restrict__ pos, float* __restrict__ x,
                        float* __restrict__ xtf)
{
    int idx = blockIdx.x * blockDim.x + threadIdx.x;
    int t = idx >> 9, d = idx & 511;
    float v = emb[(long long)src[t] * D + d] * SQRTD_F + pos[(t & 511) * D + d];
    x[idx]   = v;
    xtf[idx] = tf32r(v);
}

// ---------------- round static weights ----------------
__global__ void k_round_w(const float* __restrict__ opw, const float* __restrict__ ow, int nOw)
{
    int i = blockIdx.x * blockDim.x + threadIdx.x;
    if (i < L * D * D) d_wr[i] = tf32r(opw[i]);
    if (i < nOw)       d_owr[i] = tf32r(ow[i]);
}

// ---------------- batched prune pipeline ----------------
__device__ __forceinline__ const float* slot_w(int slot, const float* ipw,
                                               const float* w1, const float* w2, int& n)
{
    int t = slot / 6, l = slot - t * 6;
    if (t == 0) { n = 3 * D * D; return ipw + (size_t)l * 3 * D * D; }
    n = F * D;
    return (t == 1) ? w1 + (size_t)l * F * D : w2 + (size_t)l * F * D;
}

__global__ void k_zero_all()
{
    int i = blockIdx.x * blockDim.x + threadIdx.x;
    if (i < NSLOT * 2 * 65536) d_h2g[i] = 0;
    if (i < NSLOT * 4096)      d_h1g[i] = 0;
    if (i < NSLOT * 32)        d_h3g[i] = 0;
}

__global__ void k_etch_all(const float* __restrict__ ipw, const float* __restrict__ w1,
                           const float* __restrict__ w2)
{
    int slot = blockIdx.y;
    int n;
    const float* w = slot_w(slot, ipw, w1, w2, n);
    float inv = 1.f / (float)(n - 1);
    float* aout = d_abs_all + (size_t)slot * SLOT_STRIDE;
    unsigned* h1 = d_h1g + slot * 4096;

    __shared__ unsigned h[4096];
    for (int j = threadIdx.x; j < 4096; j += blockDim.x) h[j] = 0;
    __syncthreads();
    int stride = gridDim.x * blockDim.x;
    for (int i = blockIdx.x * blockDim.x + threadIdx.x; i < n; i += stride) {
        float wv = w[i];
        float b0 = __sinf(wv * PI_F);
        b0 = fminf(fmaxf(b0, -1.f), 1.f);
        float bl = b0 + b0 * __cosf((float)i * inv + THIRD_F) * 1.5f;
        float e = __cosf(bl * PI2_F) + bl * bl * DEVPI_F;
        float a = fabsf(e);
        aout[i] = a;
        atomicAdd(&h[__float_as_uint(a) >> 20], 1u);
    }
    __syncthreads();
    for (int j = threadIdx.x; j < 4096; j += blockDim.x) {
        unsigned c = h[j];
        if (c) atomicAdd(&h1[j], c);
    }
}

__global__ void k_scan1_all(const float* ipw, const float* w1, const float* w2)
{
    int slot = blockIdx.x;
    int n; slot_w(slot, ipw, w1, w2, n);
    unsigned rA = (unsigned)((n - 1) >> 2);
    unsigned rB = rA + 1;
    const unsigned* h1 = d_h1g + slot * 4096;
    unsigned* sel = d_selg + slot * 8;

    __shared__ unsigned part[256];
    __shared__ unsigned pref[256];
    int t = threadIdx.x, base = t * 16;
    unsigned c[16]; unsigned s = 0;
    for (int j = 0; j < 16; j++) { c[j] = h1[base + j]; s += c[j]; }
    part[t] = s; __syncthreads();
    if (t == 0) { unsigned a = 0; for (int i = 0; i < 256; i++) { pref[i] = a; a += part[i]; } }
    __syncthreads();
    unsigned p = pref[t];
    for (int j = 0; j < 16; j++) {
        if (rA >= p && rA < p + c[j]) { sel[0] = base + j; sel[1] = rA - p; }
        if (rB >= p && rB < p + c[j]) { sel[2] = base + j; sel[3] = rB - p; }
        p += c[j];
    }
}

__global__ void k_hist2_all(const float* ipw, const float* w1, const float* w2)
{
    int slot = blockIdx.y;
    int n; slot_w(slot, ipw, w1, w2, n);
    const float* ab = d_abs_all + (size_t)slot * SLOT_STRIDE;
    const unsigned* sel = d_selg + slot * 8;
    unsigned* h2 = d_h2g + (size_t)slot * 131072;
    unsigned sA = sel[0], sB = sel[2];
    int stride = gridDim.x * blockDim.x;
    for (int i = blockIdx.x * blockDim.x + threadIdx.x; i < n; i += stride) {
        unsigned u = __float_as_uint(ab[i]);
        unsigned hi = u >> 20, mid = (u >> 4) & 0xFFFFu;
        if (hi == sA) atomicAdd(&h2[mid], 1u);
        if (hi == sB) atomicAdd(&h2[65536 + mid], 1u);
    }
}

__global__ void k_scan2_all()
{
    int slot = blockIdx.x;
    unsigned* sel = d_selg + slot * 8;
    __shared__ unsigned part[256];
    __shared__ unsigned pref[256];
    int t = threadIdx.x;
    for (int sidx = 0; sidx < 2; sidx++) {
        unsigned rank = sel[1 + sidx * 2];
        const unsigned* hb = d_h2g + (size_t)slot * 131072 + sidx * 65536;
        int base = t * 256;
        unsigned s = 0;
        for (int j = 0; j < 256; j++) s += hb[base + j];
        part[t] = s; __syncthreads();
        if (t == 0) { unsigned a = 0; for (int i = 0; i < 256; i++) { pref[i] = a; a += part[i]; } }
        __syncthreads();
        unsigned p = pref[t];
        for (int j = 0; j < 256; j++) {
            unsigned c = hb[base + j];
            if (rank >= p && rank < p + c) { sel[4 + sidx*2] = base + j; sel[5 + sidx*2] = rank - p; }
            p += c;
        }
        __syncthreads();
    }
}

__global__ void k_hist3_all(const float* ipw, const float* w1, const float* w2)
{
    int slot = blockIdx.y;
    int n; slot_w(slot, ipw, w1, w2, n);
    const float* ab = d_abs_all + (size_t)slot * SLOT_STRIDE;
    const unsigned* sel = d_selg + slot * 8;
    unsigned* h3 = d_h3g + slot * 32;
    unsigned kA = (sel[0] << 16) | sel[4];
    unsigned kB = (sel[2] << 16) | sel[6];
    int stride = gridDim.x * blockDim.x;
    for (int i = blockIdx.x * blockDim.x + threadIdx.x; i < n; i += stride) {
        unsigned u = __float_as_uint(ab[i]);
        unsigned top = u >> 4;
        if (top == kA) atomicAdd(&h3[u & 15u], 1u);
        if (top == kB) atomicAdd(&h3[16 + (u & 15u)], 1u);
    }
}

__global__ void k_thr_all(const float* ipw, const float* w1, const float* w2)
{
    int slot = blockIdx.x * blockDim.x + threadIdx.x;
    if (slot >= NSLOT) return;
    int n; slot_w(slot, ipw, w1, w2, n);
    float frac = 0.25f * (float)((n - 1) & 3);
    const unsigned* sel = d_selg + slot * 8;
    const unsigned* h3 = d_h3g + slot * 32;
    unsigned remA = sel[5]; unsigned lowA = 0;
    for (int j = 0; j < 16; j++) { unsigned c = h3[j]; if (remA < c) { lowA = j; break; } remA -= c; }
    unsigned remB = sel[7]; unsigned lowB = 0;
    for (int j = 0; j < 16; j++) { unsigned c = h3[16 + j]; if (remB < c) { lowB = j; break; } remB -= c; }
    float vA = __uint_as_float((sel[0] << 20) | (sel[4] << 4) | lowA);
    float vB = __uint_as_float((sel[2] << 20) | (sel[6] << 4) | lowB);
    d_thrg[slot] = vA + frac * (vB - vA);
}

__global__ void k_mask_all(const float* __restrict__ ipw, const float* __restrict__ w1,
                           const float* __restrict__ w2)
{
    int slot = blockIdx.y;
    int n;
    const float* w = slot_w(slot, ipw, w1, w2, n);
    int i = blockIdx.x * blockDim.x + threadIdx.x;
    if (i >= n) return;
    float thr = d_thrg[slot];
    d_wp[(size_t)slot * SLOT_STRIDE + i] =
        (d_abs_all[(size_t)slot * SLOT_STRIDE + i] > thr) ? tf32r(w[i]) : 0.f;
}

// ---------------- entry point ----------------
extern "C" void kernel_launch(void* const* d_in, const int* in_sizes, int n_in,
                              void* d_out, int out_size)
{
    const int*   src = (const int*)  d_in[0];
    const float* emb = (const float*)d_in[1];
    const float* pos = (const float*)d_in[2];
    const float* ipw = (const float*)d_in[3];
    const float* ipb = (const float*)d_in[4];
    const float* opw = (const float*)d_in[5];
    const float* opb = (const float*)d_in[6];
    const float* l1g = (const float*)d_in[7];
    const float* l1b = (const float*)d_in[8];
    const float* l2g = (const float*)d_in[9];
    const float* l2b = (const float*)d_in[10];
    const float* w1  = (const float*)d_in[11];
    const float* b1  = (const float*)d_in[12];
    const float* w2  = (const float*)d_in[13];
    const float* b2  = (const float*)d_in[14];
    const float* ow  = (const float*)d_in[15];
    const float* ob  = (const float*)d_in[16];
    const int V = in_sizes[16];
    float* out = (float*)d_out;

    float *px, *pxtf, *pqkv, *pao, *pff, *ptmp, *pwp, *pwr, *powr;
    cudaGetSymbolAddress((void**)&px,   d_x);
    cudaGetSymbolAddress((void**)&pxtf, d_xtf);
    cudaGetSymbolAddress((void**)&pqkv, d_qkv);
    cudaGetSymbolAddress((void**)&pao,  d_ao);
    cudaGetSymbolAddress((void**)&pff,  d_ff);
    cudaGetSymbolAddress((void**)&ptmp, d_tmp);
    cudaGetSymbolAddress((void**)&pwp,  d_wp);
    cudaGetSymbolAddress((void**)&pwr,  d_wr);
    cudaGetSymbolAddress((void**)&powr, d_owr);

    cudaFuncAttributes fa{};
    cudaFuncGetAttributes(&fa, k_tc2<false,false,true>);
    const bool use_tc = fa.numRegs > 40;

    if (use_tc) {
        cudaFuncSetAttribute(k_tc2<false,false,true >, cudaFuncAttributeMaxDynamicSharedMemorySize, T2_SMEM);
        cudaFuncSetAttribute(k_tc2<false,false,false>, cudaFuncAttributeMaxDynamicSharedMemorySize, T2_SMEM);
        cudaFuncSetAttribute(k_tc2<true ,false,true >, cudaFuncAttributeMaxDynamicSharedMemorySize, T2_SMEM);
        cudaFuncSetAttribute(k_tc2<false,true ,false>, cudaFuncAttributeMaxDynamicSharedMemorySize, T2_SMEM);
    }
    cudaFuncSetAttribute(k_attn, cudaFuncAttributeMaxDynamicSharedMemorySize, AT_SMEM);

    k_embed<<<MT * D / 256, 256>>>(src, emb, pos, px, pxtf);
    k_round_w<<<(V * D + 255) / 256, 256>>>(opw, ow, V * D);

    k_zero_all<<<(NSLOT * 2 * 65536 + 255) / 256, 256>>>();
    k_etch_all <<<dim3(128, NSLOT), 256>>>(ipw, w1, w2);
    k_scan1_all<<<NSLOT, 256>>>(ipw, w1, w2);
    k_hist2_all<<<dim3(128, NSLOT), 256>>>(ipw, w1, w2);
    k_scan2_all<<<NSLOT, 256>>>();
    k_hist3_all<<<dim3(128, NSLOT), 256>>>(ipw, w1, w2);
    k_thr_all  <<<1, 32>>>(ipw, w1, w2);
    k_mask_all <<<dim3(4096, NSLOT), 256>>>(ipw, w1, w2);

    const int MT256 = MT / 256;   // 32

    for (int l = 0; l < L; l++) {
        const float* wi_l = pwp + (size_t)(0 * 6 + l) * SLOT_STRIDE;
        const float* w1_l = pwp + (size_t)(1 * 6 + l) * SLOT_STRIDE;
        const float* w2_l = pwp + (size_t)(2 * 6 + l) * SLOT_STRIDE;

        // qkv = x @ wi^T + b (output tf32-rounded: feeds attention)
        if (use_tc)
            k_tc2<false,false,true><<<dim3(2 * (3*D/256), MT256), 256, T2_SMEM>>>(
                3*D, D, pxtf, D, wi_l, D, pqkv, 3*D, ipb + (size_t)l * 3 * D);
        else
            k_mma<128,128,2,2,true,false,false,true><<<dim3((3*D)/128, MT/128, 1), 128>>>(
                MT, 3*D, D, pxtf, D, 0, 0, wi_l, D, 0, 0, pqkv, 3*D, 0, 0, 1,
                ipb + (size_t)l * 3 * D, 1.f);

        // fused flash attention
        k_attn<<<dim3(4, BH), 256, AT_SMEM>>>(pqkv, pao);

        // out projection
        if (use_tc)
            k_tc2<false,false,false><<<dim3(2 * (D/256), MT256), 256, T2_SMEM>>>(
                D, D, pao, D, pwr + (size_t)l*D*D, D, ptmp, D, opb + (size_t)l*D);
        else
            k_mma<128,128,2,2,true,false,false,false><<<dim3(D/128, MT/128, 1), 128>>>(
                MT, D, D, pao, D, 0, 0, pwr + (size_t)l*D*D, D, 0, 0,
                ptmp, D, 0, 0, 1, opb + (size_t)l*D, 1.f);
        k_add_ln<<<MT, 256>>>(px, ptmp, l1g + (size_t)l*D, l1b + (size_t)l*D, px, pxtf);

        // feed-forward
        if (use_tc) {
            k_tc2<true,false,true><<<dim3(2 * (F/256), MT256), 256, T2_SMEM>>>(
                F, D, pxtf, D, w1_l, D, pff, F, b1 + (size_t)l*F);
            k_tc2<false,false,false><<<dim3(2 * (D/256), MT256), 256, T2_SMEM>>>(
                D, F, pff, F, w2_l, F, ptmp, D, b2 + (size_t)l*D);
        } else {
            k_mma<128,128,2,2,true,true,false,true><<<dim3(F/128, MT/128, 1), 128>>>(
                MT, F, D, pxtf, D, 0, 0, w1_l, D, 0, 0, pff, F, 0, 0, 1,
                b1 + (size_t)l*F, 1.f);
            k_mma<128,128,2,2,true,false,false,false><<<dim3(D/128, MT/128, 1), 128>>>(
                MT, D, F, pff, F, 0, 0, w2_l, F, 0, 0, ptmp, D, 0, 0, 1,
                b2 + (size_t)l*D, 1.f);
        }
        k_add_ln<<<MT, 256>>>(px, ptmp, l2g + (size_t)l*D, l2b + (size_t)l*D, px, pxtf);
    }

    // logits
    if (use_tc)
        k_tc2<false,true,false><<<dim3(2 * ((V + 255)/256), MT256), 256, T2_SMEM>>>(
            V, D, pxtf, D, powr, D, out, V, ob);
    else
        k_mma<128,128,2,2,true,false,true,false><<<dim3((V + 127) / 128, MT / 128, 1), 128>>>(
            MT, V, D, pxtf, D, 0, 0, powr, D, 0, 0, out, V, 0, 0, 1, ob, 1.f);
}

// round 8
// speedup vs baseline: 1.6330x; 1.6330x over previous
#include <cuda_runtime.h>
#include <cstdint>
#include <math.h>

// ---------------- constants ----------------
#define PI_F      3.14159265358979323846f
#define PI2_F     9.86960440108935861883f
#define THIRD_F   2.09439510239319549231f
#define DEVPI_F   0.003183098861837907f
#define SQRTD_F   22.62741699796952f

constexpr int S  = 512;
constexpr int D  = 512;
constexpr int H  = 8;
constexpr int DH = 64;
constexpr int L  = 6;
constexpr int F  = 2048;
constexpr int BB = 16;
constexpr int MT = BB * S;   // 8192 tokens
constexpr int BH = BB * H;   // 128
constexpr int NSLOT = 18;
constexpr size_t SLOT_STRIDE = 1048576;
constexpr int VMAX = 10240;

// Feature gate: tcgen05 only exists on arch-specific (sm_103a) / family (sm_103f) targets.
#if !defined(__CUDA_ARCH__) || defined(__CUDA_ARCH_FEAT_SM103_ALL) || defined(__CUDA_ARCH_SPECIFIC__) || defined(__CUDA_ARCH_FAMILY_SPECIFIC__)
#define TC_AVAIL 1
#else
#define TC_AVAIL 0
#endif

// ---------------- device scratch ----------------
__device__ __align__(128) float d_x   [MT * D];
__device__ __align__(128) float d_xtf [MT * D];
__device__ __align__(128) float d_qkv [MT * 3 * D];
__device__ __align__(128) float d_ao  [MT * D];
__device__ __align__(128) float d_ff  [MT * F];
__device__ __align__(128) float d_tmp [MT * D];
__device__ __align__(128) float d_wp  [NSLOT * SLOT_STRIDE];
__device__ __align__(128) float d_wr  [L * D * D];
__device__ __align__(128) float d_owr [VMAX * D];
__device__ __align__(128) float d_abs_all[NSLOT * SLOT_STRIDE];
__device__ unsigned d_h1g[NSLOT * 4096];
__device__ unsigned d_h2g[NSLOT * 2 * 65536];
__device__ unsigned d_h3g[NSLOT * 32];
__device__ unsigned d_selg[NSLOT * 8];
__device__ float d_thrg[NSLOT];

// ---------------- helpers ----------------
__device__ __forceinline__ float tf32r(float f) {
    uint32_t u;
    asm("cvt.rna.tf32.f32 %0, %1;" : "=r"(u) : "f"(f));
    return __uint_as_float(u);
}

__device__ __forceinline__ void mma_tf32(float c[4],
    uint32_t a0, uint32_t a1, uint32_t a2, uint32_t a3,
    uint32_t b0, uint32_t b1)
{
    asm volatile(
        "mma.sync.aligned.m16n8k8.row.col.f32.tf32.tf32.f32 "
        "{%0,%1,%2,%3}, {%4,%5,%6,%7}, {%8,%9}, {%0,%1,%2,%3};"
        : "+f"(c[0]), "+f"(c[1]), "+f"(c[2]), "+f"(c[3])
        : "r"(a0), "r"(a1), "r"(a2), "r"(a3), "r"(b0), "r"(b1));
}

__device__ __forceinline__ void cp16(void* d, const void* s) {
    uint32_t a = (uint32_t)__cvta_generic_to_shared(d);
    asm volatile("cp.async.cg.shared.global [%0], [%1], 16;" :: "r"(a), "l"(s));
}
__device__ __forceinline__ void cp16p(void* d, const void* s, bool p) {
    uint32_t a = (uint32_t)__cvta_generic_to_shared(d);
    int sz = p ? 16 : 0;
    asm volatile("cp.async.cg.shared.global [%0], [%1], 16, %2;" :: "r"(a), "l"(s), "r"(sz));
}
#define CP_COMMIT() asm volatile("cp.async.commit_group;")
#define CP_WAIT0()  asm volatile("cp.async.wait_group 0;")
#define CP_WAIT1()  asm volatile("cp.async.wait_group 1;")

// ================= tcgen05 tf32 GEMM (cg1, BN=512 via dual-dispatch) =================
constexpr int TC_BM = 128, TC_BN = 512, TC_BK = 32, TC_NS = 2;
constexpr int TC_ASZ = TC_BM * TC_BK * 4;       // 16384 (128 rows x 128B)
constexpr int TC_BSZ = TC_BN * TC_BK * 4;       // 65536 (512 rows x 128B)
constexpr int TC_SMEM = 1024 + TC_NS * (TC_ASZ + TC_BSZ);   // 164864

#if TC_AVAIL
__device__ __forceinline__ uint32_t elect1() {
    uint32_t pred;
    asm volatile("{\n\t.reg .pred p;\n\telect.sync _|p, 0xFFFFFFFF;\n\t"
                 "selp.b32 %0, 1, 0, p;\n\t}" : "=r"(pred));
    return pred;
}
#define MBAR_INIT(addr, cnt) \
    asm volatile("mbarrier.init.shared.b64 [%0], %1;" :: "r"(addr), "r"(cnt) : "memory")
#define MBAR_WAIT(addr, par) do { \
    asm volatile("{\n\t.reg .pred P1;\n\tWL%=:\n\t" \
        "mbarrier.try_wait.parity.acquire.cta.shared::cta.b64 P1, [%0], %1, 0x989680;\n\t" \
        "@P1 bra.uni WD%=;\n\tbra.uni WL%=;\n\tWD%=:\n\t}" \
        :: "r"(addr), "r"(par) : "memory"); \
} while (0)
#define TC_ALLOC(sm, n)   asm volatile("tcgen05.alloc.cta_group::1.sync.aligned.shared::cta.b32 [%0], %1;" :: "r"(sm), "r"(n) : "memory")
#define TC_DEALLOC(t, n)  asm volatile("tcgen05.dealloc.cta_group::1.sync.aligned.b32 %0, %1;" :: "r"(t), "r"(n))
#define TC_COMMIT(mb)     asm volatile("tcgen05.commit.cta_group::1.mbarrier::arrive::one.shared::cluster.b64 [%0];" :: "r"(mb) : "memory")
#define TC_FENCE_AFTER()  asm volatile("tcgen05.fence::after_thread_sync;" ::: "memory")
#define TC_FENCE_BEFORE() asm volatile("tcgen05.fence::before_thread_sync;" ::: "memory")
#define TC_WAIT_LD()      asm volatile("tcgen05.wait::ld.sync.aligned;" ::: "memory")
#define FENCE_PROXY()     asm volatile("fence.proxy.async.shared::cta;" ::: "memory")

#define TC_LD_X32(r, addr) \
    asm volatile("tcgen05.ld.sync.aligned.32x32b.x32.b32 " \
        "{%0, %1, %2, %3, %4, %5, %6, %7, %8, %9, %10, %11, %12, %13, %14, %15, " \
        " %16, %17, %18, %19, %20, %21, %22, %23, %24, %25, %26, %27, %28, %29, %30, %31}, [%32];" \
        : "=r"((r)[0]),  "=r"((r)[1]),  "=r"((r)[2]),  "=r"((r)[3]), \
          "=r"((r)[4]),  "=r"((r)[5]),  "=r"((r)[6]),  "=r"((r)[7]), \
          "=r"((r)[8]),  "=r"((r)[9]),  "=r"((r)[10]), "=r"((r)[11]), \
          "=r"((r)[12]), "=r"((r)[13]), "=r"((r)[14]), "=r"((r)[15]), \
          "=r"((r)[16]), "=r"((r)[17]), "=r"((r)[18]), "=r"((r)[19]), \
          "=r"((r)[20]), "=r"((r)[21]), "=r"((r)[22]), "=r"((r)[23]), \
          "=r"((r)[24]), "=r"((r)[25]), "=r"((r)[26]), "=r"((r)[27]), \
          "=r"((r)[28]), "=r"((r)[29]), "=r"((r)[30]), "=r"((r)[31]) \
        : "r"(addr))

static constexpr uint64_t SMEM_DESC_BASE =
    (uint64_t(2) << 61) | (uint64_t(1) << 46) | (uint64_t(64) << 32) | (uint64_t(1) << 16);
#define MK_DESC(a) (SMEM_DESC_BASE | ((uint64_t)((a) >> 4) & 0x3FFF))

__device__ __forceinline__ void mma_tc(uint32_t d, uint64_t ad, uint64_t bd,
                                       uint32_t idesc, bool en)
{
    uint32_t e = en ? 1 : 0;
    asm volatile(
        "{\n\t.reg .pred p;\n\tsetp.ne.u32 p, %4, 0;\n\t"
        "tcgen05.mma.cta_group::1.kind::tf32 [%0], %1, %2, %3, {%5,%5,%5,%5}, p;\n\t}"
        :: "r"(d), "l"(ad), "l"(bd), "r"(idesc), "r"(e), "r"(0u) : "memory");
}
#endif  // TC_AVAIL

// per-dispatch idesc: dtype=F32, a/b=tf32, N=256, M=128
constexpr uint32_t TC_IDESC =
    (1u << 4) | (2u << 7) | (2u << 10) | ((256 / 8) << 17) | ((TC_BM / 16) << 24);

// C[m,n] = sum_k A[m,k]*B[n,k] + bias[n]; operands pre-rounded to tf32 values.
// grid: (ceil(N/512), M/128). BK=32 floats, K % 32 == 0.
template<bool RELU, bool GN, bool TFO>
__global__ void __launch_bounds__(256, 1)
k_tc(int N, int K,
     const float* __restrict__ A, int lda,
     const float* __restrict__ B, int ldb,
     float* __restrict__ C, int ldc,
     const float* __restrict__ bias)
{
#if TC_AVAIL
    extern __shared__ char smem[];
    uint32_t sbase = (uint32_t)__cvta_generic_to_shared(smem);
    const int tid = threadIdx.x, lane = tid & 31, warp = tid >> 5;
    const int m0 = blockIdx.y * TC_BM, n0 = blockIdx.x * TC_BN;

    if (warp == 0) TC_ALLOC(sbase, 512);
    if (tid == 0) {
        MBAR_INIT(sbase + 16, 1);
        MBAR_INIT(sbase + 24, 1);
    }
    __syncthreads();
    uint32_t tmem;
    asm volatile("ld.shared.b32 %0, [%1];" : "=r"(tmem) : "r"(sbase));

    const uint32_t aoff = 1024, boff = 1024 + TC_NS * TC_ASZ;

    auto loadStage = [&](int st, int k0) {
        char* pa = smem + aoff + st * TC_ASZ;
        char* pb = smem + boff + st * TC_BSZ;
        // A: 128 rows x 8 chunks(16B) = 1024 -> 4 per thread
        #pragma unroll
        for (int r = 0; r < 4; r++) {
            int i = tid + r * 256;
            int m = i >> 3, c = i & 7;
            int cs = c ^ (m & 7);     // SW128
            cp16(pa + m * 128 + cs * 16, &A[(size_t)(m0 + m) * lda + k0 + c * 4]);
        }
        // B: 512 rows x 8 chunks = 4096 -> 16 per thread
        #pragma unroll
        for (int r = 0; r < 16; r++) {
            int i = tid + r * 256;
            int n = i >> 3, c = i & 7;
            int cs = c ^ (n & 7);
            int gn = n0 + n;
            if (GN) {
                bool ok = gn < N;
                cp16p(pb + n * 128 + cs * 16,
                      ok ? &B[(size_t)gn * ldb + k0 + c * 4] : (const float*)B, ok);
            } else {
                cp16(pb + n * 128 + cs * 16, &B[(size_t)gn * ldb + k0 + c * 4]);
            }
        }
    };

    const int nk = K / TC_BK;

    loadStage(0, 0);
    CP_COMMIT();

    for (int kt = 0; kt < nk; kt++) {
        int cur = kt & 1;
        CP_WAIT0();               // stage kt data arrived (this thread)
        __syncthreads();          // all threads' data arrived
        FENCE_PROXY();
        if (warp == 0 && elect1()) {
            uint64_t ad  = MK_DESC(sbase + aoff + cur * TC_ASZ);
            uint64_t bd0 = MK_DESC(sbase + boff + cur * TC_BSZ);
            uint64_t bd1 = MK_DESC(sbase + boff + cur * TC_BSZ + 256 * 128);
            #pragma unroll
            for (int j = 0; j < 4; j++) {
                bool en = (kt > 0) || (j > 0);
                mma_tc(tmem,       ad + j * 2, bd0 + j * 2, TC_IDESC, en);
                mma_tc(tmem + 256, ad + j * 2, bd1 + j * 2, TC_IDESC, en);
            }
            TC_COMMIT(sbase + 16 + 8 * cur);
        }
        // MMA of kt-1 must finish before its buffer (cur^1) is overwritten
        if (kt >= 1) MBAR_WAIT(sbase + 16 + 8 * (cur ^ 1), ((kt - 1) / 2) & 1);
        if (kt + 1 < nk) loadStage(cur ^ 1, (kt + 1) * TC_BK);
        CP_COMMIT();
    }
    MBAR_WAIT(sbase + 16 + 8 * ((nk - 1) & 1), ((nk - 1) / 2) & 1);

    __syncthreads();
    TC_FENCE_AFTER();

    // epilogue: warp w reads rows (w&3)*32..; col half (w>>2)*256, 8 chunks of 32
    float* myep = (float*)(smem + 1024) + warp * (32 * 33);
    int rbase = m0 + (warp & 3) * 32;
    int cbase = (warp >> 2) * 256;

    #pragma unroll
    for (int ch = 0; ch < 8; ch++) {
        int c0 = cbase + ch * 32;
        uint32_t regs[32];
        TC_LD_X32(regs, tmem + c0);
        TC_WAIT_LD();
        #pragma unroll
        for (int c = 0; c < 32; c++) {
            float v = __uint_as_float(regs[c]);
            if (!GN || (n0 + c0 + c) < N) {
                v += bias[n0 + c0 + c];
                if (RELU) v = fmaxf(v, 0.f);
                if (TFO)  v = tf32r(v);
            }
            myep[lane * 33 + c] = v;
        }
        __syncwarp();
        int col = n0 + c0 + lane;
        #pragma unroll
        for (int i = 0; i < 32; i++) {
            if (!GN || col < N)
                C[(size_t)(rbase + i) * ldc + col] = myep[i * 33 + lane];
        }
        __syncwarp();
    }

    __syncthreads();
    if (warp == 0) { TC_FENCE_BEFORE(); TC_DEALLOC(tmem, 512); }
#endif  // TC_AVAIL (else: empty stub — host detects via numRegs and falls back)
}

// ================= fused flash attention (mma.sync tf32) =================
constexpr int AT_SMEM = 174080;

__global__ void __launch_bounds__(256, 1)
k_attn(const float* __restrict__ qkv, float* __restrict__ ao)
{
    extern __shared__ float sm_[];
    float* Qs   = sm_;               // [128][68]
    float* Ks   = Qs + 128 * 68;
    float* Vs   = Ks + 128 * 68;
    float* Ps   = Vs + 128 * 68;     // [128][132]
    float* rmx  = Ps + 128 * 132;
    float* rsm  = rmx + 256;

    const int tid = threadIdx.x, lane = tid & 31, warp = tid >> 5;
    const int wm = warp >> 1, wn = warp & 1;
    const int g = lane >> 2, t4 = lane & 3;
    const int bh = blockIdx.y, b = bh >> 3, h = bh & 7;
    const int qrow0 = b * 512 + blockIdx.x * 128;
    const int kvbase = b * 512;

    #pragma unroll
    for (int r = 0; r < 8; r++) {
        int i = tid + r * 256;
        int row = i >> 4, c = (i & 15) << 2;
        float4 v = *(const float4*)&qkv[(size_t)(qrow0 + row) * 1536 + h * 64 + c];
        Qs[row * 68 + c]     = v.x * 0.125f;
        Qs[row * 68 + c + 1] = v.y * 0.125f;
        Qs[row * 68 + c + 2] = v.z * 0.125f;
        Qs[row * 68 + c + 3] = v.w * 0.125f;
    }

    float m_i[2][2], l_i[2][2];
    float oa[2][4][4];
    #pragma unroll
    for (int i = 0; i < 2; i++)
        #pragma unroll
        for (int hf = 0; hf < 2; hf++) { m_i[i][hf] = -1e30f; l_i[i][hf] = 0.f; }
    #pragma unroll
    for (int i = 0; i < 2; i++)
        #pragma unroll
        for (int j = 0; j < 4; j++)
            #pragma unroll
            for (int q = 0; q < 4; q++) oa[i][j][q] = 0.f;

    for (int kc = 0; kc < 4; kc++) {
        __syncthreads();
        int kvrow0 = kvbase + kc * 128;
        #pragma unroll
        for (int r = 0; r < 8; r++) {
            int i = tid + r * 256;
            int row = i >> 4, c = (i & 15) << 2;
            cp16(&Ks[row * 68 + c], &qkv[(size_t)(kvrow0 + row) * 1536 + 512 + h * 64 + c]);
        }
        #pragma unroll
        for (int r = 0; r < 8; r++) {
            int i = tid + r * 256;
            int row = i >> 4, c = (i & 15) << 2;
            cp16(&Vs[row * 68 + c], &qkv[(size_t)(kvrow0 + row) * 1536 + 1024 + h * 64 + c]);
        }
        CP_COMMIT();
        CP_WAIT0();
        __syncthreads();

        float s[2][8][4];
        #pragma unroll
        for (int i = 0; i < 2; i++)
            #pragma unroll
            for (int j = 0; j < 8; j++)
                #pragma unroll
                for (int q = 0; q < 4; q++) s[i][j][q] = 0.f;

        #pragma unroll
        for (int ks = 0; ks < 8; ks++) {
            uint32_t af[2][4], bf[8][2];
            #pragma unroll
            for (int i = 0; i < 2; i++) {
                int row = wm * 32 + i * 16 + g;
                af[i][0] = __float_as_uint(Qs[row * 68 + ks * 8 + t4]);
                af[i][1] = __float_as_uint(Qs[(row + 8) * 68 + ks * 8 + t4]);
                af[i][2] = __float_as_uint(Qs[row * 68 + ks * 8 + t4 + 4]);
                af[i][3] = __float_as_uint(Qs[(row + 8) * 68 + ks * 8 + t4 + 4]);
            }
            #pragma unroll
            for (int j = 0; j < 8; j++) {
                int nc = wn * 64 + j * 8 + g;
                bf[j][0] = __float_as_uint(Ks[nc * 68 + ks * 8 + t4]);
                bf[j][1] = __float_as_uint(Ks[nc * 68 + ks * 8 + t4 + 4]);
            }
            #pragma unroll
            for (int i = 0; i < 2; i++)
                #pragma unroll
                for (int j = 0; j < 8; j++)
                    mma_tf32(s[i][j], af[i][0], af[i][1], af[i][2], af[i][3],
                             bf[j][0], bf[j][1]);
        }

        float mn[2][2];
        #pragma unroll
        for (int i = 0; i < 2; i++)
            #pragma unroll
            for (int hf = 0; hf < 2; hf++) {
                float v = -1e30f;
                #pragma unroll
                for (int j = 0; j < 8; j++)
                    v = fmaxf(v, fmaxf(s[i][j][2 * hf], s[i][j][2 * hf + 1]));
                v = fmaxf(v, __shfl_xor_sync(0xFFFFFFFF, v, 1));
                v = fmaxf(v, __shfl_xor_sync(0xFFFFFFFF, v, 2));
                mn[i][hf] = v;
            }
        if (t4 == 0) {
            #pragma unroll
            for (int i = 0; i < 2; i++)
                #pragma unroll
                for (int hf = 0; hf < 2; hf++)
                    rmx[(wm * 32 + i * 16 + g + 8 * hf) * 2 + wn] = mn[i][hf];
        }
        __syncthreads();
        float sc[2][2];
        #pragma unroll
        for (int i = 0; i < 2; i++)
            #pragma unroll
            for (int hf = 0; hf < 2; hf++) {
                int row = wm * 32 + i * 16 + g + 8 * hf;
                float cm = fmaxf(rmx[row * 2], rmx[row * 2 + 1]);
                float nm = fmaxf(m_i[i][hf], cm);
                sc[i][hf] = __expf(m_i[i][hf] - nm);
                mn[i][hf] = nm;
            }
        #pragma unroll
        for (int i = 0; i < 2; i++)
            #pragma unroll
            for (int j = 0; j < 4; j++) {
                oa[i][j][0] *= sc[i][0]; oa[i][j][1] *= sc[i][0];
                oa[i][j][2] *= sc[i][1]; oa[i][j][3] *= sc[i][1];
            }
        float smv[2][2] = {{0.f, 0.f}, {0.f, 0.f}};
        #pragma unroll
        for (int i = 0; i < 2; i++) {
            int row = wm * 32 + i * 16 + g;
            #pragma unroll
            for (int j = 0; j < 8; j++) {
                int col = wn * 64 + j * 8 + 2 * t4;
                float p0 = __expf(s[i][j][0] - mn[i][0]);
                float p1 = __expf(s[i][j][1] - mn[i][0]);
                float p2 = __expf(s[i][j][2] - mn[i][1]);
                float p3 = __expf(s[i][j][3] - mn[i][1]);
                smv[i][0] += p0 + p1;
                smv[i][1] += p2 + p3;
                Ps[row * 132 + col]           = tf32r(p0);
                Ps[row * 132 + col + 1]       = tf32r(p1);
                Ps[(row + 8) * 132 + col]     = tf32r(p2);
                Ps[(row + 8) * 132 + col + 1] = tf32r(p3);
            }
        }
        #pragma unroll
        for (int i = 0; i < 2; i++)
            #pragma unroll
            for (int hf = 0; hf < 2; hf++) {
                float v = smv[i][hf];
                v += __shfl_xor_sync(0xFFFFFFFF, v, 1);
                v += __shfl_xor_sync(0xFFFFFFFF, v, 2);
                smv[i][hf] = v;
            }
        if (t4 == 0) {
            #pragma unroll
            for (int i = 0; i < 2; i++)
                #pragma unroll
                for (int hf = 0; hf < 2; hf++)
                    rsm[(wm * 32 + i * 16 + g + 8 * hf) * 2 + wn] = smv[i][hf];
        }
        __syncthreads();
        #pragma unroll
        for (int i = 0; i < 2; i++)
            #pragma unroll
            for (int hf = 0; hf < 2; hf++) {
                int row = wm * 32 + i * 16 + g + 8 * hf;
                l_i[i][hf] = l_i[i][hf] * sc[i][hf] + rsm[row * 2] + rsm[row * 2 + 1];
                m_i[i][hf] = mn[i][hf];
            }

        #pragma unroll
        for (int ks = 0; ks < 16; ks++) {
            uint32_t af[2][4], bf[4][2];
            #pragma unroll
            for (int i = 0; i < 2; i++) {
                int row = wm * 32 + i * 16 + g;
                af[i][0] = __float_as_uint(Ps[row * 132 + ks * 8 + t4]);
                af[i][1] = __float_as_uint(Ps[(row + 8) * 132 + ks * 8 + t4]);
                af[i][2] = __float_as_uint(Ps[row * 132 + ks * 8 + t4 + 4]);
                af[i][3] = __float_as_uint(Ps[(row + 8) * 132 + ks * 8 + t4 + 4]);
            }
            #pragma unroll
            for (int j = 0; j < 4; j++) {
                int nc = wn * 32 + j * 8 + g;
                bf[j][0] = __float_as_uint(Vs[(ks * 8 + t4) * 68 + nc]);
                bf[j][1] = __float_as_uint(Vs[(ks * 8 + t4 + 4) * 68 + nc]);
            }
            #pragma unroll
            for (int i = 0; i < 2; i++)
                #pragma unroll
                for (int j = 0; j < 4; j++)
                    mma_tf32(oa[i][j], af[i][0], af[i][1], af[i][2], af[i][3],
                             bf[j][0], bf[j][1]);
        }
    }

    #pragma unroll
    for (int i = 0; i < 2; i++) {
        float r0 = 1.f / l_i[i][0], r1 = 1.f / l_i[i][1];
        int row = qrow0 + wm * 32 + i * 16 + g;
        #pragma unroll
        for (int j = 0; j < 4; j++) {
            int col = h * 64 + wn * 32 + j * 8 + 2 * t4;
            *(float2*)&ao[(size_t)row * 512 + col] =
                make_float2(tf32r(oa[i][j][0] * r0), tf32r(oa[i][j][1] * r0));
            *(float2*)&ao[(size_t)(row + 8) * 512 + col] =
                make_float2(tf32r(oa[i][j][2] * r1), tf32r(oa[i][j][3] * r1));
        }
    }
}

// ================= mma.sync GEMM (fallback path) =================
template<int BM,int BN,int WARPS_M,int WARPS_N,bool TB,bool RELU,bool GN,bool TFO>
__global__ void __launch_bounds__(WARPS_M*WARPS_N*32)
k_mma(int M, int N, int K,
      const float* __restrict__ Ag, int lda, long long sA1, long long sA2,
      const float* __restrict__ Bg, int ldb, long long sB1, long long sB2,
      float* __restrict__ Cg, int ldc, long long sC1, long long sC2,
      int zdiv, const float* __restrict__ bias, float alpha)
{
    constexpr int BK = 16;
    constexpr int NT = WARPS_M * WARPS_N * 32;
    constexpr int WM = BM / WARPS_M, WN = BN / WARPS_N;
    constexpr int MI = WM / 16, NI = WN / 8;
    constexpr int AST = BK + 4;
    constexpr int BROWS = TB ? BN : BK;
    constexpr int BCOLS = TB ? (BK + 4) : (BN + 8);

    __shared__ __align__(16) float As[2][BM][AST];
    __shared__ __align__(16) float Bs[2][BROWS][BCOLS];

    const int bz = blockIdx.z;
    const int z1 = bz / zdiv, z2 = bz - z1 * zdiv;
    const float* A  = Ag + z1 * sA1 + z2 * sA2;
    const float* Bp = Bg + z1 * sB1 + z2 * sB2;
    float* C        = Cg + z1 * sC1 + z2 * sC2;

    const int m0 = blockIdx.y * BM, n0 = blockIdx.x * BN;
    const int tid  = threadIdx.x;
    const int lane = tid & 31, warp = tid >> 5;
    const int wm = warp / WARPS_N, wn = warp - wm * WARPS_N;
    const int g = lane >> 2, t4 = lane & 3;

    float acc[MI][NI][4];
    #pragma unroll
    for (int i = 0; i < MI; i++)
        #pragma unroll
        for (int j = 0; j < NI; j++)
            #pragma unroll
            for (int q = 0; q < 4; q++) acc[i][j][q] = 0.f;

    auto loadTiles = [&](int st, int k0) {
        #pragma unroll
        for (int r = 0; r < (BM * (BK/4)) / NT; r++) {
            int i = tid + r * NT;
            int m = i >> 2;
            int c = (i & 3) << 2;
            cp16(&As[st][m][c], &A[(size_t)(m0 + m) * lda + k0 + c]);
        }
        if (TB) {
            #pragma unroll
            for (int r = 0; r < (BN * (BK/4)) / NT; r++) {
                int i = tid + r * NT;
                int n = i >> 2;
                int c = (i & 3) << 2;
                int gn = n0 + n;
                if (GN) {
                    bool ok = gn < N;
                    cp16p(&Bs[st][n][c], ok ? &Bp[(size_t)gn * ldb + k0 + c] : (const float*)Bp, ok);
                } else {
                    cp16(&Bs[st][n][c], &Bp[(size_t)gn * ldb + k0 + c]);
                }
            }
        } else {
            #pragma unroll
            for (int r = 0; r < (BK * (BN/4)) / NT; r++) {
                int i = tid + r * NT;
                int kk = i / (BN/4);
                int c  = (i - kk * (BN/4)) << 2;
                cp16(&Bs[st][kk][c], &Bp[(size_t)(k0 + kk) * ldb + n0 + c]);
            }
        }
    };

    const int nk = K / BK;
    loadTiles(0, 0);
    CP_COMMIT();

    for (int kt = 0; kt < nk; kt++) {
        int cur = kt & 1;
        if (kt + 1 < nk) loadTiles(cur ^ 1, (kt + 1) * BK);
        CP_COMMIT();
        CP_WAIT1();
        __syncthreads();

        #pragma unroll
        for (int ks = 0; ks < 2; ks++) {
            uint32_t af[MI][4], bf[NI][2];
            #pragma unroll
            for (int i = 0; i < MI; i++) {
                int mr = wm * WM + i * 16 + g;
                af[i][0] = __float_as_uint(As[cur][mr    ][ks*8 + t4    ]);
                af[i][1] = __float_as_uint(As[cur][mr + 8][ks*8 + t4    ]);
                af[i][2] = __float_as_uint(As[cur][mr    ][ks*8 + t4 + 4]);
                af[i][3] = __float_as_uint(As[cur][mr + 8][ks*8 + t4 + 4]);
            }
            #pragma unroll
            for (int j = 0; j < NI; j++) {
                int nc = wn * WN + j * 8 + g;
                if (TB) {
                    bf[j][0] = __float_as_uint(Bs[cur][nc][ks*8 + t4    ]);
                    bf[j][1] = __float_as_uint(Bs[cur][nc][ks*8 + t4 + 4]);
                } else {
                    bf[j][0] = __float_as_uint(Bs[cur][ks*8 + t4    ][nc]);
                    bf[j][1] = __float_as_uint(Bs[cur][ks*8 + t4 + 4][nc]);
                }
            }
            #pragma unroll
            for (int i = 0; i < MI; i++)
                #pragma unroll
                for (int j = 0; j < NI; j++)
                    mma_tf32(acc[i][j], af[i][0], af[i][1], af[i][2], af[i][3],
                             bf[j][0], bf[j][1]);
        }
        __syncthreads();
    }

    #pragma unroll
    for (int i = 0; i < MI; i++) {
        int r0 = m0 + wm * WM + i * 16 + g;
        #pragma unroll
        for (int j = 0; j < NI; j++) {
            int col = n0 + wn * WN + j * 8 + t4 * 2;
            if (GN && col >= N) continue;
            float b0v = 0.f, b1v = 0.f;
            if (bias) { b0v = bias[col]; b1v = bias[col + 1]; }
            float v0 = acc[i][j][0] * alpha + b0v;
            float v1 = acc[i][j][1] * alpha + b1v;
            float v2 = acc[i][j][2] * alpha + b0v;
            float v3 = acc[i][j][3] * alpha + b1v;
            if (RELU) {
                v0 = fmaxf(v0, 0.f); v1 = fmaxf(v1, 0.f);
                v2 = fmaxf(v2, 0.f); v3 = fmaxf(v3, 0.f);
            }
            if (TFO) {
                v0 = tf32r(v0); v1 = tf32r(v1); v2 = tf32r(v2); v3 = tf32r(v3);
            }
            *reinterpret_cast<float2*>(&C[(size_t)r0 * ldc + col])       = make_float2(v0, v1);
            *reinterpret_cast<float2*>(&C[(size_t)(r0 + 8) * ldc + col]) = make_float2(v2, v3);
        }
    }
}

// ---------------- residual add + layernorm ----------------
__global__ void k_add_ln(const float* __restrict__ xin, const float* __restrict__ res,
                         const float* __restrict__ g, const float* __restrict__ b,
                         float* __restrict__ xout, float* __restrict__ xtf)
{
    int row = blockIdx.x, t = threadIdx.x;
    long long base = (long long)row * D;
    float v0 = xin[base + t]       + res[base + t];
    float v1 = xin[base + t + 256] + res[base + t + 256];
    __shared__ float red[256];
    red[t] = v0 + v1; __syncthreads();
    for (int o = 128; o > 0; o >>= 1) { if (t < o) red[t] += red[t+o]; __syncthreads(); }
    float mean = red[0] * (1.f / D); __syncthreads();
    red[t] = v0*v0 + v1*v1; __syncthreads();
    for (int o = 128; o > 0; o >>= 1) { if (t < o) red[t] += red[t+o]; __syncthreads(); }
    float var = red[0] * (1.f / D) - mean*mean;
    float rs = rsqrtf(var + 1e-5f);
    float o0 = (v0 - mean) * rs * g[t]       + b[t];
    float o1 = (v1 - mean) * rs * g[t + 256] + b[t + 256];
    xout[base + t]       = o0;
    xout[base + t + 256] = o1;
    xtf [base + t]       = tf32r(o0);
    xtf [base + t + 256] = tf32r(o1);
}

// ---------------- embedding ----------------
__global__ void k_embed(const int* __restrict__ src, const float* __restrict__ emb,
                        const float* __restrict__ pos, float* __restrict__ x,
                        float* __restrict__ xtf)
{
    int idx = blockIdx.x * blockDim.x + threadIdx.x;
    int t = idx >> 9, d = idx & 511;
    float v = emb[(long long)src[t] * D + d] * SQRTD_F + pos[(t & 511) * D + d];
    x[idx]   = v;
    xtf[idx] = tf32r(v);
}

// ---------------- round static weights ----------------
__global__ void k_round_w(const float* __restrict__ opw, const float* __restrict__ ow, int nOw)
{
    int i = blockIdx.x * blockDim.x + threadIdx.x;
    if (i < L * D * D) d_wr[i] = tf32r(opw[i]);
    if (i < nOw)       d_owr[i] = tf32r(ow[i]);
}

// ---------------- batched prune pipeline ----------------
__device__ __forceinline__ const float* slot_w(int slot, const float* ipw,
                                               const float* w1, const float* w2, int& n)
{
    int t = slot / 6, l = slot - t * 6;
    if (t == 0) { n = 3 * D * D; return ipw + (size_t)l * 3 * D * D; }
    n = F * D;
    return (t == 1) ? w1 + (size_t)l * F * D : w2 + (size_t)l * F * D;
}

__global__ void k_zero_all()
{
    int i = blockIdx.x * blockDim.x + threadIdx.x;
    if (i < NSLOT * 2 * 65536) d_h2g[i] = 0;
    if (i < NSLOT * 4096)      d_h1g[i] = 0;
    if (i < NSLOT * 32)        d_h3g[i] = 0;
}

__global__ void k_etch_all(const float* __restrict__ ipw, const float* __restrict__ w1,
                           const float* __restrict__ w2)
{
    int slot = blockIdx.y;
    int n;
    const float* w = slot_w(slot, ipw, w1, w2, n);
    float inv = 1.f / (float)(n - 1);
    float* aout = d_abs_all + (size_t)slot * SLOT_STRIDE;
    unsigned* h1 = d_h1g + slot * 4096;

    __shared__ unsigned h[4096];
    for (int j = threadIdx.x; j < 4096; j += blockDim.x) h[j] = 0;
    __syncthreads();
    int stride = gridDim.x * blockDim.x;
    for (int i = blockIdx.x * blockDim.x + threadIdx.x; i < n; i += stride) {
        float wv = w[i];
        float b0 = sinf(wv * PI_F);
        b0 = fminf(fmaxf(b0, -1.f), 1.f);
        float bl = b0 + b0 * cosf((float)i * inv + THIRD_F) * 1.5f;
        float e = cosf(bl * PI2_F) + bl * bl * DEVPI_F;
        float a = fabsf(e);
        aout[i] = a;
        atomicAdd(&h[__float_as_uint(a) >> 20], 1u);
    }
    __syncthreads();
    for (int j = threadIdx.x; j < 4096; j += blockDim.x) {
        unsigned c = h[j];
        if (c) atomicAdd(&h1[j], c);
    }
}

__global__ void k_scan1_all(const float* ipw, const float* w1, const float* w2)
{
    int slot = blockIdx.x;
    int n; slot_w(slot, ipw, w1, w2, n);
    unsigned rA = (unsigned)((n - 1) >> 2);
    unsigned rB = rA + 1;
    const unsigned* h1 = d_h1g + slot * 4096;
    unsigned* sel = d_selg + slot * 8;

    __shared__ unsigned part[256];
    __shared__ unsigned pref[256];
    int t = threadIdx.x, base = t * 16;
    unsigned c[16]; unsigned s = 0;
    for (int j = 0; j < 16; j++) { c[j] = h1[base + j]; s += c[j]; }
    part[t] = s; __syncthreads();
    if (t == 0) { unsigned a = 0; for (int i = 0; i < 256; i++) { pref[i] = a; a += part[i]; } }
    __syncthreads();
    unsigned p = pref[t];
    for (int j = 0; j < 16; j++) {
        if (rA >= p && rA < p + c[j]) { sel[0] = base + j; sel[1] = rA - p; }
        if (rB >= p && rB < p + c[j]) { sel[2] = base + j; sel[3] = rB - p; }
        p += c[j];
    }
}

__global__ void k_hist2_all(const float* ipw, const float* w1, const float* w2)
{
    int slot = blockIdx.y;
    int n; slot_w(slot, ipw, w1, w2, n);
    const float* ab = d_abs_all + (size_t)slot * SLOT_STRIDE;
    const unsigned* sel = d_selg + slot * 8;
    unsigned* h2 = d_h2g + (size_t)slot * 131072;
    unsigned sA = sel[0], sB = sel[2];
    int stride = gridDim.x * blockDim.x;
    for (int i = blockIdx.x * blockDim.x + threadIdx.x; i < n; i += stride) {
        unsigned u = __float_as_uint(ab[i]);
        unsigned hi = u >> 20, mid = (u >> 4) & 0xFFFFu;
        if (hi == sA) atomicAdd(&h2[mid], 1u);
        if (hi == sB) atomicAdd(&h2[65536 + mid], 1u);
    }
}

__global__ void k_scan2_all()
{
    int slot = blockIdx.x;
    unsigned* sel = d_selg + slot * 8;
    __shared__ unsigned part[256];
    __shared__ unsigned pref[256];
    int t = threadIdx.x;
    for (int sidx = 0; sidx < 2; sidx++) {
        unsigned rank = sel[1 + sidx * 2];
        const unsigned* hb = d_h2g + (size_t)slot * 131072 + sidx * 65536;
        int base = t * 256;
        unsigned s = 0;
        for (int j = 0; j < 256; j++) s += hb[base + j];
        part[t] = s; __syncthreads();
        if (t == 0) { unsigned a = 0; for (int i = 0; i < 256; i++) { pref[i] = a; a += part[i]; } }
        __syncthreads();
        unsigned p = pref[t];
        for (int j = 0; j < 256; j++) {
            unsigned c = hb[base + j];
            if (rank >= p && rank < p + c) { sel[4 + sidx*2] = base + j; sel[5 + sidx*2] = rank - p; }
            p += c;
        }
        __syncthreads();
    }
}

__global__ void k_hist3_all(const float* ipw, const float* w1, const float* w2)
{
    int slot = blockIdx.y;
    int n; slot_w(slot, ipw, w1, w2, n);
    const float* ab = d_abs_all + (size_t)slot * SLOT_STRIDE;
    const unsigned* sel = d_selg + slot * 8;
    unsigned* h3 = d_h3g + slot * 32;
    unsigned kA = (sel[0] << 16) | sel[4];
    unsigned kB = (sel[2] << 16) | sel[6];
    int stride = gridDim.x * blockDim.x;
    for (int i = blockIdx.x * blockDim.x + threadIdx.x; i < n; i += stride) {
        unsigned u = __float_as_uint(ab[i]);
        unsigned top = u >> 4;
        if (top == kA) atomicAdd(&h3[u & 15u], 1u);
        if (top == kB) atomicAdd(&h3[16 + (u & 15u)], 1u);
    }
}

__global__ void k_thr_all(const float* ipw, const float* w1, const float* w2)
{
    int slot = blockIdx.x * blockDim.x + threadIdx.x;
    if (slot >= NSLOT) return;
    int n; slot_w(slot, ipw, w1, w2, n);
    float frac = 0.25f * (float)((n - 1) & 3);
    const unsigned* sel = d_selg + slot * 8;
    const unsigned* h3 = d_h3g + slot * 32;
    unsigned remA = sel[5]; unsigned lowA = 0;
    for (int j = 0; j < 16; j++) { unsigned c = h3[j]; if (remA < c) { lowA = j; break; } remA -= c; }
    unsigned remB = sel[7]; unsigned lowB = 0;
    for (int j = 0; j < 16; j++) { unsigned c = h3[16 + j]; if (remB < c) { lowB = j; break; } remB -= c; }
    float vA = __uint_as_float((sel[0] << 20) | (sel[4] << 4) | lowA);
    float vB = __uint_as_float((sel[2] << 20) | (sel[6] << 4) | lowB);
    d_thrg[slot] = vA + frac * (vB - vA);
}

__global__ void k_mask_all(const float* __restrict__ ipw, const float* __restrict__ w1,
                           const float* __restrict__ w2)
{
    int slot = blockIdx.y;
    int n;
    const float* w = slot_w(slot, ipw, w1, w2, n);
    int i = blockIdx.x * blockDim.x + threadIdx.x;
    if (i >= n) return;
    float thr = d_thrg[slot];
    d_wp[(size_t)slot * SLOT_STRIDE + i] =
        (d_abs_all[(size_t)slot * SLOT_STRIDE + i] > thr) ? tf32r(w[i]) : 0.f;
}

// ---------------- entry point ----------------
extern "C" void kernel_launch(void* const* d_in, const int* in_sizes, int n_in,
                              void* d_out, int out_size)
{
    const int*   src = (const int*)  d_in[0];
    const float* emb = (const float*)d_in[1];
    const float* pos = (const float*)d_in[2];
    const float* ipw = (const float*)d_in[3];
    const float* ipb = (const float*)d_in[4];
    const float* opw = (const float*)d_in[5];
    const float* opb = (const float*)d_in[6];
    const float* l1g = (const float*)d_in[7];
    const float* l1b = (const float*)d_in[8];
    const float* l2g = (const float*)d_in[9];
    const float* l2b = (const float*)d_in[10];
    const float* w1  = (const float*)d_in[11];
    const float* b1  = (const float*)d_in[12];
    const float* w2  = (const float*)d_in[13];
    const float* b2  = (const float*)d_in[14];
    const float* ow  = (const float*)d_in[15];
    const float* ob  = (const float*)d_in[16];
    const int V = in_sizes[16];
    float* out = (float*)d_out;

    float *px, *pxtf, *pqkv, *pao, *pff, *ptmp, *pwp, *pwr, *powr;
    cudaGetSymbolAddress((void**)&px,   d_x);
    cudaGetSymbolAddress((void**)&pxtf, d_xtf);
    cudaGetSymbolAddress((void**)&pqkv, d_qkv);
    cudaGetSymbolAddress((void**)&pao,  d_ao);
    cudaGetSymbolAddress((void**)&pff,  d_ff);
    cudaGetSymbolAddress((void**)&ptmp, d_tmp);
    cudaGetSymbolAddress((void**)&pwp,  d_wp);
    cudaGetSymbolAddress((void**)&pwr,  d_wr);
    cudaGetSymbolAddress((void**)&powr, d_owr);

    cudaFuncAttributes fa{};
    cudaFuncGetAttributes(&fa, k_tc<false,false,true>);
    const bool use_tc = fa.numRegs > 40;

    if (use_tc) {
        cudaFuncSetAttribute(k_tc<false,false,true >, cudaFuncAttributeMaxDynamicSharedMemorySize, TC_SMEM);
        cudaFuncSetAttribute(k_tc<false,false,false>, cudaFuncAttributeMaxDynamicSharedMemorySize, TC_SMEM);
        cudaFuncSetAttribute(k_tc<true ,false,true >, cudaFuncAttributeMaxDynamicSharedMemorySize, TC_SMEM);
        cudaFuncSetAttribute(k_tc<false,true ,false>, cudaFuncAttributeMaxDynamicSharedMemorySize, TC_SMEM);
    }
    cudaFuncSetAttribute(k_attn, cudaFuncAttributeMaxDynamicSharedMemorySize, AT_SMEM);

    k_embed<<<MT * D / 256, 256>>>(src, emb, pos, px, pxtf);
    k_round_w<<<(V * D + 255) / 256, 256>>>(opw, ow, V * D);

    k_zero_all<<<(NSLOT * 2 * 65536 + 255) / 256, 256>>>();
    k_etch_all <<<dim3(128, NSLOT), 256>>>(ipw, w1, w2);
    k_scan1_all<<<NSLOT, 256>>>(ipw, w1, w2);
    k_hist2_all<<<dim3(128, NSLOT), 256>>>(ipw, w1, w2);
    k_scan2_all<<<NSLOT, 256>>>();
    k_hist3_all<<<dim3(128, NSLOT), 256>>>(ipw, w1, w2);
    k_thr_all  <<<1, 32>>>(ipw, w1, w2);
    k_mask_all <<<dim3(4096, NSLOT), 256>>>(ipw, w1, w2);

    const int MT128 = MT / 128;   // 64

    for (int l = 0; l < L; l++) {
        const float* wi_l = pwp + (size_t)(0 * 6 + l) * SLOT_STRIDE;
        const float* w1_l = pwp + (size_t)(1 * 6 + l) * SLOT_STRIDE;
        const float* w2_l = pwp + (size_t)(2 * 6 + l) * SLOT_STRIDE;

        // qkv = x @ wi^T + b (output tf32-rounded: feeds attention)
        if (use_tc)
            k_tc<false,false,true><<<dim3((3*D)/TC_BN, MT128), 256, TC_SMEM>>>(
                3*D, D, pxtf, D, wi_l, D, pqkv, 3*D, ipb + (size_t)l * 3 * D);
        else
            k_mma<128,128,2,2,true,false,false,true><<<dim3((3*D)/128, MT/128, 1), 128>>>(
                MT, 3*D, D, pxtf, D, 0, 0, wi_l, D, 0, 0, pqkv, 3*D, 0, 0, 1,
                ipb + (size_t)l * 3 * D, 1.f);

        // fused flash attention
        k_attn<<<dim3(4, BH), 256, AT_SMEM>>>(pqkv, pao);

        // out projection
        if (use_tc)
            k_tc<false,false,false><<<dim3(D/TC_BN, MT128), 256, TC_SMEM>>>(
                D, D, pao, D, pwr + (size_t)l*D*D, D, ptmp, D, opb + (size_t)l*D);
        else
            k_mma<128,128,2,2,true,false,false,false><<<dim3(D/128, MT/128, 1), 128>>>(
                MT, D, D, pao, D, 0, 0, pwr + (size_t)l*D*D, D, 0, 0,
                ptmp, D, 0, 0, 1, opb + (size_t)l*D, 1.f);
        k_add_ln<<<MT, 256>>>(px, ptmp, l1g + (size_t)l*D, l1b + (size_t)l*D, px, pxtf);

        // feed-forward
        if (use_tc) {
            k_tc<true,false,true><<<dim3(F/TC_BN, MT128), 256, TC_SMEM>>>(
                F, D, pxtf, D, w1_l, D, pff, F, b1 + (size_t)l*F);
            k_tc<false,false,false><<<dim3(D/TC_BN, MT128), 256, TC_SMEM>>>(
                D, F, pff, F, w2_l, F, ptmp, D, b2 + (size_t)l*D);
        } else {
            k_mma<128,128,2,2,true,true,false,true><<<dim3(F/128, MT/128, 1), 128>>>(
                MT, F, D, pxtf, D, 0, 0, w1_l, D, 0, 0, pff, F, 0, 0, 1,
                b1 + (size_t)l*F, 1.f);
            k_mma<128,128,2,2,true,false,false,false><<<dim3(D/128, MT/128, 1), 128>>>(
                MT, D, F, pff, F, 0, 0, w2_l, F, 0, 0, ptmp, D, 0, 0, 1,
                b2 + (size_t)l*D, 1.f);
        }
        k_add_ln<<<MT, 256>>>(px, ptmp, l2g + (size_t)l*D, l2b + (size_t)l*D, px, pxtf);
    }

    // logits
    if (use_tc)
        k_tc<false,true,false><<<dim3((V + TC_BN - 1)/TC_BN, MT128), 256, TC_SMEM>>>(
            V, D, pxtf, D, powr, D, out, V, ob);
    else
        k_mma<128,128,2,2,true,false,true,false><<<dim3((V + 127) / 128, MT / 128, 1), 128>>>(
            MT, V, D, pxtf, D, 0, 0, powr, D, 0, 0, out, V, 0, 0, 1, ob, 1.f);
}

// round 9
// speedup vs baseline: 2.0207x; 1.2374x over previous
#include <cuda_runtime.h>
#include <cstdint>
#include <math.h>

// ---------------- constants ----------------
#define PI_F      3.14159265358979323846f
#define PI2_F     9.86960440108935861883f
#define THIRD_F   2.09439510239319549231f
#define DEVPI_F   0.003183098861837907f
#define SQRTD_F   22.62741699796952f

constexpr int S  = 512;
constexpr int D  = 512;
constexpr int H  = 8;
constexpr int DH = 64;
constexpr int L  = 6;
constexpr int F  = 2048;
constexpr int BB = 16;
constexpr int MT = BB * S;   // 8192 tokens
constexpr int BH = BB * H;   // 128
constexpr int NSLOT = 18;
constexpr size_t SLOT_STRIDE = 1048576;
constexpr int VMAX = 10240;

// Feature gate: tcgen05 only exists on arch-specific (sm_103a) / family (sm_103f) targets.
#if !defined(__CUDA_ARCH__) || defined(__CUDA_ARCH_FEAT_SM103_ALL) || defined(__CUDA_ARCH_SPECIFIC__) || defined(__CUDA_ARCH_FAMILY_SPECIFIC__)
#define TC_AVAIL 1
#else
#define TC_AVAIL 0
#endif

// ---------------- device scratch ----------------
__device__ __align__(128) float d_x   [MT * D];
__device__ __align__(128) float d_xtf [MT * D];
__device__ __align__(128) float d_qkv [MT * 3 * D];
__device__ __align__(128) float d_ao  [MT * D];
__device__ __align__(128) float d_ff  [MT * F];
__device__ __align__(128) float d_tmp [MT * D];
__device__ __align__(128) float d_wp  [NSLOT * SLOT_STRIDE];
__device__ __align__(128) float d_wr  [L * D * D];
__device__ __align__(128) float d_owr [VMAX * D];
__device__ __align__(128) float d_abs_all[NSLOT * SLOT_STRIDE];
__device__ unsigned d_h1g[NSLOT * 4096];
__device__ unsigned d_h2g[NSLOT * 2 * 65536];
__device__ unsigned d_h3g[NSLOT * 32];
__device__ unsigned d_selg[NSLOT * 8];
__device__ float d_thrg[NSLOT];

// ---------------- helpers ----------------
__device__ __forceinline__ float tf32r(float f) {
    uint32_t u;
    asm("cvt.rna.tf32.f32 %0, %1;" : "=r"(u) : "f"(f));
    return __uint_as_float(u);
}

__device__ __forceinline__ void mma_tf32(float c[4],
    uint32_t a0, uint32_t a1, uint32_t a2, uint32_t a3,
    uint32_t b0, uint32_t b1)
{
    asm volatile(
        "mma.sync.aligned.m16n8k8.row.col.f32.tf32.tf32.f32 "
        "{%0,%1,%2,%3}, {%4,%5,%6,%7}, {%8,%9}, {%0,%1,%2,%3};"
        : "+f"(c[0]), "+f"(c[1]), "+f"(c[2]), "+f"(c[3])
        : "r"(a0), "r"(a1), "r"(a2), "r"(a3), "r"(b0), "r"(b1));
}

__device__ __forceinline__ void cp16(void* d, const void* s) {
    uint32_t a = (uint32_t)__cvta_generic_to_shared(d);
    asm volatile("cp.async.cg.shared.global [%0], [%1], 16;" :: "r"(a), "l"(s));
}
__device__ __forceinline__ void cp16p(void* d, const void* s, bool p) {
    uint32_t a = (uint32_t)__cvta_generic_to_shared(d);
    int sz = p ? 16 : 0;
    asm volatile("cp.async.cg.shared.global [%0], [%1], 16, %2;" :: "r"(a), "l"(s), "r"(sz));
}
#define CP_COMMIT() asm volatile("cp.async.commit_group;")
#define CP_WAIT0()  asm volatile("cp.async.wait_group 0;")
#define CP_WAIT1()  asm volatile("cp.async.wait_group 1;")
#define CP_WAIT2()  asm volatile("cp.async.wait_group 2;")

// ================= tcgen05 tf32 GEMM (guarded) =================
constexpr int TC_BM = 128, TC_BN = 256, TC_BK = 32, TC_NS = 4;
constexpr int TC_ASZ = TC_BM * TC_BK * 4;       // 16384 (128 rows x 128B)
constexpr int TC_BSZ = TC_BN * TC_BK * 4;       // 32768 (256 rows x 128B)
constexpr int TC_SMEM = 1024 + TC_NS * (TC_ASZ + TC_BSZ);   // 197632

#if TC_AVAIL
__device__ __forceinline__ uint32_t elect1() {
    uint32_t pred;
    asm volatile("{\n\t.reg .pred p;\n\telect.sync _|p, 0xFFFFFFFF;\n\t"
                 "selp.b32 %0, 1, 0, p;\n\t}" : "=r"(pred));
    return pred;
}
#define MBAR_INIT(addr, cnt) \
    asm volatile("mbarrier.init.shared.b64 [%0], %1;" :: "r"(addr), "r"(cnt) : "memory")
#define MBAR_WAIT(addr, par) do { \
    asm volatile("{\n\t.reg .pred P1;\n\tWL%=:\n\t" \
        "mbarrier.try_wait.parity.acquire.cta.shared::cta.b64 P1, [%0], %1, 0x989680;\n\t" \
        "@P1 bra.uni WD%=;\n\tbra.uni WL%=;\n\tWD%=:\n\t}" \
        :: "r"(addr), "r"(par) : "memory"); \
} while (0)
#define TC_ALLOC(sm, n)   asm volatile("tcgen05.alloc.cta_group::1.sync.aligned.shared::cta.b32 [%0], %1;" :: "r"(sm), "r"(n) : "memory")
#define TC_DEALLOC(t, n)  asm volatile("tcgen05.dealloc.cta_group::1.sync.aligned.b32 %0, %1;" :: "r"(t), "r"(n))
#define TC_COMMIT(mb)     asm volatile("tcgen05.commit.cta_group::1.mbarrier::arrive::one.shared::cluster.b64 [%0];" :: "r"(mb) : "memory")
#define TC_FENCE_AFTER()  asm volatile("tcgen05.fence::after_thread_sync;" ::: "memory")
#define TC_FENCE_BEFORE() asm volatile("tcgen05.fence::before_thread_sync;" ::: "memory")
#define TC_WAIT_LD()      asm volatile("tcgen05.wait::ld.sync.aligned;" ::: "memory")
#define FENCE_PROXY()     asm volatile("fence.proxy.async.shared::cta;" ::: "memory")

#define TC_LD_X32(r, addr) \
    asm volatile("tcgen05.ld.sync.aligned.32x32b.x32.b32 " \
        "{%0, %1, %2, %3, %4, %5, %6, %7, %8, %9, %10, %11, %12, %13, %14, %15, " \
        " %16, %17, %18, %19, %20, %21, %22, %23, %24, %25, %26, %27, %28, %29, %30, %31}, [%32];" \
        : "=r"((r)[0]),  "=r"((r)[1]),  "=r"((r)[2]),  "=r"((r)[3]), \
          "=r"((r)[4]),  "=r"((r)[5]),  "=r"((r)[6]),  "=r"((r)[7]), \
          "=r"((r)[8]),  "=r"((r)[9]),  "=r"((r)[10]), "=r"((r)[11]), \
          "=r"((r)[12]), "=r"((r)[13]), "=r"((r)[14]), "=r"((r)[15]), \
          "=r"((r)[16]), "=r"((r)[17]), "=r"((r)[18]), "=r"((r)[19]), \
          "=r"((r)[20]), "=r"((r)[21]), "=r"((r)[22]), "=r"((r)[23]), \
          "=r"((r)[24]), "=r"((r)[25]), "=r"((r)[26]), "=r"((r)[27]), \
          "=r"((r)[28]), "=r"((r)[29]), "=r"((r)[30]), "=r"((r)[31]) \
        : "r"(addr))

static constexpr uint64_t SMEM_DESC_BASE =
    (uint64_t(2) << 61) | (uint64_t(1) << 46) | (uint64_t(64) << 32) | (uint64_t(1) << 16);
#define MK_DESC(a) (SMEM_DESC_BASE | ((uint64_t)((a) >> 4) & 0x3FFF))

__device__ __forceinline__ void mma_tc(uint32_t d, uint64_t ad, uint64_t bd,
                                       uint32_t idesc, bool en)
{
    uint32_t e = en ? 1 : 0;
    asm volatile(
        "{\n\t.reg .pred p;\n\tsetp.ne.u32 p, %4, 0;\n\t"
        "tcgen05.mma.cta_group::1.kind::tf32 [%0], %1, %2, %3, {%5,%5,%5,%5}, p;\n\t}"
        :: "r"(d), "l"(ad), "l"(bd), "r"(idesc), "r"(e), "r"(0u) : "memory");
}
#endif  // TC_AVAIL

constexpr uint32_t TC_IDESC =
    (1u << 4) | (2u << 7) | (2u << 10) | ((TC_BN / 8) << 17) | ((TC_BM / 16) << 24);

// C[m,n] = sum_k A[m,k]*B[n,k] + bias[n]; operands pre-rounded to tf32 values.
template<bool RELU, bool GN, bool TFO>
__global__ void __launch_bounds__(256, 1)
k_tc(int N, int K,
     const float* __restrict__ A, int lda,
     const float* __restrict__ B, int ldb,
     float* __restrict__ C, int ldc,
     const float* __restrict__ bias)
{
#if TC_AVAIL
    extern __shared__ char smem[];
    uint32_t sbase = (uint32_t)__cvta_generic_to_shared(smem);
    const int tid = threadIdx.x, lane = tid & 31, warp = tid >> 5;
    const int m0 = blockIdx.y * TC_BM, n0 = blockIdx.x * TC_BN;

    if (warp == 0) TC_ALLOC(sbase, 256);
    if (tid == 0) {
        #pragma unroll
        for (int s = 0; s < TC_NS; s++) MBAR_INIT(sbase + 16 + 8 * s, 1);
    }
    __syncthreads();
    uint32_t tmem;
    asm volatile("ld.shared.b32 %0, [%1];" : "=r"(tmem) : "r"(sbase));

    const uint32_t aoff = 1024, boff = 1024 + TC_NS * TC_ASZ;

    auto loadStage = [&](int st, int k0) {
        char* pa = smem + aoff + st * TC_ASZ;
        char* pb = smem + boff + st * TC_BSZ;
        #pragma unroll
        for (int r = 0; r < 4; r++) {
            int i = tid + r * 256;
            int m = i >> 3, c = i & 7;
            int cs = c ^ (m & 7);     // SW128
            cp16(pa + m * 128 + cs * 16, &A[(size_t)(m0 + m) * lda + k0 + c * 4]);
        }
        #pragma unroll
        for (int r = 0; r < 8; r++) {
            int i = tid + r * 256;
            int n = i >> 3, c = i & 7;
            int cs = c ^ (n & 7);
            int gn = n0 + n;
            if (GN) {
                bool ok = gn < N;
                cp16p(pb + n * 128 + cs * 16,
                      ok ? &B[(size_t)gn * ldb + k0 + c * 4] : (const float*)B, ok);
            } else {
                cp16(pb + n * 128 + cs * 16, &B[(size_t)gn * ldb + k0 + c * 4]);
            }
        }
    };

    const int nk = K / TC_BK;

    #pragma unroll
    for (int s = 0; s < 3; s++) { loadStage(s, s * TC_BK); CP_COMMIT(); }

    for (int kt = 0; kt < nk; kt++) {
        int cur = kt & 3;
        CP_WAIT2();               // stage kt data arrived (this thread)
        __syncthreads();          // all threads' data arrived
        FENCE_PROXY();
        if (warp == 0 && elect1()) {
            uint64_t ad = MK_DESC(sbase + aoff + cur * TC_ASZ);
            uint64_t bd = MK_DESC(sbase + boff + cur * TC_BSZ);
            #pragma unroll
            for (int j = 0; j < 4; j++)
                mma_tc(tmem, ad + j * 2, bd + j * 2, TC_IDESC, (kt > 0) || (j > 0));
            TC_COMMIT(sbase + 16 + 8 * cur);
        }
        if (kt >= 1) MBAR_WAIT(sbase + 16 + 8 * ((kt - 1) & 3), ((kt - 1) / 4) & 1);
        int kn = kt + 3;
        if (kn < nk) loadStage(kn & 3, kn * TC_BK);
        CP_COMMIT();
    }
    MBAR_WAIT(sbase + 16 + 8 * ((nk - 1) & 3), ((nk - 1) / 4) & 1);

    __syncthreads();
    TC_FENCE_AFTER();

    float* myep = (float*)(smem + 1024) + warp * (32 * 33);
    int rbase = m0 + (warp & 3) * 32;
    int cbase = (warp >> 2) * 128;

    #pragma unroll
    for (int ch = 0; ch < 4; ch++) {
        int c0 = cbase + ch * 32;
        uint32_t regs[32];
        TC_LD_X32(regs, tmem + c0);
        TC_WAIT_LD();
        #pragma unroll
        for (int c = 0; c < 32; c++) {
            float v = __uint_as_float(regs[c]);
            if (!GN || (n0 + c0 + c) < N) {
                v += bias[n0 + c0 + c];
                if (RELU) v = fmaxf(v, 0.f);
                if (TFO)  v = tf32r(v);
            }
            myep[lane * 33 + c] = v;
        }
        __syncwarp();
        int col = n0 + c0 + lane;
        #pragma unroll
        for (int i = 0; i < 32; i++) {
            if (!GN || col < N)
                C[(size_t)(rbase + i) * ldc + col] = myep[i * 33 + lane];
        }
        __syncwarp();
    }

    __syncthreads();
    if (warp == 0) { TC_FENCE_BEFORE(); TC_DEALLOC(tmem, 256); }
#endif  // TC_AVAIL (else: empty stub — host detects via numRegs and falls back)
}

// ================= fused flash attention (mma.sync tf32, pipelined KV) =================
constexpr int AT_SMEM = 174080;

__global__ void __launch_bounds__(256, 1)
k_attn(const float* __restrict__ qkv, float* __restrict__ ao)
{
    extern __shared__ float sm_[];
    float* Qs   = sm_;               // [128][68]
    float* Ks   = Qs + 128 * 68;
    float* Vs   = Ks + 128 * 68;
    float* Ps   = Vs + 128 * 68;     // [128][132]
    float* rmx  = Ps + 128 * 132;
    float* rsm  = rmx + 256;

    const int tid = threadIdx.x, lane = tid & 31, warp = tid >> 5;
    const int wm = warp >> 1, wn = warp & 1;
    const int g = lane >> 2, t4 = lane & 3;
    const int bh = blockIdx.y, b = bh >> 3, h = bh & 7;
    const int qrow0 = b * 512 + blockIdx.x * 128;
    const int kvbase = b * 512;

    auto loadK = [&](int kc) {
        int kvrow0 = kvbase + kc * 128;
        #pragma unroll
        for (int r = 0; r < 8; r++) {
            int i = tid + r * 256;
            int row = i >> 4, c = (i & 15) << 2;
            cp16(&Ks[row * 68 + c], &qkv[(size_t)(kvrow0 + row) * 1536 + 512 + h * 64 + c]);
        }
    };
    auto loadV = [&](int kc) {
        int kvrow0 = kvbase + kc * 128;
        #pragma unroll
        for (int r = 0; r < 8; r++) {
            int i = tid + r * 256;
            int row = i >> 4, c = (i & 15) << 2;
            cp16(&Vs[row * 68 + c], &qkv[(size_t)(kvrow0 + row) * 1536 + 1024 + h * 64 + c]);
        }
    };

    // prologue: K0 and V0 in flight as separate groups
    loadK(0); CP_COMMIT();
    loadV(0); CP_COMMIT();

    // Q tile, pre-scaled by 1/8 (exact power of 2 -> stays tf32)
    #pragma unroll
    for (int r = 0; r < 8; r++) {
        int i = tid + r * 256;
        int row = i >> 4, c = (i & 15) << 2;
        float4 v = *(const float4*)&qkv[(size_t)(qrow0 + row) * 1536 + h * 64 + c];
        Qs[row * 68 + c]     = v.x * 0.125f;
        Qs[row * 68 + c + 1] = v.y * 0.125f;
        Qs[row * 68 + c + 2] = v.z * 0.125f;
        Qs[row * 68 + c + 3] = v.w * 0.125f;
    }

    float m_i[2][2], l_i[2][2];
    float oa[2][4][4];
    #pragma unroll
    for (int i = 0; i < 2; i++)
        #pragma unroll
        for (int hf = 0; hf < 2; hf++) { m_i[i][hf] = -1e30f; l_i[i][hf] = 0.f; }
    #pragma unroll
    for (int i = 0; i < 2; i++)
        #pragma unroll
        for (int j = 0; j < 4; j++)
            #pragma unroll
            for (int q = 0; q < 4; q++) oa[i][j][q] = 0.f;

    for (int kc = 0; kc < 4; kc++) {
        CP_WAIT1();          // K(kc) arrived (V(kc) may still be in flight)
        __syncthreads();     // all threads see Ks (and Qs/Vs-reuse on later iters)

        // ---- S = Q Kt ----
        float s[2][8][4];
        #pragma unroll
        for (int i = 0; i < 2; i++)
            #pragma unroll
            for (int j = 0; j < 8; j++)
                #pragma unroll
                for (int q = 0; q < 4; q++) s[i][j][q] = 0.f;

        #pragma unroll
        for (int ks = 0; ks < 8; ks++) {
            uint32_t af[2][4], bf[8][2];
            #pragma unroll
            for (int i = 0; i < 2; i++) {
                int row = wm * 32 + i * 16 + g;
                af[i][0] = __float_as_uint(Qs[row * 68 + ks * 8 + t4]);
                af[i][1] = __float_as_uint(Qs[(row + 8) * 68 + ks * 8 + t4]);
                af[i][2] = __float_as_uint(Qs[row * 68 + ks * 8 + t4 + 4]);
                af[i][3] = __float_as_uint(Qs[(row + 8) * 68 + ks * 8 + t4 + 4]);
            }
            #pragma unroll
            for (int j = 0; j < 8; j++) {
                int nc = wn * 64 + j * 8 + g;
                bf[j][0] = __float_as_uint(Ks[nc * 68 + ks * 8 + t4]);
                bf[j][1] = __float_as_uint(Ks[nc * 68 + ks * 8 + t4 + 4]);
            }
            #pragma unroll
            for (int i = 0; i < 2; i++)
                #pragma unroll
                for (int j = 0; j < 8; j++)
                    mma_tf32(s[i][j], af[i][0], af[i][1], af[i][2], af[i][3],
                             bf[j][0], bf[j][1]);
        }

        // ---- row max (warp + cross-warp via smem) ----
        float mn[2][2];
        #pragma unroll
        for (int i = 0; i < 2; i++)
            #pragma unroll
            for (int hf = 0; hf < 2; hf++) {
                float v = -1e30f;
                #pragma unroll
                for (int j = 0; j < 8; j++)
                    v = fmaxf(v, fmaxf(s[i][j][2 * hf], s[i][j][2 * hf + 1]));
                v = fmaxf(v, __shfl_xor_sync(0xFFFFFFFF, v, 1));
                v = fmaxf(v, __shfl_xor_sync(0xFFFFFFFF, v, 2));
                mn[i][hf] = v;
            }
        if (t4 == 0) {
            #pragma unroll
            for (int i = 0; i < 2; i++)
                #pragma unroll
                for (int hf = 0; hf < 2; hf++)
                    rmx[(wm * 32 + i * 16 + g + 8 * hf) * 2 + wn] = mn[i][hf];
        }
        __syncthreads();     // also: all S reads of Ks are done -> Ks reusable

        // prefetch next K, overlapping with softmax + PV
        if (kc < 3) loadK(kc + 1);
        CP_COMMIT();

        float sc[2][2];
        #pragma unroll
        for (int i = 0; i < 2; i++)
            #pragma unroll
            for (int hf = 0; hf < 2; hf++) {
                int row = wm * 32 + i * 16 + g + 8 * hf;
                float cm = fmaxf(rmx[row * 2], rmx[row * 2 + 1]);
                float nm = fmaxf(m_i[i][hf], cm);
                sc[i][hf] = __expf(m_i[i][hf] - nm);
                mn[i][hf] = nm;
            }
        #pragma unroll
        for (int i = 0; i < 2; i++)
            #pragma unroll
            for (int j = 0; j < 4; j++) {
                oa[i][j][0] *= sc[i][0]; oa[i][j][1] *= sc[i][0];
                oa[i][j][2] *= sc[i][1]; oa[i][j][3] *= sc[i][1];
            }
        float smv[2][2] = {{0.f, 0.f}, {0.f, 0.f}};
        #pragma unroll
        for (int i = 0; i < 2; i++) {
            int row = wm * 32 + i * 16 + g;
            #pragma unroll
            for (int j = 0; j < 8; j++) {
                int col = wn * 64 + j * 8 + 2 * t4;
                float p0 = __expf(s[i][j][0] - mn[i][0]);
                float p1 = __expf(s[i][j][1] - mn[i][0]);
                float p2 = __expf(s[i][j][2] - mn[i][1]);
                float p3 = __expf(s[i][j][3] - mn[i][1]);
                smv[i][0] += p0 + p1;
                smv[i][1] += p2 + p3;
                Ps[row * 132 + col]           = tf32r(p0);
                Ps[row * 132 + col + 1]       = tf32r(p1);
                Ps[(row + 8) * 132 + col]     = tf32r(p2);
                Ps[(row + 8) * 132 + col + 1] = tf32r(p3);
            }
        }
        #pragma unroll
        for (int i = 0; i < 2; i++)
            #pragma unroll
            for (int hf = 0; hf < 2; hf++) {
                float v = smv[i][hf];
                v += __shfl_xor_sync(0xFFFFFFFF, v, 1);
                v += __shfl_xor_sync(0xFFFFFFFF, v, 2);
                smv[i][hf] = v;
            }
        if (t4 == 0) {
            #pragma unroll
            for (int i = 0; i < 2; i++)
                #pragma unroll
                for (int hf = 0; hf < 2; hf++)
                    rsm[(wm * 32 + i * 16 + g + 8 * hf) * 2 + wn] = smv[i][hf];
        }
        CP_WAIT1();          // V(kc) arrived (next K may still be in flight)
        __syncthreads();     // P staged + row sums ready + Vs visible everywhere
        #pragma unroll
        for (int i = 0; i < 2; i++)
            #pragma unroll
            for (int hf = 0; hf < 2; hf++) {
                int row = wm * 32 + i * 16 + g + 8 * hf;
                l_i[i][hf] = l_i[i][hf] * sc[i][hf] + rsm[row * 2] + rsm[row * 2 + 1];
                m_i[i][hf] = mn[i][hf];
            }

        // ---- O += P · V ----
        #pragma unroll
        for (int ks = 0; ks < 16; ks++) {
            uint32_t af[2][4], bf[4][2];
            #pragma unroll
            for (int i = 0; i < 2; i++) {
                int row = wm * 32 + i * 16 + g;
                af[i][0] = __float_as_uint(Ps[row * 132 + ks * 8 + t4]);
                af[i][1] = __float_as_uint(Ps[(row + 8) * 132 + ks * 8 + t4]);
                af[i][2] = __float_as_uint(Ps[row * 132 + ks * 8 + t4 + 4]);
                af[i][3] = __float_as_uint(Ps[(row + 8) * 132 + ks * 8 + t4 + 4]);
            }
            #pragma unroll
            for (int j = 0; j < 4; j++) {
                int nc = wn * 32 + j * 8 + g;
                bf[j][0] = __float_as_uint(Vs[(ks * 8 + t4) * 68 + nc]);
                bf[j][1] = __float_as_uint(Vs[(ks * 8 + t4 + 4) * 68 + nc]);
            }
            #pragma unroll
            for (int i = 0; i < 2; i++)
                #pragma unroll
                for (int j = 0; j < 4; j++)
                    mma_tf32(oa[i][j], af[i][0], af[i][1], af[i][2], af[i][3],
                             bf[j][0], bf[j][1]);
        }

        __syncthreads();     // all PV reads of Vs done -> Vs reusable
        if (kc < 3) loadV(kc + 1);
        CP_COMMIT();
    }

    #pragma unroll
    for (int i = 0; i < 2; i++) {
        float r0 = 1.f / l_i[i][0], r1 = 1.f / l_i[i][1];
        int row = qrow0 + wm * 32 + i * 16 + g;
        #pragma unroll
        for (int j = 0; j < 4; j++) {
            int col = h * 64 + wn * 32 + j * 8 + 2 * t4;
            *(float2*)&ao[(size_t)row * 512 + col] =
                make_float2(tf32r(oa[i][j][0] * r0), tf32r(oa[i][j][1] * r0));
            *(float2*)&ao[(size_t)(row + 8) * 512 + col] =
                make_float2(tf32r(oa[i][j][2] * r1), tf32r(oa[i][j][3] * r1));
        }
    }
}

// ================= mma.sync GEMM (fallback path) =================
template<int BM,int BN,int WARPS_M,int WARPS_N,bool TB,bool RELU,bool GN,bool TFO>
__global__ void __launch_bounds__(WARPS_M*WARPS_N*32)
k_mma(int M, int N, int K,
      const float* __restrict__ Ag, int lda, long long sA1, long long sA2,
      const float* __restrict__ Bg, int ldb, long long sB1, long long sB2,
      float* __restrict__ Cg, int ldc, long long sC1, long long sC2,
      int zdiv, const float* __restrict__ bias, float alpha)
{
    constexpr int BK = 16;
    constexpr int NT = WARPS_M * WARPS_N * 32;
    constexpr int WM = BM / WARPS_M, WN = BN / WARPS_N;
    constexpr int MI = WM / 16, NI = WN / 8;
    constexpr int AST = BK + 4;
    constexpr int BROWS = TB ? BN : BK;
    constexpr int BCOLS = TB ? (BK + 4) : (BN + 8);

    __shared__ __align__(16) float As[2][BM][AST];
    __shared__ __align__(16) float Bs[2][BROWS][BCOLS];

    const int bz = blockIdx.z;
    const int z1 = bz / zdiv, z2 = bz - z1 * zdiv;
    const float* A  = Ag + z1 * sA1 + z2 * sA2;
    const float* Bp = Bg + z1 * sB1 + z2 * sB2;
    float* C        = Cg + z1 * sC1 + z2 * sC2;

    const int m0 = blockIdx.y * BM, n0 = blockIdx.x * BN;
    const int tid  = threadIdx.x;
    const int lane = tid & 31, warp = tid >> 5;
    const int wm = warp / WARPS_N, wn = warp - wm * WARPS_N;
    const int g = lane >> 2, t4 = lane & 3;

    float acc[MI][NI][4];
    #pragma unroll
    for (int i = 0; i < MI; i++)
        #pragma unroll
        for (int j = 0; j < NI; j++)
            #pragma unroll
            for (int q = 0; q < 4; q++) acc[i][j][q] = 0.f;

    auto loadTiles = [&](int st, int k0) {
        #pragma unroll
        for (int r = 0; r < (BM * (BK/4)) / NT; r++) {
            int i = tid + r * NT;
            int m = i >> 2;
            int c = (i & 3) << 2;
            cp16(&As[st][m][c], &A[(size_t)(m0 + m) * lda + k0 + c]);
        }
        if (TB) {
            #pragma unroll
            for (int r = 0; r < (BN * (BK/4)) / NT; r++) {
                int i = tid + r * NT;
                int n = i >> 2;
                int c = (i & 3) << 2;
                int gn = n0 + n;
                if (GN) {
                    bool ok = gn < N;
                    cp16p(&Bs[st][n][c], ok ? &Bp[(size_t)gn * ldb + k0 + c] : (const float*)Bp, ok);
                } else {
                    cp16(&Bs[st][n][c], &Bp[(size_t)gn * ldb + k0 + c]);
                }
            }
        } else {
            #pragma unroll
            for (int r = 0; r < (BK * (BN/4)) / NT; r++) {
                int i = tid + r * NT;
                int kk = i / (BN/4);
                int c  = (i - kk * (BN/4)) << 2;
                cp16(&Bs[st][kk][c], &Bp[(size_t)(k0 + kk) * ldb + n0 + c]);
            }
        }
    };

    const int nk = K / BK;
    loadTiles(0, 0);
    CP_COMMIT();

    for (int kt = 0; kt < nk; kt++) {
        int cur = kt & 1;
        if (kt + 1 < nk) loadTiles(cur ^ 1, (kt + 1) * BK);
        CP_COMMIT();
        CP_WAIT1();
        __syncthreads();

        #pragma unroll
        for (int ks = 0; ks < 2; ks++) {
            uint32_t af[MI][4], bf[NI][2];
            #pragma unroll
            for (int i = 0; i < MI; i++) {
                int mr = wm * WM + i * 16 + g;
                af[i][0] = __float_as_uint(As[cur][mr    ][ks*8 + t4    ]);
                af[i][1] = __float_as_uint(As[cur][mr + 8][ks*8 + t4    ]);
                af[i][2] = __float_as_uint(As[cur][mr    ][ks*8 + t4 + 4]);
                af[i][3] = __float_as_uint(As[cur][mr + 8][ks*8 + t4 + 4]);
            }
            #pragma unroll
            for (int j = 0; j < NI; j++) {
                int nc = wn * WN + j * 8 + g;
                if (TB) {
                    bf[j][0] = __float_as_uint(Bs[cur][nc][ks*8 + t4    ]);
                    bf[j][1] = __float_as_uint(Bs[cur][nc][ks*8 + t4 + 4]);
                } else {
                    bf[j][0] = __float_as_uint(Bs[cur][ks*8 + t4    ][nc]);
                    bf[j][1] = __float_as_uint(Bs[cur][ks*8 + t4 + 4][nc]);
                }
            }
            #pragma unroll
            for (int i = 0; i < MI; i++)
                #pragma unroll
                for (int j = 0; j < NI; j++)
                    mma_tf32(acc[i][j], af[i][0], af[i][1], af[i][2], af[i][3],
                             bf[j][0], bf[j][1]);
        }
        __syncthreads();
    }

    #pragma unroll
    for (int i = 0; i < MI; i++) {
        int r0 = m0 + wm * WM + i * 16 + g;
        #pragma unroll
        for (int j = 0; j < NI; j++) {
            int col = n0 + wn * WN + j * 8 + t4 * 2;
            if (GN && col >= N) continue;
            float b0v = 0.f, b1v = 0.f;
            if (bias) { b0v = bias[col]; b1v = bias[col + 1]; }
            float v0 = acc[i][j][0] * alpha + b0v;
            float v1 = acc[i][j][1] * alpha + b1v;
            float v2 = acc[i][j][2] * alpha + b0v;
            float v3 = acc[i][j][3] * alpha + b1v;
            if (RELU) {
                v0 = fmaxf(v0, 0.f); v1 = fmaxf(v1, 0.f);
                v2 = fmaxf(v2, 0.f); v3 = fmaxf(v3, 0.f);
            }
            if (TFO) {
                v0 = tf32r(v0); v1 = tf32r(v1); v2 = tf32r(v2); v3 = tf32r(v3);
            }
            *reinterpret_cast<float2*>(&C[(size_t)r0 * ldc + col])       = make_float2(v0, v1);
            *reinterpret_cast<float2*>(&C[(size_t)(r0 + 8) * ldc + col]) = make_float2(v2, v3);
        }
    }
}

// ---------------- residual add + layernorm ----------------
__global__ void k_add_ln(const float* __restrict__ xin, const float* __restrict__ res,
                         const float* __restrict__ g, const float* __restrict__ b,
                         float* __restrict__ xout, float* __restrict__ xtf)
{
    int row = blockIdx.x, t = threadIdx.x;
    long long base = (long long)row * D;
    float v0 = xin[base + t]       + res[base + t];
    float v1 = xin[base + t + 256] + res[base + t + 256];
    __shared__ float red[256];
    red[t] = v0 + v1; __syncthreads();
    for (int o = 128; o > 0; o >>= 1) { if (t < o) red[t] += red[t+o]; __syncthreads(); }
    float mean = red[0] * (1.f / D); __syncthreads();
    red[t] = v0*v0 + v1*v1; __syncthreads();
    for (int o = 128; o > 0; o >>= 1) { if (t < o) red[t] += red[t+o]; __syncthreads(); }
    float var = red[0] * (1.f / D) - mean*mean;
    float rs = rsqrtf(var + 1e-5f);
    float o0 = (v0 - mean) * rs * g[t]       + b[t];
    float o1 = (v1 - mean) * rs * g[t + 256] + b[t + 256];
    xout[base + t]       = o0;
    xout[base + t + 256] = o1;
    xtf [base + t]       = tf32r(o0);
    xtf [base + t + 256] = tf32r(o1);
}

// ---------------- embedding ----------------
__global__ void k_embed(const int* __restrict__ src, const float* __restrict__ emb,
                        const float* __restrict__ pos, float* __restrict__ x,
                        float* __restrict__ xtf)
{
    int idx = blockIdx.x * blockDim.x + threadIdx.x;
    int t = idx >> 9, d = idx & 511;
    float v = emb[(long long)src[t] * D + d] * SQRTD_F + pos[(t & 511) * D + d];
    x[idx]   = v;
    xtf[idx] = tf32r(v);
}

// ---------------- round static weights ----------------
__global__ void k_round_w(const float* __restrict__ opw, const float* __restrict__ ow, int nOw)
{
    int i = blockIdx.x * blockDim.x + threadIdx.x;
    if (i < L * D * D) d_wr[i] = tf32r(opw[i]);
    if (i < nOw)       d_owr[i] = tf32r(ow[i]);
}

// ---------------- batched prune pipeline ----------------
__device__ __forceinline__ const float* slot_w(int slot, const float* ipw,
                                               const float* w1, const float* w2, int& n)
{
    int t = slot / 6, l = slot - t * 6;
    if (t == 0) { n = 3 * D * D; return ipw + (size_t)l * 3 * D * D; }
    n = F * D;
    return (t == 1) ? w1 + (size_t)l * F * D : w2 + (size_t)l * F * D;
}

__global__ void k_zero_all()
{
    int i = blockIdx.x * blockDim.x + threadIdx.x;
    if (i < NSLOT * 2 * 65536) d_h2g[i] = 0;
    if (i < NSLOT * 4096)      d_h1g[i] = 0;
    if (i < NSLOT * 32)        d_h3g[i] = 0;
}

__global__ void k_etch_all(const float* __restrict__ ipw, const float* __restrict__ w1,
                           const float* __restrict__ w2)
{
    int slot = blockIdx.y;
    int n;
    const float* w = slot_w(slot, ipw, w1, w2, n);
    float inv = 1.f / (float)(n - 1);
    float* aout = d_abs_all + (size_t)slot * SLOT_STRIDE;
    unsigned* h1 = d_h1g + slot * 4096;

    __shared__ unsigned h[4096];
    for (int j = threadIdx.x; j < 4096; j += blockDim.x) h[j] = 0;
    __syncthreads();
    int stride = gridDim.x * blockDim.x;
    for (int i = blockIdx.x * blockDim.x + threadIdx.x; i < n; i += stride) {
        float wv = w[i];
        float b0 = sinf(wv * PI_F);
        b0 = fminf(fmaxf(b0, -1.f), 1.f);
        float bl = b0 + b0 * cosf((float)i * inv + THIRD_F) * 1.5f;
        float e = cosf(bl * PI2_F) + bl * bl * DEVPI_F;
        float a = fabsf(e);
        aout[i] = a;
        atomicAdd(&h[__float_as_uint(a) >> 20], 1u);
    }
    __syncthreads();
    for (int j = threadIdx.x; j < 4096; j += blockDim.x) {
        unsigned c = h[j];
        if (c) atomicAdd(&h1[j], c);
    }
}

__global__ void k_scan1_all(const float* ipw, const float* w1, const float* w2)
{
    int slot = blockIdx.x;
    int n; slot_w(slot, ipw, w1, w2, n);
    unsigned rA = (unsigned)((n - 1) >> 2);
    unsigned rB = rA + 1;
    const unsigned* h1 = d_h1g + slot * 4096;
    unsigned* sel = d_selg + slot * 8;

    __shared__ unsigned part[256];
    __shared__ unsigned pref[256];
    int t = threadIdx.x, base = t * 16;
    unsigned c[16]; unsigned s = 0;
    for (int j = 0; j < 16; j++) { c[j] = h1[base + j]; s += c[j]; }
    part[t] = s; __syncthreads();
    if (t == 0) { unsigned a = 0; for (int i = 0; i < 256; i++) { pref[i] = a; a += part[i]; } }
    __syncthreads();
    unsigned p = pref[t];
    for (int j = 0; j < 16; j++) {
        if (rA >= p && rA < p + c[j]) { sel[0] = base + j; sel[1] = rA - p; }
        if (rB >= p && rB < p + c[j]) { sel[2] = base + j; sel[3] = rB - p; }
        p += c[j];
    }
}

__global__ void k_hist2_all(const float* ipw, const float* w1, const float* w2)
{
    int slot = blockIdx.y;
    int n; slot_w(slot, ipw, w1, w2, n);
    const float* ab = d_abs_all + (size_t)slot * SLOT_STRIDE;
    const unsigned* sel = d_selg + slot * 8;
    unsigned* h2 = d_h2g + (size_t)slot * 131072;
    unsigned sA = sel[0], sB = sel[2];
    int stride = gridDim.x * blockDim.x;
    for (int i = blockIdx.x * blockDim.x + threadIdx.x; i < n; i += stride) {
        unsigned u = __float_as_uint(ab[i]);
        unsigned hi = u >> 20, mid = (u >> 4) & 0xFFFFu;
        if (hi == sA) atomicAdd(&h2[mid], 1u);
        if (hi == sB) atomicAdd(&h2[65536 + mid], 1u);
    }
}

__global__ void k_scan2_all()
{
    int slot = blockIdx.x;
    unsigned* sel = d_selg + slot * 8;
    __shared__ unsigned part[256];
    __shared__ unsigned pref[256];
    int t = threadIdx.x;
    for (int sidx = 0; sidx < 2; sidx++) {
        unsigned rank = sel[1 + sidx * 2];
        const unsigned* hb = d_h2g + (size_t)slot * 131072 + sidx * 65536;
        int base = t * 256;
        unsigned s = 0;
        for (int j = 0; j < 256; j++) s += hb[base + j];
        part[t] = s; __syncthreads();
        if (t == 0) { unsigned a = 0; for (int i = 0; i < 256; i++) { pref[i] = a; a += part[i]; } }
        __syncthreads();
        unsigned p = pref[t];
        for (int j = 0; j < 256; j++) {
            unsigned c = hb[base + j];
            if (rank >= p && rank < p + c) { sel[4 + sidx*2] = base + j; sel[5 + sidx*2] = rank - p; }
            p += c;
        }
        __syncthreads();
    }
}

__global__ void k_hist3_all(const float* ipw, const float* w1, const float* w2)
{
    int slot = blockIdx.y;
    int n; slot_w(slot, ipw, w1, w2, n);
    const float* ab = d_abs_all + (size_t)slot * SLOT_STRIDE;
    const unsigned* sel = d_selg + slot * 8;
    unsigned* h3 = d_h3g + slot * 32;
    unsigned kA = (sel[0] << 16) | sel[4];
    unsigned kB = (sel[2] << 16) | sel[6];
    int stride = gridDim.x * blockDim.x;
    for (int i = blockIdx.x * blockDim.x + threadIdx.x; i < n; i += stride) {
        unsigned u = __float_as_uint(ab[i]);
        unsigned top = u >> 4;
        if (top == kA) atomicAdd(&h3[u & 15u], 1u);
        if (top == kB) atomicAdd(&h3[16 + (u & 15u)], 1u);
    }
}

__global__ void k_thr_all(const float* ipw, const float* w1, const float* w2)
{
    int slot = blockIdx.x * blockDim.x + threadIdx.x;
    if (slot >= NSLOT) return;
    int n; slot_w(slot, ipw, w1, w2, n);
    float frac = 0.25f * (float)((n - 1) & 3);
    const unsigned* sel = d_selg + slot * 8;
    const unsigned* h3 = d_h3g + slot * 32;
    unsigned remA = sel[5]; unsigned lowA = 0;
    for (int j = 0; j < 16; j++) { unsigned c = h3[j]; if (remA < c) { lowA = j; break; } remA -= c; }
    unsigned remB = sel[7]; unsigned lowB = 0;
    for (int j = 0; j < 16; j++) { unsigned c = h3[16 + j]; if (remB < c) { lowB = j; break; } remB -= c; }
    float vA = __uint_as_float((sel[0] << 20) | (sel[4] << 4) | lowA);
    float vB = __uint_as_float((sel[2] << 20) | (sel[6] << 4) | lowB);
    d_thrg[slot] = vA + frac * (vB - vA);
}

__global__ void k_mask_all(const float* __restrict__ ipw, const float* __restrict__ w1,
                           const float* __restrict__ w2)
{
    int slot = blockIdx.y;
    int n;
    const float* w = slot_w(slot, ipw, w1, w2, n);
    int i = blockIdx.x * blockDim.x + threadIdx.x;
    if (i >= n) return;
    float thr = d_thrg[slot];
    d_wp[(size_t)slot * SLOT_STRIDE + i] =
        (d_abs_all[(size_t)slot * SLOT_STRIDE + i] > thr) ? tf32r(w[i]) : 0.f;
}

// ---------------- entry point ----------------
extern "C" void kernel_launch(void* const* d_in, const int* in_sizes, int n_in,
                              void* d_out, int out_size)
{
    const int*   src = (const int*)  d_in[0];
    const float* emb = (const float*)d_in[1];
    const float* pos = (const float*)d_in[2];
    const float* ipw = (const float*)d_in[3];
    const float* ipb = (const float*)d_in[4];
    const float* opw = (const float*)d_in[5];
    const float* opb = (const float*)d_in[6];
    const float* l1g = (const float*)d_in[7];
    const float* l1b = (const float*)d_in[8];
    const float* l2g = (const float*)d_in[9];
    const float* l2b = (const float*)d_in[10];
    const float* w1  = (const float*)d_in[11];
    const float* b1  = (const float*)d_in[12];
    const float* w2  = (const float*)d_in[13];
    const float* b2  = (const float*)d_in[14];
    const float* ow  = (const float*)d_in[15];
    const float* ob  = (const float*)d_in[16];
    const int V = in_sizes[16];
    float* out = (float*)d_out;

    float *px, *pxtf, *pqkv, *pao, *pff, *ptmp, *pwp, *pwr, *powr;
    cudaGetSymbolAddress((void**)&px,   d_x);
    cudaGetSymbolAddress((void**)&pxtf, d_xtf);
    cudaGetSymbolAddress((void**)&pqkv, d_qkv);
    cudaGetSymbolAddress((void**)&pao,  d_ao);
    cudaGetSymbolAddress((void**)&pff,  d_ff);
    cudaGetSymbolAddress((void**)&ptmp, d_tmp);
    cudaGetSymbolAddress((void**)&pwp,  d_wp);
    cudaGetSymbolAddress((void**)&pwr,  d_wr);
    cudaGetSymbolAddress((void**)&powr, d_owr);

    cudaFuncAttributes fa{};
    cudaFuncGetAttributes(&fa, k_tc<false,false,true>);
    const bool use_tc = fa.numRegs > 40;

    if (use_tc) {
        cudaFuncSetAttribute(k_tc<false,false,true >, cudaFuncAttributeMaxDynamicSharedMemorySize, TC_SMEM);
        cudaFuncSetAttribute(k_tc<false,false,false>, cudaFuncAttributeMaxDynamicSharedMemorySize, TC_SMEM);
        cudaFuncSetAttribute(k_tc<true ,false,true >, cudaFuncAttributeMaxDynamicSharedMemorySize, TC_SMEM);
        cudaFuncSetAttribute(k_tc<false,true ,false>, cudaFuncAttributeMaxDynamicSharedMemorySize, TC_SMEM);
    }
    cudaFuncSetAttribute(k_attn, cudaFuncAttributeMaxDynamicSharedMemorySize, AT_SMEM);

    k_embed<<<MT * D / 256, 256>>>(src, emb, pos, px, pxtf);
    k_round_w<<<(V * D + 255) / 256, 256>>>(opw, ow, V * D);

    k_zero_all<<<(NSLOT * 2 * 65536 + 255) / 256, 256>>>();
    k_etch_all <<<dim3(128, NSLOT), 256>>>(ipw, w1, w2);
    k_scan1_all<<<NSLOT, 256>>>(ipw, w1, w2);
    k_hist2_all<<<dim3(128, NSLOT), 256>>>(ipw, w1, w2);
    k_scan2_all<<<NSLOT, 256>>>();
    k_hist3_all<<<dim3(128, NSLOT), 256>>>(ipw, w1, w2);
    k_thr_all  <<<1, 32>>>(ipw, w1, w2);
    k_mask_all <<<dim3(4096, NSLOT), 256>>>(ipw, w1, w2);

    for (int l = 0; l < L; l++) {
        const float* wi_l = pwp + (size_t)(0 * 6 + l) * SLOT_STRIDE;
        const float* w1_l = pwp + (size_t)(1 * 6 + l) * SLOT_STRIDE;
        const float* w2_l = pwp + (size_t)(2 * 6 + l) * SLOT_STRIDE;

        // qkv = x @ wi^T + b (output tf32-rounded: feeds attention)
        if (use_tc)
            k_tc<false,false,true><<<dim3((3*D)/TC_BN, MT/TC_BM), 256, TC_SMEM>>>(
                3*D, D, pxtf, D, wi_l, D, pqkv, 3*D, ipb + (size_t)l * 3 * D);
        else
            k_mma<128,128,2,2,true,false,false,true><<<dim3((3*D)/128, MT/128, 1), 128>>>(
                MT, 3*D, D, pxtf, D, 0, 0, wi_l, D, 0, 0, pqkv, 3*D, 0, 0, 1,
                ipb + (size_t)l * 3 * D, 1.f);

        // fused flash attention
        k_attn<<<dim3(4, BH), 256, AT_SMEM>>>(pqkv, pao);

        // out projection
        if (use_tc)
            k_tc<false,false,false><<<dim3(D/TC_BN, MT/TC_BM), 256, TC_SMEM>>>(
                D, D, pao, D, pwr + (size_t)l*D*D, D, ptmp, D, opb + (size_t)l*D);
        else
            k_mma<128,128,2,2,true,false,false,false><<<dim3(D/128, MT/128, 1), 128>>>(
                MT, D, D, pao, D, 0, 0, pwr + (size_t)l*D*D, D, 0, 0,
                ptmp, D, 0, 0, 1, opb + (size_t)l*D, 1.f);
        k_add_ln<<<MT, 256>>>(px, ptmp, l1g + (size_t)l*D, l1b + (size_t)l*D, px, pxtf);

        // feed-forward
        if (use_tc) {
            k_tc<true,false,true><<<dim3(F/TC_BN, MT/TC_BM), 256, TC_SMEM>>>(
                F, D, pxtf, D, w1_l, D, pff, F, b1 + (size_t)l*F);
            k_tc<false,false,false><<<dim3(D/TC_BN, MT/TC_BM), 256, TC_SMEM>>>(
                D, F, pff, F, w2_l, F, ptmp, D, b2 + (size_t)l*D);
        } else {
            k_mma<128,128,2,2,true,true,false,true><<<dim3(F/128, MT/128, 1), 128>>>(
                MT, F, D, pxtf, D, 0, 0, w1_l, D, 0, 0, pff, F, 0, 0, 1,
                b1 + (size_t)l*F, 1.f);
            k_mma<128,128,2,2,true,false,false,false><<<dim3(D/128, MT/128, 1), 128>>>(
                MT, D, F, pff, F, 0, 0, w2_l, F, 0, 0, ptmp, D, 0, 0, 1,
                b2 + (size_t)l*D, 1.f);
        }
        k_add_ln<<<MT, 256>>>(px, ptmp, l2g + (size_t)l*D, l2b + (size_t)l*D, px, pxtf);
    }

    // logits
    if (use_tc)
        k_tc<false,true,false><<<dim3((V + TC_BN - 1)/TC_BN, MT/TC_BM), 256, TC_SMEM>>>(
            V, D, pxtf, D, powr, D, out, V, ob);
    else
        k_mma<128,128,2,2,true,false,true,false><<<dim3((V + 127) / 128, MT / 128, 1), 128>>>(
            MT, V, D, pxtf, D, 0, 0, powr, D, 0, 0, out, V, 0, 0, 1, ob, 1.f);
}

// round 10
// speedup vs baseline: 2.0457x; 1.0124x over previous
#include <cuda_runtime.h>
#include <cstdint>
#include <math.h>

// ---------------- constants ----------------
#define PI_F      3.14159265358979323846f
#define PI2_F     9.86960440108935861883f
#define THIRD_F   2.09439510239319549231f
#define DEVPI_F   0.003183098861837907f
#define SQRTD_F   22.62741699796952f

constexpr int S  = 512;
constexpr int D  = 512;
constexpr int H  = 8;
constexpr int DH = 64;
constexpr int L  = 6;
constexpr int F  = 2048;
constexpr int BB = 16;
constexpr int MT = BB * S;   // 8192 tokens
constexpr int BH = BB * H;   // 128
constexpr int NSLOT = 18;
constexpr size_t SLOT_STRIDE = 1048576;
constexpr int VMAX = 10240;

// Feature gate: tcgen05 only exists on arch-specific (sm_103a) / family (sm_103f) targets.
#if !defined(__CUDA_ARCH__) || defined(__CUDA_ARCH_FEAT_SM103_ALL) || defined(__CUDA_ARCH_SPECIFIC__) || defined(__CUDA_ARCH_FAMILY_SPECIFIC__)
#define TC_AVAIL 1
#else
#define TC_AVAIL 0
#endif

// ---------------- device scratch ----------------
__device__ __align__(128) float d_x   [MT * D];
__device__ __align__(128) float d_xtf [MT * D];
__device__ __align__(128) float d_qkv [MT * 3 * D];
__device__ __align__(128) float d_ao  [MT * D];
__device__ __align__(128) float d_ff  [MT * F];
__device__ __align__(128) float d_tmp [MT * D];
__device__ __align__(128) float d_wp  [NSLOT * SLOT_STRIDE];
__device__ __align__(128) float d_wr  [L * D * D];
__device__ __align__(128) float d_owr [VMAX * D];
__device__ __align__(128) float d_abs_all[NSLOT * SLOT_STRIDE];
__device__ unsigned d_h1g[NSLOT * 4096];
__device__ unsigned d_h2g[NSLOT * 2 * 65536];
__device__ unsigned d_h3g[NSLOT * 32];
__device__ unsigned d_selg[NSLOT * 8];
__device__ float d_thrg[NSLOT];

// ---------------- helpers ----------------
__device__ __forceinline__ float tf32r(float f) {
    uint32_t u;
    asm("cvt.rna.tf32.f32 %0, %1;" : "=r"(u) : "f"(f));
    return __uint_as_float(u);
}

__device__ __forceinline__ void mma_tf32(float c[4],
    uint32_t a0, uint32_t a1, uint32_t a2, uint32_t a3,
    uint32_t b0, uint32_t b1)
{
    asm volatile(
        "mma.sync.aligned.m16n8k8.row.col.f32.tf32.tf32.f32 "
        "{%0,%1,%2,%3}, {%4,%5,%6,%7}, {%8,%9}, {%0,%1,%2,%3};"
        : "+f"(c[0]), "+f"(c[1]), "+f"(c[2]), "+f"(c[3])
        : "r"(a0), "r"(a1), "r"(a2), "r"(a3), "r"(b0), "r"(b1));
}

__device__ __forceinline__ void cp16(void* d, const void* s) {
    uint32_t a = (uint32_t)__cvta_generic_to_shared(d);
    asm volatile("cp.async.cg.shared.global [%0], [%1], 16;" :: "r"(a), "l"(s));
}
__device__ __forceinline__ void cp16p(void* d, const void* s, bool p) {
    uint32_t a = (uint32_t)__cvta_generic_to_shared(d);
    int sz = p ? 16 : 0;
    asm volatile("cp.async.cg.shared.global [%0], [%1], 16, %2;" :: "r"(a), "l"(s), "r"(sz));
}
#define CP_COMMIT() asm volatile("cp.async.commit_group;")
#define CP_WAIT0()  asm volatile("cp.async.wait_group 0;")
#define CP_WAIT1()  asm volatile("cp.async.wait_group 1;")
#define CP_WAIT2()  asm volatile("cp.async.wait_group 2;")

// ================= tcgen05 tf32 GEMM (guarded) =================
// Single-M: 128x256 tile, NS=4. Dual-M (M2): 256x256 tile via two TMEM halves, NS=3.
constexpr int TC_BN = 256;
constexpr int TC_BK = 32;
constexpr int TC_SMEM = 197632;   // both variants fit

#if TC_AVAIL
__device__ __forceinline__ uint32_t elect1() {
    uint32_t pred;
    asm volatile("{\n\t.reg .pred p;\n\telect.sync _|p, 0xFFFFFFFF;\n\t"
                 "selp.b32 %0, 1, 0, p;\n\t}" : "=r"(pred));
    return pred;
}
#define MBAR_INIT(addr, cnt) \
    asm volatile("mbarrier.init.shared.b64 [%0], %1;" :: "r"(addr), "r"(cnt) : "memory")
#define MBAR_WAIT(addr, par) do { \
    asm volatile("{\n\t.reg .pred P1;\n\tWL%=:\n\t" \
        "mbarrier.try_wait.parity.acquire.cta.shared::cta.b64 P1, [%0], %1, 0x989680;\n\t" \
        "@P1 bra.uni WD%=;\n\tbra.uni WL%=;\n\tWD%=:\n\t}" \
        :: "r"(addr), "r"(par) : "memory"); \
} while (0)
#define TC_ALLOC(sm, n)   asm volatile("tcgen05.alloc.cta_group::1.sync.aligned.shared::cta.b32 [%0], %1;" :: "r"(sm), "r"(n) : "memory")
#define TC_DEALLOC(t, n)  asm volatile("tcgen05.dealloc.cta_group::1.sync.aligned.b32 %0, %1;" :: "r"(t), "r"(n))
#define TC_COMMIT(mb)     asm volatile("tcgen05.commit.cta_group::1.mbarrier::arrive::one.shared::cluster.b64 [%0];" :: "r"(mb) : "memory")
#define TC_FENCE_AFTER()  asm volatile("tcgen05.fence::after_thread_sync;" ::: "memory")
#define TC_FENCE_BEFORE() asm volatile("tcgen05.fence::before_thread_sync;" ::: "memory")
#define TC_WAIT_LD()      asm volatile("tcgen05.wait::ld.sync.aligned;" ::: "memory")
#define FENCE_PROXY()     asm volatile("fence.proxy.async.shared::cta;" ::: "memory")

#define TC_LD_X32(r, addr) \
    asm volatile("tcgen05.ld.sync.aligned.32x32b.x32.b32 " \
        "{%0, %1, %2, %3, %4, %5, %6, %7, %8, %9, %10, %11, %12, %13, %14, %15, " \
        " %16, %17, %18, %19, %20, %21, %22, %23, %24, %25, %26, %27, %28, %29, %30, %31}, [%32];" \
        : "=r"((r)[0]),  "=r"((r)[1]),  "=r"((r)[2]),  "=r"((r)[3]), \
          "=r"((r)[4]),  "=r"((r)[5]),  "=r"((r)[6]),  "=r"((r)[7]), \
          "=r"((r)[8]),  "=r"((r)[9]),  "=r"((r)[10]), "=r"((r)[11]), \
          "=r"((r)[12]), "=r"((r)[13]), "=r"((r)[14]), "=r"((r)[15]), \
          "=r"((r)[16]), "=r"((r)[17]), "=r"((r)[18]), "=r"((r)[19]), \
          "=r"((r)[20]), "=r"((r)[21]), "=r"((r)[22]), "=r"((r)[23]), \
          "=r"((r)[24]), "=r"((r)[25]), "=r"((r)[26]), "=r"((r)[27]), \
          "=r"((r)[28]), "=r"((r)[29]), "=r"((r)[30]), "=r"((r)[31]) \
        : "r"(addr))

static constexpr uint64_t SMEM_DESC_BASE =
    (uint64_t(2) << 61) | (uint64_t(1) << 46) | (uint64_t(64) << 32) | (uint64_t(1) << 16);
#define MK_DESC(a) (SMEM_DESC_BASE | ((uint64_t)((a) >> 4) & 0x3FFF))

__device__ __forceinline__ void mma_tc(uint32_t d, uint64_t ad, uint64_t bd,
                                       uint32_t idesc, bool en)
{
    uint32_t e = en ? 1 : 0;
    asm volatile(
        "{\n\t.reg .pred p;\n\tsetp.ne.u32 p, %4, 0;\n\t"
        "tcgen05.mma.cta_group::1.kind::tf32 [%0], %1, %2, %3, {%5,%5,%5,%5}, p;\n\t}"
        :: "r"(d), "l"(ad), "l"(bd), "r"(idesc), "r"(e), "r"(0u) : "memory");
}
#endif  // TC_AVAIL

constexpr uint32_t TC_IDESC =
    (1u << 4) | (2u << 7) | (2u << 10) | ((TC_BN / 8) << 17) | ((128 / 16) << 24);

// C[m,n] = sum_k A[m,k]*B[n,k] + bias[n]; operands pre-rounded to tf32 values.
// M2=false: grid (N/256, M/128).  M2=true: grid (N/256, M/256), B loaded once per 256 M-rows.
template<bool RELU, bool GN, bool TFO, bool M2>
__global__ void __launch_bounds__(256, 1)
k_tc(int N, int K,
     const float* __restrict__ A, int lda,
     const float* __restrict__ B, int ldb,
     float* __restrict__ C, int ldc,
     const float* __restrict__ bias)
{
#if TC_AVAIL
    constexpr int NS    = M2 ? 3 : 4;
    constexpr int AROWS = M2 ? 256 : 128;
    constexpr int ASZ   = AROWS * 128;     // bytes per stage (128B per row)
    constexpr int BSZ   = TC_BN * 128;
    constexpr int TCOLS = M2 ? 512 : 256;

    extern __shared__ char smem[];
    uint32_t sbase = (uint32_t)__cvta_generic_to_shared(smem);
    const int tid = threadIdx.x, lane = tid & 31, warp = tid >> 5;
    const int m0 = blockIdx.y * AROWS, n0 = blockIdx.x * TC_BN;

    if (warp == 0) TC_ALLOC(sbase, TCOLS);
    if (tid == 0) {
        #pragma unroll
        for (int s = 0; s < NS; s++) MBAR_INIT(sbase + 16 + 8 * s, 1);
    }
    __syncthreads();
    uint32_t tmem;
    asm volatile("ld.shared.b32 %0, [%1];" : "=r"(tmem) : "r"(sbase));

    const uint32_t aoff = 1024, boff = 1024 + NS * ASZ;

    auto loadStage = [&](int st, int k0) {
        char* pa = smem + aoff + st * ASZ;
        char* pb = smem + boff + st * BSZ;
        #pragma unroll
        for (int r = 0; r < AROWS / 32; r++) {   // AROWS*8 chunks / 256 threads
            int i = tid + r * 256;
            int m = i >> 3, c = i & 7;
            int cs = c ^ (m & 7);     // SW128
            cp16(pa + m * 128 + cs * 16, &A[(size_t)(m0 + m) * lda + k0 + c * 4]);
        }
        #pragma unroll
        for (int r = 0; r < 8; r++) {
            int i = tid + r * 256;
            int n = i >> 3, c = i & 7;
            int cs = c ^ (n & 7);
            int gn = n0 + n;
            if (GN) {
                bool ok = gn < N;
                cp16p(pb + n * 128 + cs * 16,
                      ok ? &B[(size_t)gn * ldb + k0 + c * 4] : (const float*)B, ok);
            } else {
                cp16(pb + n * 128 + cs * 16, &B[(size_t)gn * ldb + k0 + c * 4]);
            }
        }
    };

    const int nk = K / TC_BK;

    #pragma unroll
    for (int s = 0; s < NS - 1; s++) { loadStage(s, s * TC_BK); CP_COMMIT(); }

    for (int kt = 0; kt < nk; kt++) {
        int cur = kt % NS;
        if (M2) { CP_WAIT1(); } else { CP_WAIT2(); }   // stage kt landed
        __syncthreads();
        FENCE_PROXY();
        if (warp == 0 && elect1()) {
            uint64_t ad = MK_DESC(sbase + aoff + cur * ASZ);
            uint64_t bd = MK_DESC(sbase + boff + cur * BSZ);
            #pragma unroll
            for (int j = 0; j < 4; j++) {
                bool en = (kt > 0) || (j > 0);
                mma_tc(tmem, ad + j * 2, bd + j * 2, TC_IDESC, en);
                if (M2) {
                    uint64_t ad2 = MK_DESC(sbase + aoff + cur * ASZ + 128 * 128);
                    mma_tc(tmem + 256, ad2 + j * 2, bd + j * 2, TC_IDESC, en);
                }
            }
            TC_COMMIT(sbase + 16 + 8 * cur);
        }
        if (kt >= 1) MBAR_WAIT(sbase + 16 + 8 * ((kt - 1) % NS), ((kt - 1) / NS) & 1);
        int kn = kt + NS - 1;
        if (kn < nk) loadStage(kn % NS, kn * TC_BK);
        CP_COMMIT();
    }
    MBAR_WAIT(sbase + 16 + 8 * ((nk - 1) % NS), ((nk - 1) / NS) & 1);

    __syncthreads();
    TC_FENCE_AFTER();

    // epilogue
    float* myep = (float*)(smem + 1024) + warp * (32 * 33);
    if (M2) {
        // warps 0-3 -> m-tile0 (tmem+0), warps 4-7 -> m-tile1 (tmem+256); 256 cols each
        int half = warp >> 2;
        uint32_t tbase = tmem + half * 256;
        int rbase = m0 + half * 128 + (warp & 3) * 32;
        #pragma unroll
        for (int ch = 0; ch < 8; ch++) {
            int c0 = ch * 32;
            uint32_t regs[32];
            TC_LD_X32(regs, tbase + c0);
            TC_WAIT_LD();
            #pragma unroll
            for (int c = 0; c < 32; c++) {
                float v = __uint_as_float(regs[c]);
                if (!GN || (n0 + c0 + c) < N) {
                    v += bias[n0 + c0 + c];
                    if (RELU) v = fmaxf(v, 0.f);
                    if (TFO)  v = tf32r(v);
                }
                myep[lane * 33 + c] = v;
            }
            __syncwarp();
            int col = n0 + c0 + lane;
            #pragma unroll
            for (int i = 0; i < 32; i++) {
                if (!GN || col < N)
                    C[(size_t)(rbase + i) * ldc + col] = myep[i * 33 + lane];
            }
            __syncwarp();
        }
    } else {
        int rbase = m0 + (warp & 3) * 32;
        int cbase = (warp >> 2) * 128;
        #pragma unroll
        for (int ch = 0; ch < 4; ch++) {
            int c0 = cbase + ch * 32;
            uint32_t regs[32];
            TC_LD_X32(regs, tmem + c0);
            TC_WAIT_LD();
            #pragma unroll
            for (int c = 0; c < 32; c++) {
                float v = __uint_as_float(regs[c]);
                if (!GN || (n0 + c0 + c) < N) {
                    v += bias[n0 + c0 + c];
                    if (RELU) v = fmaxf(v, 0.f);
                    if (TFO)  v = tf32r(v);
                }
                myep[lane * 33 + c] = v;
            }
            __syncwarp();
            int col = n0 + c0 + lane;
            #pragma unroll
            for (int i = 0; i < 32; i++) {
                if (!GN || col < N)
                    C[(size_t)(rbase + i) * ldc + col] = myep[i * 33 + lane];
            }
            __syncwarp();
        }
    }

    __syncthreads();
    if (warp == 0) { TC_FENCE_BEFORE(); TC_DEALLOC(tmem, TCOLS); }
#endif  // TC_AVAIL (else: empty stub — host detects via numRegs and falls back)
}

// ================= fused flash attention (mma.sync tf32, pipelined KV) =================
constexpr int AT_SMEM = 174080;

__global__ void __launch_bounds__(256, 1)
k_attn(const float* __restrict__ qkv, float* __restrict__ ao)
{
    extern __shared__ float sm_[];
    float* Qs   = sm_;               // [128][68]
    float* Ks   = Qs + 128 * 68;
    float* Vs   = Ks + 128 * 68;
    float* Ps   = Vs + 128 * 68;     // [128][132]
    float* rmx  = Ps + 128 * 132;
    float* rsm  = rmx + 256;

    const int tid = threadIdx.x, lane = tid & 31, warp = tid >> 5;
    const int wm = warp >> 1, wn = warp & 1;
    const int g = lane >> 2, t4 = lane & 3;
    const int bh = blockIdx.y, b = bh >> 3, h = bh & 7;
    const int qrow0 = b * 512 + blockIdx.x * 128;
    const int kvbase = b * 512;

    auto loadK = [&](int kc) {
        int kvrow0 = kvbase + kc * 128;
        #pragma unroll
        for (int r = 0; r < 8; r++) {
            int i = tid + r * 256;
            int row = i >> 4, c = (i & 15) << 2;
            cp16(&Ks[row * 68 + c], &qkv[(size_t)(kvrow0 + row) * 1536 + 512 + h * 64 + c]);
        }
    };
    auto loadV = [&](int kc) {
        int kvrow0 = kvbase + kc * 128;
        #pragma unroll
        for (int r = 0; r < 8; r++) {
            int i = tid + r * 256;
            int row = i >> 4, c = (i & 15) << 2;
            cp16(&Vs[row * 68 + c], &qkv[(size_t)(kvrow0 + row) * 1536 + 1024 + h * 64 + c]);
        }
    };

    loadK(0); CP_COMMIT();
    loadV(0); CP_COMMIT();

    #pragma unroll
    for (int r = 0; r < 8; r++) {
        int i = tid + r * 256;
        int row = i >> 4, c = (i & 15) << 2;
        float4 v = *(const float4*)&qkv[(size_t)(qrow0 + row) * 1536 + h * 64 + c];
        Qs[row * 68 + c]     = v.x * 0.125f;
        Qs[row * 68 + c + 1] = v.y * 0.125f;
        Qs[row * 68 + c + 2] = v.z * 0.125f;
        Qs[row * 68 + c + 3] = v.w * 0.125f;
    }

    float m_i[2][2], l_i[2][2];
    float oa[2][4][4];
    #pragma unroll
    for (int i = 0; i < 2; i++)
        #pragma unroll
        for (int hf = 0; hf < 2; hf++) { m_i[i][hf] = -1e30f; l_i[i][hf] = 0.f; }
    #pragma unroll
    for (int i = 0; i < 2; i++)
        #pragma unroll
        for (int j = 0; j < 4; j++)
            #pragma unroll
            for (int q = 0; q < 4; q++) oa[i][j][q] = 0.f;

    for (int kc = 0; kc < 4; kc++) {
        CP_WAIT1();          // K(kc) arrived
        __syncthreads();

        float s[2][8][4];
        #pragma unroll
        for (int i = 0; i < 2; i++)
            #pragma unroll
            for (int j = 0; j < 8; j++)
                #pragma unroll
                for (int q = 0; q < 4; q++) s[i][j][q] = 0.f;

        #pragma unroll
        for (int ks = 0; ks < 8; ks++) {
            uint32_t af[2][4], bf[8][2];
            #pragma unroll
            for (int i = 0; i < 2; i++) {
                int row = wm * 32 + i * 16 + g;
                af[i][0] = __float_as_uint(Qs[row * 68 + ks * 8 + t4]);
                af[i][1] = __float_as_uint(Qs[(row + 8) * 68 + ks * 8 + t4]);
                af[i][2] = __float_as_uint(Qs[row * 68 + ks * 8 + t4 + 4]);
                af[i][3] = __float_as_uint(Qs[(row + 8) * 68 + ks * 8 + t4 + 4]);
            }
            #pragma unroll
            for (int j = 0; j < 8; j++) {
                int nc = wn * 64 + j * 8 + g;
                bf[j][0] = __float_as_uint(Ks[nc * 68 + ks * 8 + t4]);
                bf[j][1] = __float_as_uint(Ks[nc * 68 + ks * 8 + t4 + 4]);
            }
            #pragma unroll
            for (int i = 0; i < 2; i++)
                #pragma unroll
                for (int j = 0; j < 8; j++)
                    mma_tf32(s[i][j], af[i][0], af[i][1], af[i][2], af[i][3],
                             bf[j][0], bf[j][1]);
        }

        float mn[2][2];
        #pragma unroll
        for (int i = 0; i < 2; i++)
            #pragma unroll
            for (int hf = 0; hf < 2; hf++) {
                float v = -1e30f;
                #pragma unroll
                for (int j = 0; j < 8; j++)
                    v = fmaxf(v, fmaxf(s[i][j][2 * hf], s[i][j][2 * hf + 1]));
                v = fmaxf(v, __shfl_xor_sync(0xFFFFFFFF, v, 1));
                v = fmaxf(v, __shfl_xor_sync(0xFFFFFFFF, v, 2));
                mn[i][hf] = v;
            }
        if (t4 == 0) {
            #pragma unroll
            for (int i = 0; i < 2; i++)
                #pragma unroll
                for (int hf = 0; hf < 2; hf++)
                    rmx[(wm * 32 + i * 16 + g + 8 * hf) * 2 + wn] = mn[i][hf];
        }
        __syncthreads();     // all S reads of Ks done -> Ks reusable

        if (kc < 3) loadK(kc + 1);
        CP_COMMIT();

        float sc[2][2];
        #pragma unroll
        for (int i = 0; i < 2; i++)
            #pragma unroll
            for (int hf = 0; hf < 2; hf++) {
                int row = wm * 32 + i * 16 + g + 8 * hf;
                float cm = fmaxf(rmx[row * 2], rmx[row * 2 + 1]);
                float nm = fmaxf(m_i[i][hf], cm);
                sc[i][hf] = __expf(m_i[i][hf] - nm);
                mn[i][hf] = nm;
            }
        #pragma unroll
        for (int i = 0; i < 2; i++)
            #pragma unroll
            for (int j = 0; j < 4; j++) {
                oa[i][j][0] *= sc[i][0]; oa[i][j][1] *= sc[i][0];
                oa[i][j][2] *= sc[i][1]; oa[i][j][3] *= sc[i][1];
            }
        float smv[2][2] = {{0.f, 0.f}, {0.f, 0.f}};
        #pragma unroll
        for (int i = 0; i < 2; i++) {
            int row = wm * 32 + i * 16 + g;
            #pragma unroll
            for (int j = 0; j < 8; j++) {
                int col = wn * 64 + j * 8 + 2 * t4;
                float p0 = __expf(s[i][j][0] - mn[i][0]);
                float p1 = __expf(s[i][j][1] - mn[i][0]);
                float p2 = __expf(s[i][j][2] - mn[i][1]);
                float p3 = __expf(s[i][j][3] - mn[i][1]);
                smv[i][0] += p0 + p1;
                smv[i][1] += p2 + p3;
                Ps[row * 132 + col]           = tf32r(p0);
                Ps[row * 132 + col + 1]       = tf32r(p1);
                Ps[(row + 8) * 132 + col]     = tf32r(p2);
                Ps[(row + 8) * 132 + col + 1] = tf32r(p3);
            }
        }
        #pragma unroll
        for (int i = 0; i < 2; i++)
            #pragma unroll
            for (int hf = 0; hf < 2; hf++) {
                float v = smv[i][hf];
                v += __shfl_xor_sync(0xFFFFFFFF, v, 1);
                v += __shfl_xor_sync(0xFFFFFFFF, v, 2);
                smv[i][hf] = v;
            }
        if (t4 == 0) {
            #pragma unroll
            for (int i = 0; i < 2; i++)
                #pragma unroll
                for (int hf = 0; hf < 2; hf++)
                    rsm[(wm * 32 + i * 16 + g + 8 * hf) * 2 + wn] = smv[i][hf];
        }
        CP_WAIT1();          // V(kc) arrived
        __syncthreads();
        #pragma unroll
        for (int i = 0; i < 2; i++)
            #pragma unroll
            for (int hf = 0; hf < 2; hf++) {
                int row = wm * 32 + i * 16 + g + 8 * hf;
                l_i[i][hf] = l_i[i][hf] * sc[i][hf] + rsm[row * 2] + rsm[row * 2 + 1];
                m_i[i][hf] = mn[i][hf];
            }

        #pragma unroll
        for (int ks = 0; ks < 16; ks++) {
            uint32_t af[2][4], bf[4][2];
            #pragma unroll
            for (int i = 0; i < 2; i++) {
                int row = wm * 32 + i * 16 + g;
                af[i][0] = __float_as_uint(Ps[row * 132 + ks * 8 + t4]);
                af[i][1] = __float_as_uint(Ps[(row + 8) * 132 + ks * 8 + t4]);
                af[i][2] = __float_as_uint(Ps[row * 132 + ks * 8 + t4 + 4]);
                af[i][3] = __float_as_uint(Ps[(row + 8) * 132 + ks * 8 + t4 + 4]);
            }
            #pragma unroll
            for (int j = 0; j < 4; j++) {
                int nc = wn * 32 + j * 8 + g;
                bf[j][0] = __float_as_uint(Vs[(ks * 8 + t4) * 68 + nc]);
                bf[j][1] = __float_as_uint(Vs[(ks * 8 + t4 + 4) * 68 + nc]);
            }
            #pragma unroll
            for (int i = 0; i < 2; i++)
                #pragma unroll
                for (int j = 0; j < 4; j++)
                    mma_tf32(oa[i][j], af[i][0], af[i][1], af[i][2], af[i][3],
                             bf[j][0], bf[j][1]);
        }

        __syncthreads();     // Vs reusable
        if (kc < 3) loadV(kc + 1);
        CP_COMMIT();
    }

    #pragma unroll
    for (int i = 0; i < 2; i++) {
        float r0 = 1.f / l_i[i][0], r1 = 1.f / l_i[i][1];
        int row = qrow0 + wm * 32 + i * 16 + g;
        #pragma unroll
        for (int j = 0; j < 4; j++) {
            int col = h * 64 + wn * 32 + j * 8 + 2 * t4;
            *(float2*)&ao[(size_t)row * 512 + col] =
                make_float2(tf32r(oa[i][j][0] * r0), tf32r(oa[i][j][1] * r0));
            *(float2*)&ao[(size_t)(row + 8) * 512 + col] =
                make_float2(tf32r(oa[i][j][2] * r1), tf32r(oa[i][j][3] * r1));
        }
    }
}

// ================= mma.sync GEMM (fallback path) =================
template<int BM,int BN,int WARPS_M,int WARPS_N,bool TB,bool RELU,bool GN,bool TFO>
__global__ void __launch_bounds__(WARPS_M*WARPS_N*32)
k_mma(int M, int N, int K,
      const float* __restrict__ Ag, int lda, long long sA1, long long sA2,
      const float* __restrict__ Bg, int ldb, long long sB1, long long sB2,
      float* __restrict__ Cg, int ldc, long long sC1, long long sC2,
      int zdiv, const float* __restrict__ bias, float alpha)
{
    constexpr int BK = 16;
    constexpr int NT = WARPS_M * WARPS_N * 32;
    constexpr int WM = BM / WARPS_M, WN = BN / WARPS_N;
    constexpr int MI = WM / 16, NI = WN / 8;
    constexpr int AST = BK + 4;
    constexpr int BROWS = TB ? BN : BK;
    constexpr int BCOLS = TB ? (BK + 4) : (BN + 8);

    __shared__ __align__(16) float As[2][BM][AST];
    __shared__ __align__(16) float Bs[2][BROWS][BCOLS];

    const int bz = blockIdx.z;
    const int z1 = bz / zdiv, z2 = bz - z1 * zdiv;
    const float* A  = Ag + z1 * sA1 + z2 * sA2;
    const float* Bp = Bg + z1 * sB1 + z2 * sB2;
    float* C        = Cg + z1 * sC1 + z2 * sC2;

    const int m0 = blockIdx.y * BM, n0 = blockIdx.x * BN;
    const int tid  = threadIdx.x;
    const int lane = tid & 31, warp = tid >> 5;
    const int wm = warp / WARPS_N, wn = warp - wm * WARPS_N;
    const int g = lane >> 2, t4 = lane & 3;

    float acc[MI][NI][4];
    #pragma unroll
    for (int i = 0; i < MI; i++)
        #pragma unroll
        for (int j = 0; j < NI; j++)
            #pragma unroll
            for (int q = 0; q < 4; q++) acc[i][j][q] = 0.f;

    auto loadTiles = [&](int st, int k0) {
        #pragma unroll
        for (int r = 0; r < (BM * (BK/4)) / NT; r++) {
            int i = tid + r * NT;
            int m = i >> 2;
            int c = (i & 3) << 2;
            cp16(&As[st][m][c], &A[(size_t)(m0 + m) * lda + k0 + c]);
        }
        if (TB) {
            #pragma unroll
            for (int r = 0; r < (BN * (BK/4)) / NT; r++) {
                int i = tid + r * NT;
                int n = i >> 2;
                int c = (i & 3) << 2;
                int gn = n0 + n;
                if (GN) {
                    bool ok = gn < N;
                    cp16p(&Bs[st][n][c], ok ? &Bp[(size_t)gn * ldb + k0 + c] : (const float*)Bp, ok);
                } else {
                    cp16(&Bs[st][n][c], &Bp[(size_t)gn * ldb + k0 + c]);
                }
            }
        } else {
            #pragma unroll
            for (int r = 0; r < (BK * (BN/4)) / NT; r++) {
                int i = tid + r * NT;
                int kk = i / (BN/4);
                int c  = (i - kk * (BN/4)) << 2;
                cp16(&Bs[st][kk][c], &Bp[(size_t)(k0 + kk) * ldb + n0 + c]);
            }
        }
    };

    const int nk = K / BK;
    loadTiles(0, 0);
    CP_COMMIT();

    for (int kt = 0; kt < nk; kt++) {
        int cur = kt & 1;
        if (kt + 1 < nk) loadTiles(cur ^ 1, (kt + 1) * BK);
        CP_COMMIT();
        CP_WAIT1();
        __syncthreads();

        #pragma unroll
        for (int ks = 0; ks < 2; ks++) {
            uint32_t af[MI][4], bf[NI][2];
            #pragma unroll
            for (int i = 0; i < MI; i++) {
                int mr = wm * WM + i * 16 + g;
                af[i][0] = __float_as_uint(As[cur][mr    ][ks*8 + t4    ]);
                af[i][1] = __float_as_uint(As[cur][mr + 8][ks*8 + t4    ]);
                af[i][2] = __float_as_uint(As[cur][mr    ][ks*8 + t4 + 4]);
                af[i][3] = __float_as_uint(As[cur][mr + 8][ks*8 + t4 + 4]);
            }
            #pragma unroll
            for (int j = 0; j < NI; j++) {
                int nc = wn * WN + j * 8 + g;
                if (TB) {
                    bf[j][0] = __float_as_uint(Bs[cur][nc][ks*8 + t4    ]);
                    bf[j][1] = __float_as_uint(Bs[cur][nc][ks*8 + t4 + 4]);
                } else {
                    bf[j][0] = __float_as_uint(Bs[cur][ks*8 + t4    ][nc]);
                    bf[j][1] = __float_as_uint(Bs[cur][ks*8 + t4 + 4][nc]);
                }
            }
            #pragma unroll
            for (int i = 0; i < MI; i++)
                #pragma unroll
                for (int j = 0; j < NI; j++)
                    mma_tf32(acc[i][j], af[i][0], af[i][1], af[i][2], af[i][3],
                             bf[j][0], bf[j][1]);
        }
        __syncthreads();
    }

    #pragma unroll
    for (int i = 0; i < MI; i++) {
        int r0 = m0 + wm * WM + i * 16 + g;
        #pragma unroll
        for (int j = 0; j < NI; j++) {
            int col = n0 + wn * WN + j * 8 + t4 * 2;
            if (GN && col >= N) continue;
            float b0v = 0.f, b1v = 0.f;
            if (bias) { b0v = bias[col]; b1v = bias[col + 1]; }
            float v0 = acc[i][j][0] * alpha + b0v;
            float v1 = acc[i][j][1] * alpha + b1v;
            float v2 = acc[i][j][2] * alpha + b0v;
            float v3 = acc[i][j][3] * alpha + b1v;
            if (RELU) {
                v0 = fmaxf(v0, 0.f); v1 = fmaxf(v1, 0.f);
                v2 = fmaxf(v2, 0.f); v3 = fmaxf(v3, 0.f);
            }
            if (TFO) {
                v0 = tf32r(v0); v1 = tf32r(v1); v2 = tf32r(v2); v3 = tf32r(v3);
            }
            *reinterpret_cast<float2*>(&C[(size_t)r0 * ldc + col])       = make_float2(v0, v1);
            *reinterpret_cast<float2*>(&C[(size_t)(r0 + 8) * ldc + col]) = make_float2(v2, v3);
        }
    }
}

// ---------------- residual add + layernorm ----------------
__global__ void k_add_ln(const float* __restrict__ xin, const float* __restrict__ res,
                         const float* __restrict__ g, const float* __restrict__ b,
                         float* __restrict__ xout, float* __restrict__ xtf)
{
    int row = blockIdx.x, t = threadIdx.x;
    long long base = (long long)row * D;
    float v0 = xin[base + t]       + res[base + t];
    float v1 = xin[base + t + 256] + res[base + t + 256];
    __shared__ float red[256];
    red[t] = v0 + v1; __syncthreads();
    for (int o = 128; o > 0; o >>= 1) { if (t < o) red[t] += red[t+o]; __syncthreads(); }
    float mean = red[0] * (1.f / D); __syncthreads();
    red[t] = v0*v0 + v1*v1; __syncthreads();
    for (int o = 128; o > 0; o >>= 1) { if (t < o) red[t] += red[t+o]; __syncthreads(); }
    float var = red[0] * (1.f / D) - mean*mean;
    float rs = rsqrtf(var + 1e-5f);
    float o0 = (v0 - mean) * rs * g[t]       + b[t];
    float o1 = (v1 - mean) * rs * g[t + 256] + b[t + 256];
    xout[base + t]       = o0;
    xout[base + t + 256] = o1;
    xtf [base + t]       = tf32r(o0);
    xtf [base + t + 256] = tf32r(o1);
}

// ---------------- embedding ----------------
__global__ void k_embed(const int* __restrict__ src, const float* __restrict__ emb,
                        const float* __restrict__ pos, float* __restrict__ x,
                        float* __restrict__ xtf)
{
    int idx = blockIdx.x * blockDim.x + threadIdx.x;
    int t = idx >> 9, d = idx & 511;
    float v = emb[(long long)src[t] * D + d] * SQRTD_F + pos[(t & 511) * D + d];
    x[idx]   = v;
    xtf[idx] = tf32r(v);
}

// ---------------- round static weights ----------------
__global__ void k_round_w(const float* __restrict__ opw, const float* __restrict__ ow, int nOw)
{
    int i = blockIdx.x * blockDim.x + threadIdx.x;
    if (i < L * D * D) d_wr[i] = tf32r(opw[i]);
    if (i < nOw)       d_owr[i] = tf32r(ow[i]);
}

// ---------------- batched prune pipeline ----------------
__device__ __forceinline__ const float* slot_w(int slot, const float* ipw,
                                               const float* w1, const float* w2, int& n)
{
    int t = slot / 6, l = slot - t * 6;
    if (t == 0) { n = 3 * D * D; return ipw + (size_t)l * 3 * D * D; }
    n = F * D;
    return (t == 1) ? w1 + (size_t)l * F * D : w2 + (size_t)l * F * D;
}

__global__ void k_zero_all()
{
    int i = blockIdx.x * blockDim.x + threadIdx.x;
    if (i < NSLOT * 2 * 65536) d_h2g[i] = 0;
    if (i < NSLOT * 4096)      d_h1g[i] = 0;
    if (i < NSLOT * 32)        d_h3g[i] = 0;
}

__global__ void k_etch_all(const float* __restrict__ ipw, const float* __restrict__ w1,
                           const float* __restrict__ w2)
{
    int slot = blockIdx.y;
    int n;
    const float* w = slot_w(slot, ipw, w1, w2, n);
    float inv = 1.f / (float)(n - 1);
    float* aout = d_abs_all + (size_t)slot * SLOT_STRIDE;
    unsigned* h1 = d_h1g + slot * 4096;

    __shared__ unsigned h[4096];
    for (int j = threadIdx.x; j < 4096; j += blockDim.x) h[j] = 0;
    __syncthreads();
    int stride = gridDim.x * blockDim.x;
    for (int i = blockIdx.x * blockDim.x + threadIdx.x; i < n; i += stride) {
        float wv = w[i];
        float b0 = sinf(wv * PI_F);
        b0 = fminf(fmaxf(b0, -1.f), 1.f);
        float bl = b0 + b0 * cosf((float)i * inv + THIRD_F) * 1.5f;
        float e = cosf(bl * PI2_F) + bl * bl * DEVPI_F;
        float a = fabsf(e);
        aout[i] = a;
        atomicAdd(&h[__float_as_uint(a) >> 20], 1u);
    }
    __syncthreads();
    for (int j = threadIdx.x; j < 4096; j += blockDim.x) {
        unsigned c = h[j];
        if (c) atomicAdd(&h1[j], c);
    }
}

__global__ void k_scan1_all(const float* ipw, const float* w1, const float* w2)
{
    int slot = blockIdx.x;
    int n; slot_w(slot, ipw, w1, w2, n);
    unsigned rA = (unsigned)((n - 1) >> 2);
    unsigned rB = rA + 1;
    const unsigned* h1 = d_h1g + slot * 4096;
    unsigned* sel = d_selg + slot * 8;

    __shared__ unsigned part[256];
    __shared__ unsigned pref[256];
    int t = threadIdx.x, base = t * 16;
    unsigned c[16]; unsigned s = 0;
    for (int j = 0; j < 16; j++) { c[j] = h1[base + j]; s += c[j]; }
    part[t] = s; __syncthreads();
    if (t == 0) { unsigned a = 0; for (int i = 0; i < 256; i++) { pref[i] = a; a += part[i]; } }
    __syncthreads();
    unsigned p = pref[t];
    for (int j = 0; j < 16; j++) {
        if (rA >= p && rA < p + c[j]) { sel[0] = base + j; sel[1] = rA - p; }
        if (rB >= p && rB < p + c[j]) { sel[2] = base + j; sel[3] = rB - p; }
        p += c[j];
    }
}

__global__ void k_hist2_all(const float* ipw, const float* w1, const float* w2)
{
    int slot = blockIdx.y;
    int n; slot_w(slot, ipw, w1, w2, n);
    const float* ab = d_abs_all + (size_t)slot * SLOT_STRIDE;
    const unsigned* sel = d_selg + slot * 8;
    unsigned* h2 = d_h2g + (size_t)slot * 131072;
    unsigned sA = sel[0], sB = sel[2];
    int stride = gridDim.x * blockDim.x;
    for (int i = blockIdx.x * blockDim.x + threadIdx.x; i < n; i += stride) {
        unsigned u = __float_as_uint(ab[i]);
        unsigned hi = u >> 20, mid = (u >> 4) & 0xFFFFu;
        if (hi == sA) atomicAdd(&h2[mid], 1u);
        if (hi == sB) atomicAdd(&h2[65536 + mid], 1u);
    }
}

__global__ void k_scan2_all()
{
    int slot = blockIdx.x;
    unsigned* sel = d_selg + slot * 8;
    __shared__ unsigned part[256];
    __shared__ unsigned pref[256];
    int t = threadIdx.x;
    for (int sidx = 0; sidx < 2; sidx++) {
        unsigned rank = sel[1 + sidx * 2];
        const unsigned* hb = d_h2g + (size_t)slot * 131072 + sidx * 65536;
        int base = t * 256;
        unsigned s = 0;
        for (int j = 0; j < 256; j++) s += hb[base + j];
        part[t] = s; __syncthreads();
        if (t == 0) { unsigned a = 0; for (int i = 0; i < 256; i++) { pref[i] = a; a += part[i]; } }
        __syncthreads();
        unsigned p = pref[t];
        for (int j = 0; j < 256; j++) {
            unsigned c = hb[base + j];
            if (rank >= p && rank < p + c) { sel[4 + sidx*2] = base + j; sel[5 + sidx*2] = rank - p; }
            p += c;
        }
        __syncthreads();
    }
}

__global__ void k_hist3_all(const float* ipw, const float* w1, const float* w2)
{
    int slot = blockIdx.y;
    int n; slot_w(slot, ipw, w1, w2, n);
    const float* ab = d_abs_all + (size_t)slot * SLOT_STRIDE;
    const unsigned* sel = d_selg + slot * 8;
    unsigned* h3 = d_h3g + slot * 32;
    unsigned kA = (sel[0] << 16) | sel[4];
    unsigned kB = (sel[2] << 16) | sel[6];
    int stride = gridDim.x * blockDim.x;
    for (int i = blockIdx.x * blockDim.x + threadIdx.x; i < n; i += stride) {
        unsigned u = __float_as_uint(ab[i]);
        unsigned top = u >> 4;
        if (top == kA) atomicAdd(&h3[u & 15u], 1u);
        if (top == kB) atomicAdd(&h3[16 + (u & 15u)], 1u);
    }
}

__global__ void k_thr_all(const float* ipw, const float* w1, const float* w2)
{
    int slot = blockIdx.x * blockDim.x + threadIdx.x;
    if (slot >= NSLOT) return;
    int n; slot_w(slot, ipw, w1, w2, n);
    float frac = 0.25f * (float)((n - 1) & 3);
    const unsigned* sel = d_selg + slot * 8;
    const unsigned* h3 = d_h3g + slot * 32;
    unsigned remA = sel[5]; unsigned lowA = 0;
    for (int j = 0; j < 16; j++) { unsigned c = h3[j]; if (remA < c) { lowA = j; break; } remA -= c; }
    unsigned remB = sel[7]; unsigned lowB = 0;
    for (int j = 0; j < 16; j++) { unsigned c = h3[16 + j]; if (remB < c) { lowB = j; break; } remB -= c; }
    float vA = __uint_as_float((sel[0] << 20) | (sel[4] << 4) | lowA);
    float vB = __uint_as_float((sel[2] << 20) | (sel[6] << 4) | lowB);
    d_thrg[slot] = vA + frac * (vB - vA);
}

__global__ void k_mask_all(const float* __restrict__ ipw, const float* __restrict__ w1,
                           const float* __restrict__ w2)
{
    int slot = blockIdx.y;
    int n;
    const float* w = slot_w(slot, ipw, w1, w2, n);
    int i = blockIdx.x * blockDim.x + threadIdx.x;
    if (i >= n) return;
    float thr = d_thrg[slot];
    d_wp[(size_t)slot * SLOT_STRIDE + i] =
        (d_abs_all[(size_t)slot * SLOT_STRIDE + i] > thr) ? tf32r(w[i]) : 0.f;
}

// ---------------- entry point ----------------
extern "C" void kernel_launch(void* const* d_in, const int* in_sizes, int n_in,
                              void* d_out, int out_size)
{
    const int*   src = (const int*)  d_in[0];
    const float* emb = (const float*)d_in[1];
    const float* pos = (const float*)d_in[2];
    const float* ipw = (const float*)d_in[3];
    const float* ipb = (const float*)d_in[4];
    const float* opw = (const float*)d_in[5];
    const float* opb = (const float*)d_in[6];
    const float* l1g = (const float*)d_in[7];
    const float* l1b = (const float*)d_in[8];
    const float* l2g = (const float*)d_in[9];
    const float* l2b = (const float*)d_in[10];
    const float* w1  = (const float*)d_in[11];
    const float* b1  = (const float*)d_in[12];
    const float* w2  = (const float*)d_in[13];
    const float* b2  = (const float*)d_in[14];
    const float* ow  = (const float*)d_in[15];
    const float* ob  = (const float*)d_in[16];
    const int V = in_sizes[16];
    float* out = (float*)d_out;

    float *px, *pxtf, *pqkv, *pao, *pff, *ptmp, *pwp, *pwr, *powr;
    cudaGetSymbolAddress((void**)&px,   d_x);
    cudaGetSymbolAddress((void**)&pxtf, d_xtf);
    cudaGetSymbolAddress((void**)&pqkv, d_qkv);
    cudaGetSymbolAddress((void**)&pao,  d_ao);
    cudaGetSymbolAddress((void**)&pff,  d_ff);
    cudaGetSymbolAddress((void**)&ptmp, d_tmp);
    cudaGetSymbolAddress((void**)&pwp,  d_wp);
    cudaGetSymbolAddress((void**)&pwr,  d_wr);
    cudaGetSymbolAddress((void**)&powr, d_owr);

    cudaFuncAttributes fa{};
    cudaFuncGetAttributes(&fa, k_tc<false,false,false,false>);
    const bool use_tc = fa.numRegs > 40;

    if (use_tc) {
        cudaFuncSetAttribute(k_tc<false,false,false,false>, cudaFuncAttributeMaxDynamicSharedMemorySize, TC_SMEM);
        cudaFuncSetAttribute(k_tc<false,false,true ,true >, cudaFuncAttributeMaxDynamicSharedMemorySize, TC_SMEM);
        cudaFuncSetAttribute(k_tc<true ,false,true ,true >, cudaFuncAttributeMaxDynamicSharedMemorySize, TC_SMEM);
        cudaFuncSetAttribute(k_tc<false,true ,false,true >, cudaFuncAttributeMaxDynamicSharedMemorySize, TC_SMEM);
    }
    cudaFuncSetAttribute(k_attn, cudaFuncAttributeMaxDynamicSharedMemorySize, AT_SMEM);

    k_embed<<<MT * D / 256, 256>>>(src, emb, pos, px, pxtf);
    k_round_w<<<(V * D + 255) / 256, 256>>>(opw, ow, V * D);

    k_zero_all<<<(NSLOT * 2 * 65536 + 255) / 256, 256>>>();
    k_etch_all <<<dim3(128, NSLOT), 256>>>(ipw, w1, w2);
    k_scan1_all<<<NSLOT, 256>>>(ipw, w1, w2);
    k_hist2_all<<<dim3(128, NSLOT), 256>>>(ipw, w1, w2);
    k_scan2_all<<<NSLOT, 256>>>();
    k_hist3_all<<<dim3(128, NSLOT), 256>>>(ipw, w1, w2);
    k_thr_all  <<<1, 32>>>(ipw, w1, w2);
    k_mask_all <<<dim3(4096, NSLOT), 256>>>(ipw, w1, w2);

    for (int l = 0; l < L; l++) {
        const float* wi_l = pwp + (size_t)(0 * 6 + l) * SLOT_STRIDE;
        const float* w1_l = pwp + (size_t)(1 * 6 + l) * SLOT_STRIDE;
        const float* w2_l = pwp + (size_t)(2 * 6 + l) * SLOT_STRIDE;

        // qkv = x @ wi^T + b (dual-M, output tf32-rounded: feeds attention)
        if (use_tc)
            k_tc<false,false,true,true><<<dim3((3*D)/TC_BN, MT/256), 256, TC_SMEM>>>(
                3*D, D, pxtf, D, wi_l, D, pqkv, 3*D, ipb + (size_t)l * 3 * D);
        else
            k_mma<128,128,2,2,true,false,false,true><<<dim3((3*D)/128, MT/128, 1), 128>>>(
                MT, 3*D, D, pxtf, D, 0, 0, wi_l, D, 0, 0, pqkv, 3*D, 0, 0, 1,
                ipb + (size_t)l * 3 * D, 1.f);

        // fused flash attention
        k_attn<<<dim3(4, BH), 256, AT_SMEM>>>(pqkv, pao);

        // out projection (single-M: keeps grid at 128 CTAs)
        if (use_tc)
            k_tc<false,false,false,false><<<dim3(D/TC_BN, MT/128), 256, TC_SMEM>>>(
                D, D, pao, D, pwr + (size_t)l*D*D, D, ptmp, D, opb + (size_t)l*D);
        else
            k_mma<128,128,2,2,true,false,false,false><<<dim3(D/128, MT/128, 1), 128>>>(
                MT, D, D, pao, D, 0, 0, pwr + (size_t)l*D*D, D, 0, 0,
                ptmp, D, 0, 0, 1, opb + (size_t)l*D, 1.f);
        k_add_ln<<<MT, 256>>>(px, ptmp, l1g + (size_t)l*D, l1b + (size_t)l*D, px, pxtf);

        // feed-forward: ff1 dual-M, ff2 single-M
        if (use_tc) {
            k_tc<true,false,true,true><<<dim3(F/TC_BN, MT/256), 256, TC_SMEM>>>(
                F, D, pxtf, D, w1_l, D, pff, F, b1 + (size_t)l*F);
            k_tc<false,false,false,false><<<dim3(D/TC_BN, MT/128), 256, TC_SMEM>>>(
                D, F, pff, F, w2_l, F, ptmp, D, b2 + (size_t)l*D);
        } else {
            k_mma<128,128,2,2,true,true,false,true><<<dim3(F/128, MT/128, 1), 128>>>(
                MT, F, D, pxtf, D, 0, 0, w1_l, D, 0, 0, pff, F, 0, 0, 1,
                b1 + (size_t)l*F, 1.f);
            k_mma<128,128,2,2,true,false,false,false><<<dim3(D/128, MT/128, 1), 128>>>(
                MT, D, F, pff, F, 0, 0, w2_l, F, 0, 0, ptmp, D, 0, 0, 1,
                b2 + (size_t)l*D, 1.f);
        }
        k_add_ln<<<MT, 256>>>(px, ptmp, l2g + (size_t)l*D, l2b + (size_t)l*D, px, pxtf);
    }

    // logits (dual-M, N guarded)
    if (use_tc)
        k_tc<false,true,false,true><<<dim3((V + TC_BN - 1)/TC_BN, MT/256), 256, TC_SMEM>>>(
            V, D, pxtf, D, powr, D, out, V, ob);
    else
        k_mma<128,128,2,2,true,false,true,false><<<dim3((V + 127) / 128, MT / 128, 1), 128>>>(
            MT, V, D, pxtf, D, 0, 0, powr, D, 0, 0, out, V, 0, 0, 1, ob, 1.f);
}

// round 11
// speedup vs baseline: 2.1183x; 1.0355x over previous
#include <cuda_runtime.h>
#include <cstdint>
#include <math.h>

// ---------------- constants ----------------
#define PI_F      3.14159265358979323846f
#define PI2_F     9.86960440108935861883f
#define THIRD_F   2.09439510239319549231f
#define DEVPI_F   0.003183098861837907f
#define SQRTD_F   22.62741699796952f

constexpr int S  = 512;
constexpr int D  = 512;
constexpr int H  = 8;
constexpr int DH = 64;
constexpr int L  = 6;
constexpr int F  = 2048;
constexpr int BB = 16;
constexpr int MT = BB * S;   // 8192 tokens
constexpr int BH = BB * H;   // 128
constexpr int NSLOT = 18;
constexpr size_t SLOT_STRIDE = 1048576;
constexpr int VMAX = 10240;

// Feature gate: tcgen05 only exists on arch-specific (sm_103a) / family (sm_103f) targets.
#if !defined(__CUDA_ARCH__) || defined(__CUDA_ARCH_FEAT_SM103_ALL) || defined(__CUDA_ARCH_SPECIFIC__) || defined(__CUDA_ARCH_FAMILY_SPECIFIC__)
#define TC_AVAIL 1
#else
#define TC_AVAIL 0
#endif

// ---------------- device scratch ----------------
__device__ __align__(128) float d_x   [MT * D];
__device__ __align__(128) float d_xtf [MT * D];
__device__ __align__(128) float d_qkv [MT * 3 * D];
__device__ __align__(128) float d_ao  [MT * D];
__device__ __align__(128) float d_ff  [MT * F];
__device__ __align__(128) float d_tmp [MT * D];
__device__ __align__(128) float d_wp  [NSLOT * SLOT_STRIDE];
__device__ __align__(128) float d_wr  [L * D * D];
__device__ __align__(128) float d_owr [VMAX * D];
__device__ __align__(128) float d_abs_all[NSLOT * SLOT_STRIDE];
__device__ unsigned d_h1g[NSLOT * 4096];
__device__ unsigned d_h2g[NSLOT * 2 * 65536];
__device__ unsigned d_h3g[NSLOT * 32];
__device__ unsigned d_selg[NSLOT * 8];
__device__ float d_thrg[NSLOT];

// ---------------- helpers ----------------
__device__ __forceinline__ float tf32r(float f) {
    uint32_t u;
    asm("cvt.rna.tf32.f32 %0, %1;" : "=r"(u) : "f"(f));
    return __uint_as_float(u);
}

__device__ __forceinline__ void mma_tf32(float c[4],
    uint32_t a0, uint32_t a1, uint32_t a2, uint32_t a3,
    uint32_t b0, uint32_t b1)
{
    asm volatile(
        "mma.sync.aligned.m16n8k8.row.col.f32.tf32.tf32.f32 "
        "{%0,%1,%2,%3}, {%4,%5,%6,%7}, {%8,%9}, {%0,%1,%2,%3};"
        : "+f"(c[0]), "+f"(c[1]), "+f"(c[2]), "+f"(c[3])
        : "r"(a0), "r"(a1), "r"(a2), "r"(a3), "r"(b0), "r"(b1));
}

__device__ __forceinline__ void cp16(void* d, const void* s) {
    uint32_t a = (uint32_t)__cvta_generic_to_shared(d);
    asm volatile("cp.async.cg.shared.global [%0], [%1], 16;" :: "r"(a), "l"(s));
}
__device__ __forceinline__ void cp16p(void* d, const void* s, bool p) {
    uint32_t a = (uint32_t)__cvta_generic_to_shared(d);
    int sz = p ? 16 : 0;
    asm volatile("cp.async.cg.shared.global [%0], [%1], 16, %2;" :: "r"(a), "l"(s), "r"(sz));
}
#define CP_COMMIT() asm volatile("cp.async.commit_group;")
#define CP_WAIT0()  asm volatile("cp.async.wait_group 0;")
#define CP_WAIT1()  asm volatile("cp.async.wait_group 1;")
#define CP_WAIT2()  asm volatile("cp.async.wait_group 2;")

// ================= tcgen05 tf32 GEMM (guarded) =================
// Single-M: 128x256 tile, NS=4. Dual-M (M2): 256x256 tile via two TMEM halves, NS=3.
constexpr int TC_BN = 256;
constexpr int TC_BK = 32;
constexpr int TC_SMEM = 197632;

#if TC_AVAIL
__device__ __forceinline__ uint32_t elect1() {
    uint32_t pred;
    asm volatile("{\n\t.reg .pred p;\n\telect.sync _|p, 0xFFFFFFFF;\n\t"
                 "selp.b32 %0, 1, 0, p;\n\t}" : "=r"(pred));
    return pred;
}
#define MBAR_INIT(addr, cnt) \
    asm volatile("mbarrier.init.shared.b64 [%0], %1;" :: "r"(addr), "r"(cnt) : "memory")
#define MBAR_WAIT(addr, par) do { \
    asm volatile("{\n\t.reg .pred P1;\n\tWL%=:\n\t" \
        "mbarrier.try_wait.parity.acquire.cta.shared::cta.b64 P1, [%0], %1, 0x989680;\n\t" \
        "@P1 bra.uni WD%=;\n\tbra.uni WL%=;\n\tWD%=:\n\t}" \
        :: "r"(addr), "r"(par) : "memory"); \
} while (0)
#define TC_ALLOC(sm, n)   asm volatile("tcgen05.alloc.cta_group::1.sync.aligned.shared::cta.b32 [%0], %1;" :: "r"(sm), "r"(n) : "memory")
#define TC_DEALLOC(t, n)  asm volatile("tcgen05.dealloc.cta_group::1.sync.aligned.b32 %0, %1;" :: "r"(t), "r"(n))
#define TC_COMMIT(mb)     asm volatile("tcgen05.commit.cta_group::1.mbarrier::arrive::one.shared::cluster.b64 [%0];" :: "r"(mb) : "memory")
#define TC_FENCE_AFTER()  asm volatile("tcgen05.fence::after_thread_sync;" ::: "memory")
#define TC_FENCE_BEFORE() asm volatile("tcgen05.fence::before_thread_sync;" ::: "memory")
#define TC_WAIT_LD()      asm volatile("tcgen05.wait::ld.sync.aligned;" ::: "memory")
#define FENCE_PROXY()     asm volatile("fence.proxy.async.shared::cta;" ::: "memory")

#define TC_LD_X32(r, addr) \
    asm volatile("tcgen05.ld.sync.aligned.32x32b.x32.b32 " \
        "{%0, %1, %2, %3, %4, %5, %6, %7, %8, %9, %10, %11, %12, %13, %14, %15, " \
        " %16, %17, %18, %19, %20, %21, %22, %23, %24, %25, %26, %27, %28, %29, %30, %31}, [%32];" \
        : "=r"((r)[0]),  "=r"((r)[1]),  "=r"((r)[2]),  "=r"((r)[3]), \
          "=r"((r)[4]),  "=r"((r)[5]),  "=r"((r)[6]),  "=r"((r)[7]), \
          "=r"((r)[8]),  "=r"((r)[9]),  "=r"((r)[10]), "=r"((r)[11]), \
          "=r"((r)[12]), "=r"((r)[13]), "=r"((r)[14]), "=r"((r)[15]), \
          "=r"((r)[16]), "=r"((r)[17]), "=r"((r)[18]), "=r"((r)[19]), \
          "=r"((r)[20]), "=r"((r)[21]), "=r"((r)[22]), "=r"((r)[23]), \
          "=r"((r)[24]), "=r"((r)[25]), "=r"((r)[26]), "=r"((r)[27]), \
          "=r"((r)[28]), "=r"((r)[29]), "=r"((r)[30]), "=r"((r)[31]) \
        : "r"(addr))

static constexpr uint64_t SMEM_DESC_BASE =
    (uint64_t(2) << 61) | (uint64_t(1) << 46) | (uint64_t(64) << 32) | (uint64_t(1) << 16);
#define MK_DESC(a) (SMEM_DESC_BASE | ((uint64_t)((a) >> 4) & 0x3FFF))

__device__ __forceinline__ void mma_tc(uint32_t d, uint64_t ad, uint64_t bd,
                                       uint32_t idesc, bool en)
{
    uint32_t e = en ? 1 : 0;
    asm volatile(
        "{\n\t.reg .pred p;\n\tsetp.ne.u32 p, %4, 0;\n\t"
        "tcgen05.mma.cta_group::1.kind::tf32 [%0], %1, %2, %3, {%5,%5,%5,%5}, p;\n\t}"
        :: "r"(d), "l"(ad), "l"(bd), "r"(idesc), "r"(e), "r"(0u) : "memory");
}
#endif  // TC_AVAIL

constexpr uint32_t TC_IDESC =
    (1u << 4) | (2u << 7) | (2u << 10) | ((TC_BN / 8) << 17) | ((128 / 16) << 24);

// C[m,n] = sum_k A[m,k]*B[n,k] + bias[n]; operands pre-rounded to tf32 values.
// M2=false: grid (N/256, M/128).  M2=true: grid (N/256, M/256), B loaded once per 256 M-rows.
template<bool RELU, bool GN, bool TFO, bool M2>
__global__ void __launch_bounds__(256, 1)
k_tc(int N, int K,
     const float* __restrict__ A, int lda,
     const float* __restrict__ B, int ldb,
     float* __restrict__ C, int ldc,
     const float* __restrict__ bias)
{
#if TC_AVAIL
    constexpr int NS    = M2 ? 3 : 4;
    constexpr int AROWS = M2 ? 256 : 128;
    constexpr int ASZ   = AROWS * 128;
    constexpr int BSZ   = TC_BN * 128;
    constexpr int TCOLS = M2 ? 512 : 256;

    extern __shared__ char smem[];
    uint32_t sbase = (uint32_t)__cvta_generic_to_shared(smem);
    const int tid = threadIdx.x, lane = tid & 31, warp = tid >> 5;
    const int m0 = blockIdx.y * AROWS, n0 = blockIdx.x * TC_BN;

    if (warp == 0) TC_ALLOC(sbase, TCOLS);
    if (tid == 0) {
        #pragma unroll
        for (int s = 0; s < NS; s++) MBAR_INIT(sbase + 16 + 8 * s, 1);
    }
    __syncthreads();
    uint32_t tmem;
    asm volatile("ld.shared.b32 %0, [%1];" : "=r"(tmem) : "r"(sbase));

    const uint32_t aoff = 1024, boff = 1024 + NS * ASZ;

    auto loadStage = [&](int st, int k0) {
        char* pa = smem + aoff + st * ASZ;
        char* pb = smem + boff + st * BSZ;
        #pragma unroll
        for (int r = 0; r < AROWS / 32; r++) {
            int i = tid + r * 256;
            int m = i >> 3, c = i & 7;
            int cs = c ^ (m & 7);     // SW128
            cp16(pa + m * 128 + cs * 16, &A[(size_t)(m0 + m) * lda + k0 + c * 4]);
        }
        #pragma unroll
        for (int r = 0; r < 8; r++) {
            int i = tid + r * 256;
            int n = i >> 3, c = i & 7;
            int cs = c ^ (n & 7);
            int gn = n0 + n;
            if (GN) {
                bool ok = gn < N;
                cp16p(pb + n * 128 + cs * 16,
                      ok ? &B[(size_t)gn * ldb + k0 + c * 4] : (const float*)B, ok);
            } else {
                cp16(pb + n * 128 + cs * 16, &B[(size_t)gn * ldb + k0 + c * 4]);
            }
        }
    };

    const int nk = K / TC_BK;

    #pragma unroll
    for (int s = 0; s < NS - 1; s++) { loadStage(s, s * TC_BK); CP_COMMIT(); }

    for (int kt = 0; kt < nk; kt++) {
        int cur = kt % NS;
        if (M2) { CP_WAIT1(); } else { CP_WAIT2(); }
        __syncthreads();
        FENCE_PROXY();
        if (warp == 0 && elect1()) {
            uint64_t ad = MK_DESC(sbase + aoff + cur * ASZ);
            uint64_t bd = MK_DESC(sbase + boff + cur * BSZ);
            #pragma unroll
            for (int j = 0; j < 4; j++) {
                bool en = (kt > 0) || (j > 0);
                mma_tc(tmem, ad + j * 2, bd + j * 2, TC_IDESC, en);
                if (M2) {
                    uint64_t ad2 = MK_DESC(sbase + aoff + cur * ASZ + 128 * 128);
                    mma_tc(tmem + 256, ad2 + j * 2, bd + j * 2, TC_IDESC, en);
                }
            }
            TC_COMMIT(sbase + 16 + 8 * cur);
        }
        if (kt >= 1) MBAR_WAIT(sbase + 16 + 8 * ((kt - 1) % NS), ((kt - 1) / NS) & 1);
        int kn = kt + NS - 1;
        if (kn < nk) loadStage(kn % NS, kn * TC_BK);
        CP_COMMIT();
    }
    MBAR_WAIT(sbase + 16 + 8 * ((nk - 1) % NS), ((nk - 1) / NS) & 1);

    __syncthreads();
    TC_FENCE_AFTER();

    float* myep = (float*)(smem + 1024) + warp * (32 * 33);
    if (M2) {
        int half = warp >> 2;
        uint32_t tbase = tmem + half * 256;
        int rbase = m0 + half * 128 + (warp & 3) * 32;
        #pragma unroll
        for (int ch = 0; ch < 8; ch++) {
            int c0 = ch * 32;
            uint32_t regs[32];
            TC_LD_X32(regs, tbase + c0);
            TC_WAIT_LD();
            #pragma unroll
            for (int c = 0; c < 32; c++) {
                float v = __uint_as_float(regs[c]);
                if (!GN || (n0 + c0 + c) < N) {
                    v += bias[n0 + c0 + c];
                    if (RELU) v = fmaxf(v, 0.f);
                    if (TFO)  v = tf32r(v);
                }
                myep[lane * 33 + c] = v;
            }
            __syncwarp();
            int col = n0 + c0 + lane;
            #pragma unroll
            for (int i = 0; i < 32; i++) {
                if (!GN || col < N)
                    C[(size_t)(rbase + i) * ldc + col] = myep[i * 33 + lane];
            }
            __syncwarp();
        }
    } else {
        int rbase = m0 + (warp & 3) * 32;
        int cbase = (warp >> 2) * 128;
        #pragma unroll
        for (int ch = 0; ch < 4; ch++) {
            int c0 = cbase + ch * 32;
            uint32_t regs[32];
            TC_LD_X32(regs, tmem + c0);
            TC_WAIT_LD();
            #pragma unroll
            for (int c = 0; c < 32; c++) {
                float v = __uint_as_float(regs[c]);
                if (!GN || (n0 + c0 + c) < N) {
                    v += bias[n0 + c0 + c];
                    if (RELU) v = fmaxf(v, 0.f);
                    if (TFO)  v = tf32r(v);
                }
                myep[lane * 33 + c] = v;
            }
            __syncwarp();
            int col = n0 + c0 + lane;
            #pragma unroll
            for (int i = 0; i < 32; i++) {
                if (!GN || col < N)
                    C[(size_t)(rbase + i) * ldc + col] = myep[i * 33 + lane];
            }
            __syncwarp();
        }
    }

    __syncthreads();
    if (warp == 0) { TC_FENCE_BEFORE(); TC_DEALLOC(tmem, TCOLS); }
#endif  // TC_AVAIL
}

// ================= fused flash attention (mma.sync tf32, pipelined KV) =================
constexpr int AT_SMEM = 174080;

__global__ void __launch_bounds__(256, 1)
k_attn(const float* __restrict__ qkv, float* __restrict__ ao)
{
    extern __shared__ float sm_[];
    float* Qs   = sm_;               // [128][68]
    float* Ks   = Qs + 128 * 68;
    float* Vs   = Ks + 128 * 68;
    float* Ps   = Vs + 128 * 68;     // [128][132]
    float* rmx  = Ps + 128 * 132;
    float* rsm  = rmx + 256;

    const int tid = threadIdx.x, lane = tid & 31, warp = tid >> 5;
    const int wm = warp >> 1, wn = warp & 1;
    const int g = lane >> 2, t4 = lane & 3;
    const int bh = blockIdx.y, b = bh >> 3, h = bh & 7;
    const int qrow0 = b * 512 + blockIdx.x * 128;
    const int kvbase = b * 512;

    auto loadK = [&](int kc) {
        int kvrow0 = kvbase + kc * 128;
        #pragma unroll
        for (int r = 0; r < 8; r++) {
            int i = tid + r * 256;
            int row = i >> 4, c = (i & 15) << 2;
            cp16(&Ks[row * 68 + c], &qkv[(size_t)(kvrow0 + row) * 1536 + 512 + h * 64 + c]);
        }
    };
    auto loadV = [&](int kc) {
        int kvrow0 = kvbase + kc * 128;
        #pragma unroll
        for (int r = 0; r < 8; r++) {
            int i = tid + r * 256;
            int row = i >> 4, c = (i & 15) << 2;
            cp16(&Vs[row * 68 + c], &qkv[(size_t)(kvrow0 + row) * 1536 + 1024 + h * 64 + c]);
        }
    };

    loadK(0); CP_COMMIT();
    loadV(0); CP_COMMIT();

    #pragma unroll
    for (int r = 0; r < 8; r++) {
        int i = tid + r * 256;
        int row = i >> 4, c = (i & 15) << 2;
        float4 v = *(const float4*)&qkv[(size_t)(qrow0 + row) * 1536 + h * 64 + c];
        Qs[row * 68 + c]     = v.x * 0.125f;
        Qs[row * 68 + c + 1] = v.y * 0.125f;
        Qs[row * 68 + c + 2] = v.z * 0.125f;
        Qs[row * 68 + c + 3] = v.w * 0.125f;
    }

    float m_i[2][2], l_i[2][2];
    float oa[2][4][4];
    #pragma unroll
    for (int i = 0; i < 2; i++)
        #pragma unroll
        for (int hf = 0; hf < 2; hf++) { m_i[i][hf] = -1e30f; l_i[i][hf] = 0.f; }
    #pragma unroll
    for (int i = 0; i < 2; i++)
        #pragma unroll
        for (int j = 0; j < 4; j++)
            #pragma unroll
            for (int q = 0; q < 4; q++) oa[i][j][q] = 0.f;

    for (int kc = 0; kc < 4; kc++) {
        CP_WAIT1();
        __syncthreads();

        float s[2][8][4];
        #pragma unroll
        for (int i = 0; i < 2; i++)
            #pragma unroll
            for (int j = 0; j < 8; j++)
                #pragma unroll
                for (int q = 0; q < 4; q++) s[i][j][q] = 0.f;

        #pragma unroll
        for (int ks = 0; ks < 8; ks++) {
            uint32_t af[2][4], bf[8][2];
            #pragma unroll
            for (int i = 0; i < 2; i++) {
                int row = wm * 32 + i * 16 + g;
                af[i][0] = __float_as_uint(Qs[row * 68 + ks * 8 + t4]);
                af[i][1] = __float_as_uint(Qs[(row + 8) * 68 + ks * 8 + t4]);
                af[i][2] = __float_as_uint(Qs[row * 68 + ks * 8 + t4 + 4]);
                af[i][3] = __float_as_uint(Qs[(row + 8) * 68 + ks * 8 + t4 + 4]);
            }
            #pragma unroll
            for (int j = 0; j < 8; j++) {
                int nc = wn * 64 + j * 8 + g;
                bf[j][0] = __float_as_uint(Ks[nc * 68 + ks * 8 + t4]);
                bf[j][1] = __float_as_uint(Ks[nc * 68 + ks * 8 + t4 + 4]);
            }
            #pragma unroll
            for (int i = 0; i < 2; i++)
                #pragma unroll
                for (int j = 0; j < 8; j++)
                    mma_tf32(s[i][j], af[i][0], af[i][1], af[i][2], af[i][3],
                             bf[j][0], bf[j][1]);
        }

        float mn[2][2];
        #pragma unroll
        for (int i = 0; i < 2; i++)
            #pragma unroll
            for (int hf = 0; hf < 2; hf++) {
                float v = -1e30f;
                #pragma unroll
                for (int j = 0; j < 8; j++)
                    v = fmaxf(v, fmaxf(s[i][j][2 * hf], s[i][j][2 * hf + 1]));
                v = fmaxf(v, __shfl_xor_sync(0xFFFFFFFF, v, 1));
                v = fmaxf(v, __shfl_xor_sync(0xFFFFFFFF, v, 2));
                mn[i][hf] = v;
            }
        if (t4 == 0) {
            #pragma unroll
            for (int i = 0; i < 2; i++)
                #pragma unroll
                for (int hf = 0; hf < 2; hf++)
                    rmx[(wm * 32 + i * 16 + g + 8 * hf) * 2 + wn] = mn[i][hf];
        }
        __syncthreads();

        if (kc < 3) loadK(kc + 1);
        CP_COMMIT();

        float sc[2][2];
        #pragma unroll
        for (int i = 0; i < 2; i++)
            #pragma unroll
            for (int hf = 0; hf < 2; hf++) {
                int row = wm * 32 + i * 16 + g + 8 * hf;
                float cm = fmaxf(rmx[row * 2], rmx[row * 2 + 1]);
                float nm = fmaxf(m_i[i][hf], cm);
                sc[i][hf] = __expf(m_i[i][hf] - nm);
                mn[i][hf] = nm;
            }
        #pragma unroll
        for (int i = 0; i < 2; i++)
            #pragma unroll
            for (int j = 0; j < 4; j++) {
                oa[i][j][0] *= sc[i][0]; oa[i][j][1] *= sc[i][0];
                oa[i][j][2] *= sc[i][1]; oa[i][j][3] *= sc[i][1];
            }
        float smv[2][2] = {{0.f, 0.f}, {0.f, 0.f}};
        #pragma unroll
        for (int i = 0; i < 2; i++) {
            int row = wm * 32 + i * 16 + g;
            #pragma unroll
            for (int j = 0; j < 8; j++) {
                int col = wn * 64 + j * 8 + 2 * t4;
                float p0 = __expf(s[i][j][0] - mn[i][0]);
                float p1 = __expf(s[i][j][1] - mn[i][0]);
                float p2 = __expf(s[i][j][2] - mn[i][1]);
                float p3 = __expf(s[i][j][3] - mn[i][1]);
                smv[i][0] += p0 + p1;
                smv[i][1] += p2 + p3;
                Ps[row * 132 + col]           = tf32r(p0);
                Ps[row * 132 + col + 1]       = tf32r(p1);
                Ps[(row + 8) * 132 + col]     = tf32r(p2);
                Ps[(row + 8) * 132 + col + 1] = tf32r(p3);
            }
        }
        #pragma unroll
        for (int i = 0; i < 2; i++)
            #pragma unroll
            for (int hf = 0; hf < 2; hf++) {
                float v = smv[i][hf];
                v += __shfl_xor_sync(0xFFFFFFFF, v, 1);
                v += __shfl_xor_sync(0xFFFFFFFF, v, 2);
                smv[i][hf] = v;
            }
        if (t4 == 0) {
            #pragma unroll
            for (int i = 0; i < 2; i++)
                #pragma unroll
                for (int hf = 0; hf < 2; hf++)
                    rsm[(wm * 32 + i * 16 + g + 8 * hf) * 2 + wn] = smv[i][hf];
        }
        CP_WAIT1();
        __syncthreads();
        #pragma unroll
        for (int i = 0; i < 2; i++)
            #pragma unroll
            for (int hf = 0; hf < 2; hf++) {
                int row = wm * 32 + i * 16 + g + 8 * hf;
                l_i[i][hf] = l_i[i][hf] * sc[i][hf] + rsm[row * 2] + rsm[row * 2 + 1];
                m_i[i][hf] = mn[i][hf];
            }

        #pragma unroll
        for (int ks = 0; ks < 16; ks++) {
            uint32_t af[2][4], bf[4][2];
            #pragma unroll
            for (int i = 0; i < 2; i++) {
                int row = wm * 32 + i * 16 + g;
                af[i][0] = __float_as_uint(Ps[row * 132 + ks * 8 + t4]);
                af[i][1] = __float_as_uint(Ps[(row + 8) * 132 + ks * 8 + t4]);
                af[i][2] = __float_as_uint(Ps[row * 132 + ks * 8 + t4 + 4]);
                af[i][3] = __float_as_uint(Ps[(row + 8) * 132 + ks * 8 + t4 + 4]);
            }
            #pragma unroll
            for (int j = 0; j < 4; j++) {
                int nc = wn * 32 + j * 8 + g;
                bf[j][0] = __float_as_uint(Vs[(ks * 8 + t4) * 68 + nc]);
                bf[j][1] = __float_as_uint(Vs[(ks * 8 + t4 + 4) * 68 + nc]);
            }
            #pragma unroll
            for (int i = 0; i < 2; i++)
                #pragma unroll
                for (int j = 0; j < 4; j++)
                    mma_tf32(oa[i][j], af[i][0], af[i][1], af[i][2], af[i][3],
                             bf[j][0], bf[j][1]);
        }

        __syncthreads();
        if (kc < 3) loadV(kc + 1);
        CP_COMMIT();
    }

    #pragma unroll
    for (int i = 0; i < 2; i++) {
        float r0 = 1.f / l_i[i][0], r1 = 1.f / l_i[i][1];
        int row = qrow0 + wm * 32 + i * 16 + g;
        #pragma unroll
        for (int j = 0; j < 4; j++) {
            int col = h * 64 + wn * 32 + j * 8 + 2 * t4;
            *(float2*)&ao[(size_t)row * 512 + col] =
                make_float2(tf32r(oa[i][j][0] * r0), tf32r(oa[i][j][1] * r0));
            *(float2*)&ao[(size_t)(row + 8) * 512 + col] =
                make_float2(tf32r(oa[i][j][2] * r1), tf32r(oa[i][j][3] * r1));
        }
    }
}

// ================= mma.sync GEMM (fallback path) =================
template<int BM,int BN,int WARPS_M,int WARPS_N,bool TB,bool RELU,bool GN,bool TFO>
__global__ void __launch_bounds__(WARPS_M*WARPS_N*32)
k_mma(int M, int N, int K,
      const float* __restrict__ Ag, int lda, long long sA1, long long sA2,
      const float* __restrict__ Bg, int ldb, long long sB1, long long sB2,
      float* __restrict__ Cg, int ldc, long long sC1, long long sC2,
      int zdiv, const float* __restrict__ bias, float alpha)
{
    constexpr int BK = 16;
    constexpr int NT = WARPS_M * WARPS_N * 32;
    constexpr int WM = BM / WARPS_M, WN = BN / WARPS_N;
    constexpr int MI = WM / 16, NI = WN / 8;
    constexpr int AST = BK + 4;
    constexpr int BROWS = TB ? BN : BK;
    constexpr int BCOLS = TB ? (BK + 4) : (BN + 8);

    __shared__ __align__(16) float As[2][BM][AST];
    __shared__ __align__(16) float Bs[2][BROWS][BCOLS];

    const int bz = blockIdx.z;
    const int z1 = bz / zdiv, z2 = bz - z1 * zdiv;
    const float* A  = Ag + z1 * sA1 + z2 * sA2;
    const float* Bp = Bg + z1 * sB1 + z2 * sB2;
    float* C        = Cg + z1 * sC1 + z2 * sC2;

    const int m0 = blockIdx.y * BM, n0 = blockIdx.x * BN;
    const int tid  = threadIdx.x;
    const int lane = tid & 31, warp = tid >> 5;
    const int wm = warp / WARPS_N, wn = warp - wm * WARPS_N;
    const int g = lane >> 2, t4 = lane & 3;

    float acc[MI][NI][4];
    #pragma unroll
    for (int i = 0; i < MI; i++)
        #pragma unroll
        for (int j = 0; j < NI; j++)
            #pragma unroll
            for (int q = 0; q < 4; q++) acc[i][j][q] = 0.f;

    auto loadTiles = [&](int st, int k0) {
        #pragma unroll
        for (int r = 0; r < (BM * (BK/4)) / NT; r++) {
            int i = tid + r * NT;
            int m = i >> 2;
            int c = (i & 3) << 2;
            cp16(&As[st][m][c], &A[(size_t)(m0 + m) * lda + k0 + c]);
        }
        if (TB) {
            #pragma unroll
            for (int r = 0; r < (BN * (BK/4)) / NT; r++) {
                int i = tid + r * NT;
                int n = i >> 2;
                int c = (i & 3) << 2;
                int gn = n0 + n;
                if (GN) {
                    bool ok = gn < N;
                    cp16p(&Bs[st][n][c], ok ? &Bp[(size_t)gn * ldb + k0 + c] : (const float*)Bp, ok);
                } else {
                    cp16(&Bs[st][n][c], &Bp[(size_t)gn * ldb + k0 + c]);
                }
            }
        } else {
            #pragma unroll
            for (int r = 0; r < (BK * (BN/4)) / NT; r++) {
                int i = tid + r * NT;
                int kk = i / (BN/4);
                int c  = (i - kk * (BN/4)) << 2;
                cp16(&Bs[st][kk][c], &Bp[(size_t)(k0 + kk) * ldb + n0 + c]);
            }
        }
    };

    const int nk = K / BK;
    loadTiles(0, 0);
    CP_COMMIT();

    for (int kt = 0; kt < nk; kt++) {
        int cur = kt & 1;
        if (kt + 1 < nk) loadTiles(cur ^ 1, (kt + 1) * BK);
        CP_COMMIT();
        CP_WAIT1();
        __syncthreads();

        #pragma unroll
        for (int ks = 0; ks < 2; ks++) {
            uint32_t af[MI][4], bf[NI][2];
            #pragma unroll
            for (int i = 0; i < MI; i++) {
                int mr = wm * WM + i * 16 + g;
                af[i][0] = __float_as_uint(As[cur][mr    ][ks*8 + t4    ]);
                af[i][1] = __float_as_uint(As[cur][mr + 8][ks*8 + t4    ]);
                af[i][2] = __float_as_uint(As[cur][mr    ][ks*8 + t4 + 4]);
                af[i][3] = __float_as_uint(As[cur][mr + 8][ks*8 + t4 + 4]);
            }
            #pragma unroll
            for (int j = 0; j < NI; j++) {
                int nc = wn * WN + j * 8 + g;
                if (TB) {
                    bf[j][0] = __float_as_uint(Bs[cur][nc][ks*8 + t4    ]);
                    bf[j][1] = __float_as_uint(Bs[cur][nc][ks*8 + t4 + 4]);
                } else {
                    bf[j][0] = __float_as_uint(Bs[cur][ks*8 + t4    ][nc]);
                    bf[j][1] = __float_as_uint(Bs[cur][ks*8 + t4 + 4][nc]);
                }
            }
            #pragma unroll
            for (int i = 0; i < MI; i++)
                #pragma unroll
                for (int j = 0; j < NI; j++)
                    mma_tf32(acc[i][j], af[i][0], af[i][1], af[i][2], af[i][3],
                             bf[j][0], bf[j][1]);
        }
        __syncthreads();
    }

    #pragma unroll
    for (int i = 0; i < MI; i++) {
        int r0 = m0 + wm * WM + i * 16 + g;
        #pragma unroll
        for (int j = 0; j < NI; j++) {
            int col = n0 + wn * WN + j * 8 + t4 * 2;
            if (GN && col >= N) continue;
            float b0v = 0.f, b1v = 0.f;
            if (bias) { b0v = bias[col]; b1v = bias[col + 1]; }
            float v0 = acc[i][j][0] * alpha + b0v;
            float v1 = acc[i][j][1] * alpha + b1v;
            float v2 = acc[i][j][2] * alpha + b0v;
            float v3 = acc[i][j][3] * alpha + b1v;
            if (RELU) {
                v0 = fmaxf(v0, 0.f); v1 = fmaxf(v1, 0.f);
                v2 = fmaxf(v2, 0.f); v3 = fmaxf(v3, 0.f);
            }
            if (TFO) {
                v0 = tf32r(v0); v1 = tf32r(v1); v2 = tf32r(v2); v3 = tf32r(v3);
            }
            *reinterpret_cast<float2*>(&C[(size_t)r0 * ldc + col])       = make_float2(v0, v1);
            *reinterpret_cast<float2*>(&C[(size_t)(r0 + 8) * ldc + col]) = make_float2(v2, v3);
        }
    }
}

// ---------------- residual add + layernorm ----------------
__global__ void k_add_ln(const float* __restrict__ xin, const float* __restrict__ res,
                         const float* __restrict__ g, const float* __restrict__ b,
                         float* __restrict__ xout, float* __restrict__ xtf)
{
    int row = blockIdx.x, t = threadIdx.x;
    long long base = (long long)row * D;
    float v0 = xin[base + t]       + res[base + t];
    float v1 = xin[base + t + 256] + res[base + t + 256];
    __shared__ float red[256];
    red[t] = v0 + v1; __syncthreads();
    for (int o = 128; o > 0; o >>= 1) { if (t < o) red[t] += red[t+o]; __syncthreads(); }
    float mean = red[0] * (1.f / D); __syncthreads();
    red[t] = v0*v0 + v1*v1; __syncthreads();
    for (int o = 128; o > 0; o >>= 1) { if (t < o) red[t] += red[t+o]; __syncthreads(); }
    float var = red[0] * (1.f / D) - mean*mean;
    float rs = rsqrtf(var + 1e-5f);
    float o0 = (v0 - mean) * rs * g[t]       + b[t];
    float o1 = (v1 - mean) * rs * g[t + 256] + b[t + 256];
    xout[base + t]       = o0;
    xout[base + t + 256] = o1;
    xtf [base + t]       = tf32r(o0);
    xtf [base + t + 256] = tf32r(o1);
}

// ---------------- fused prep: embedding + weight rounding + histogram zero ----------------
__global__ void k_prep(const int* __restrict__ src, const float* __restrict__ emb,
                       const float* __restrict__ pos, float* __restrict__ x,
                       float* __restrict__ xtf, const float* __restrict__ opw,
                       const float* __restrict__ ow, int nOw)
{
    int idx = blockIdx.x * blockDim.x + threadIdx.x;
    if (idx < MT * D) {
        int t = idx >> 9, d = idx & 511;
        float v = emb[(long long)src[t] * D + d] * SQRTD_F + pos[(t & 511) * D + d];
        x[idx]   = v;
        xtf[idx] = tf32r(v);
    }
    if (idx < L * D * D) d_wr[idx] = tf32r(opw[idx]);
    if (idx < nOw)       d_owr[idx] = tf32r(ow[idx]);
    if (idx < NSLOT * 2 * 65536) d_h2g[idx] = 0;
    if (idx < NSLOT * 4096)      d_h1g[idx] = 0;
    if (idx < NSLOT * 32)        d_h3g[idx] = 0;
}

// ---------------- batched prune pipeline ----------------
__device__ __forceinline__ const float* slot_w(int slot, const float* ipw,
                                               const float* w1, const float* w2, int& n)
{
    int t = slot / 6, l = slot - t * 6;
    if (t == 0) { n = 3 * D * D; return ipw + (size_t)l * 3 * D * D; }
    n = F * D;
    return (t == 1) ? w1 + (size_t)l * F * D : w2 + (size_t)l * F * D;
}

__global__ void k_etch_all(const float* __restrict__ ipw, const float* __restrict__ w1,
                           const float* __restrict__ w2)
{
    int slot = blockIdx.y;
    int n;
    const float* w = slot_w(slot, ipw, w1, w2, n);
    float inv = 1.f / (float)(n - 1);
    float* aout = d_abs_all + (size_t)slot * SLOT_STRIDE;
    unsigned* h1 = d_h1g + slot * 4096;

    __shared__ unsigned h[4096];
    for (int j = threadIdx.x; j < 4096; j += blockDim.x) h[j] = 0;
    __syncthreads();
    int stride = gridDim.x * blockDim.x;
    for (int i = blockIdx.x * blockDim.x + threadIdx.x; i < n; i += stride) {
        float wv = w[i];
        float b0 = __sinf(wv * PI_F);
        b0 = fminf(fmaxf(b0, -1.f), 1.f);
        float bl = b0 + b0 * __cosf((float)i * inv + THIRD_F) * 1.5f;
        float e = __cosf(bl * PI2_F) + bl * bl * DEVPI_F;
        float a = fabsf(e);
        aout[i] = a;
        atomicAdd(&h[__float_as_uint(a) >> 20], 1u);
    }
    __syncthreads();
    for (int j = threadIdx.x; j < 4096; j += blockDim.x) {
        unsigned c = h[j];
        if (c) atomicAdd(&h1[j], c);
    }
}

__global__ void k_scan1_all(const float* ipw, const float* w1, const float* w2)
{
    int slot = blockIdx.x;
    int n; slot_w(slot, ipw, w1, w2, n);
    unsigned rA = (unsigned)((n - 1) >> 2);
    unsigned rB = rA + 1;
    const unsigned* h1 = d_h1g + slot * 4096;
    unsigned* sel = d_selg + slot * 8;

    __shared__ unsigned part[256];
    __shared__ unsigned pref[256];
    int t = threadIdx.x, base = t * 16;
    unsigned c[16]; unsigned s = 0;
    for (int j = 0; j < 16; j++) { c[j] = h1[base + j]; s += c[j]; }
    part[t] = s; __syncthreads();
    if (t == 0) { unsigned a = 0; for (int i = 0; i < 256; i++) { pref[i] = a; a += part[i]; } }
    __syncthreads();
    unsigned p = pref[t];
    for (int j = 0; j < 16; j++) {
        if (rA >= p && rA < p + c[j]) { sel[0] = base + j; sel[1] = rA - p; }
        if (rB >= p && rB < p + c[j]) { sel[2] = base + j; sel[3] = rB - p; }
        p += c[j];
    }
}

__global__ void k_hist2_all(const float* ipw, const float* w1, const float* w2)
{
    int slot = blockIdx.y;
    int n; slot_w(slot, ipw, w1, w2, n);
    const uint4* ab = (const uint4*)(d_abs_all + (size_t)slot * SLOT_STRIDE);
    const unsigned* sel = d_selg + slot * 8;
    unsigned* h2 = d_h2g + (size_t)slot * 131072;
    unsigned sA = sel[0], sB = sel[2];
    int n4 = n >> 2;
    int stride = gridDim.x * blockDim.x;
    for (int i = blockIdx.x * blockDim.x + threadIdx.x; i < n4; i += stride) {
        uint4 u = ab[i];
        #pragma unroll
        for (int q = 0; q < 4; q++) {
            unsigned v = (q == 0) ? u.x : (q == 1) ? u.y : (q == 2) ? u.z : u.w;
            unsigned hi = v >> 20, mid = (v >> 4) & 0xFFFFu;
            if (hi == sA) atomicAdd(&h2[mid], 1u);
            if (hi == sB) atomicAdd(&h2[65536 + mid], 1u);
        }
    }
}

__global__ void k_scan2_all()
{
    int slot = blockIdx.x;
    unsigned* sel = d_selg + slot * 8;
    __shared__ unsigned part[256];
    __shared__ unsigned pref[256];
    int t = threadIdx.x;
    for (int sidx = 0; sidx < 2; sidx++) {
        unsigned rank = sel[1 + sidx * 2];
        const unsigned* hb = d_h2g + (size_t)slot * 131072 + sidx * 65536;
        int base = t * 256;
        unsigned s = 0;
        for (int j = 0; j < 256; j++) s += hb[base + j];
        part[t] = s; __syncthreads();
        if (t == 0) { unsigned a = 0; for (int i = 0; i < 256; i++) { pref[i] = a; a += part[i]; } }
        __syncthreads();
        unsigned p = pref[t];
        for (int j = 0; j < 256; j++) {
            unsigned c = hb[base + j];
            if (rank >= p && rank < p + c) { sel[4 + sidx*2] = base + j; sel[5 + sidx*2] = rank - p; }
            p += c;
        }
        __syncthreads();
    }
}

__global__ void k_hist3_all(const float* ipw, const float* w1, const float* w2)
{
    int slot = blockIdx.y;
    int n; slot_w(slot, ipw, w1, w2, n);
    const uint4* ab = (const uint4*)(d_abs_all + (size_t)slot * SLOT_STRIDE);
    const unsigned* sel = d_selg + slot * 8;
    unsigned* h3 = d_h3g + slot * 32;
    unsigned kA = (sel[0] << 16) | sel[4];
    unsigned kB = (sel[2] << 16) | sel[6];
    int n4 = n >> 2;
    int stride = gridDim.x * blockDim.x;
    for (int i = blockIdx.x * blockDim.x + threadIdx.x; i < n4; i += stride) {
        uint4 u = ab[i];
        #pragma unroll
        for (int q = 0; q < 4; q++) {
            unsigned v = (q == 0) ? u.x : (q == 1) ? u.y : (q == 2) ? u.z : u.w;
            unsigned top = v >> 4;
            if (top == kA) atomicAdd(&h3[v & 15u], 1u);
            if (top == kB) atomicAdd(&h3[16 + (v & 15u)], 1u);
        }
    }
}

__global__ void k_thr_all(const float* ipw, const float* w1, const float* w2)
{
    int slot = blockIdx.x * blockDim.x + threadIdx.x;
    if (slot >= NSLOT) return;
    int n; slot_w(slot, ipw, w1, w2, n);
    float frac = 0.25f * (float)((n - 1) & 3);
    const unsigned* sel = d_selg + slot * 8;
    const unsigned* h3 = d_h3g + slot * 32;
    unsigned remA = sel[5]; unsigned lowA = 0;
    for (int j = 0; j < 16; j++) { unsigned c = h3[j]; if (remA < c) { lowA = j; break; } remA -= c; }
    unsigned remB = sel[7]; unsigned lowB = 0;
    for (int j = 0; j < 16; j++) { unsigned c = h3[16 + j]; if (remB < c) { lowB = j; break; } remB -= c; }
    float vA = __uint_as_float((sel[0] << 20) | (sel[4] << 4) | lowA);
    float vB = __uint_as_float((sel[2] << 20) | (sel[6] << 4) | lowB);
    d_thrg[slot] = vA + frac * (vB - vA);
}

__global__ void k_mask_all(const float* __restrict__ ipw, const float* __restrict__ w1,
                           const float* __restrict__ w2)
{
    int slot = blockIdx.y;
    int n;
    const float* w = slot_w(slot, ipw, w1, w2, n);
    const uint4*  av4 = (const uint4*)(d_abs_all + (size_t)slot * SLOT_STRIDE);
    const float4* wv4 = (const float4*)w;
    float4* ov4 = (float4*)(d_wp + (size_t)slot * SLOT_STRIDE);
    float thr = d_thrg[slot];
    int n4 = n >> 2;
    int stride = gridDim.x * blockDim.x;
    for (int i = blockIdx.x * blockDim.x + threadIdx.x; i < n4; i += stride) {
        uint4 a = av4[i];
        float4 wv = wv4[i];
        float4 o;
        o.x = (__uint_as_float(a.x) > thr) ? tf32r(wv.x) : 0.f;
        o.y = (__uint_as_float(a.y) > thr) ? tf32r(wv.y) : 0.f;
        o.z = (__uint_as_float(a.z) > thr) ? tf32r(wv.z) : 0.f;
        o.w = (__uint_as_float(a.w) > thr) ? tf32r(wv.w) : 0.f;
        ov4[i] = o;
    }
}

// ---------------- entry point ----------------
extern "C" void kernel_launch(void* const* d_in, const int* in_sizes, int n_in,
                              void* d_out, int out_size)
{
    const int*   src = (const int*)  d_in[0];
    const float* emb = (const float*)d_in[1];
    const float* pos = (const float*)d_in[2];
    const float* ipw = (const float*)d_in[3];
    const float* ipb = (const float*)d_in[4];
    const float* opw = (const float*)d_in[5];
    const float* opb = (const float*)d_in[6];
    const float* l1g = (const float*)d_in[7];
    const float* l1b = (const float*)d_in[8];
    const float* l2g = (const float*)d_in[9];
    const float* l2b = (const float*)d_in[10];
    const float* w1  = (const float*)d_in[11];
    const float* b1  = (const float*)d_in[12];
    const float* w2  = (const float*)d_in[13];
    const float* b2  = (const float*)d_in[14];
    const float* ow  = (const float*)d_in[15];
    const float* ob  = (const float*)d_in[16];
    const int V = in_sizes[16];
    float* out = (float*)d_out;

    float *px, *pxtf, *pqkv, *pao, *pff, *ptmp, *pwp, *pwr, *powr;
    cudaGetSymbolAddress((void**)&px,   d_x);
    cudaGetSymbolAddress((void**)&pxtf, d_xtf);
    cudaGetSymbolAddress((void**)&pqkv, d_qkv);
    cudaGetSymbolAddress((void**)&pao,  d_ao);
    cudaGetSymbolAddress((void**)&pff,  d_ff);
    cudaGetSymbolAddress((void**)&ptmp, d_tmp);
    cudaGetSymbolAddress((void**)&pwp,  d_wp);
    cudaGetSymbolAddress((void**)&pwr,  d_wr);
    cudaGetSymbolAddress((void**)&powr, d_owr);

    cudaFuncAttributes fa{};
    cudaFuncGetAttributes(&fa, k_tc<false,false,false,false>);
    const bool use_tc = fa.numRegs > 40;

    if (use_tc) {
        cudaFuncSetAttribute(k_tc<false,false,false,false>, cudaFuncAttributeMaxDynamicSharedMemorySize, TC_SMEM);
        cudaFuncSetAttribute(k_tc<false,false,true ,true >, cudaFuncAttributeMaxDynamicSharedMemorySize, TC_SMEM);
        cudaFuncSetAttribute(k_tc<true ,false,true ,true >, cudaFuncAttributeMaxDynamicSharedMemorySize, TC_SMEM);
        cudaFuncSetAttribute(k_tc<false,true ,false,true >, cudaFuncAttributeMaxDynamicSharedMemorySize, TC_SMEM);
    }
    cudaFuncSetAttribute(k_attn, cudaFuncAttributeMaxDynamicSharedMemorySize, AT_SMEM);

    // fused prep: embed + round static weights + zero histograms
    int prepN = MT * D;
    if (V * D > prepN) prepN = V * D;
    if (NSLOT * 2 * 65536 > prepN) prepN = NSLOT * 2 * 65536;
    k_prep<<<(prepN + 255) / 256, 256>>>(src, emb, pos, px, pxtf, opw, ow, V * D);

    k_etch_all <<<dim3(128, NSLOT), 256>>>(ipw, w1, w2);
    k_scan1_all<<<NSLOT, 256>>>(ipw, w1, w2);
    k_hist2_all<<<dim3(128, NSLOT), 256>>>(ipw, w1, w2);
    k_scan2_all<<<NSLOT, 256>>>();
    k_hist3_all<<<dim3(128, NSLOT), 256>>>(ipw, w1, w2);
    k_thr_all  <<<1, 32>>>(ipw, w1, w2);
    k_mask_all <<<dim3(512, NSLOT), 256>>>(ipw, w1, w2);

    for (int l = 0; l < L; l++) {
        const float* wi_l = pwp + (size_t)(0 * 6 + l) * SLOT_STRIDE;
        const float* w1_l = pwp + (size_t)(1 * 6 + l) * SLOT_STRIDE;
        const float* w2_l = pwp + (size_t)(2 * 6 + l) * SLOT_STRIDE;

        // qkv = x @ wi^T + b (dual-M, output tf32-rounded: feeds attention)
        if (use_tc)
            k_tc<false,false,true,true><<<dim3((3*D)/TC_BN, MT/256), 256, TC_SMEM>>>(
                3*D, D, pxtf, D, wi_l, D, pqkv, 3*D, ipb + (size_t)l * 3 * D);
        else
            k_mma<128,128,2,2,true,false,false,true><<<dim3((3*D)/128, MT/128, 1), 128>>>(
                MT, 3*D, D, pxtf, D, 0, 0, wi_l, D, 0, 0, pqkv, 3*D, 0, 0, 1,
                ipb + (size_t)l * 3 * D, 1.f);

        // fused flash attention
        k_attn<<<dim3(4, BH), 256, AT_SMEM>>>(pqkv, pao);

        // out projection (single-M: keeps grid at 128 CTAs)
        if (use_tc)
            k_tc<false,false,false,false><<<dim3(D/TC_BN, MT/128), 256, TC_SMEM>>>(
                D, D, pao, D, pwr + (size_t)l*D*D, D, ptmp, D, opb + (size_t)l*D);
        else
            k_mma<128,128,2,2,true,false,false,false><<<dim3(D/128, MT/128, 1), 128>>>(
                MT, D, D, pao, D, 0, 0, pwr + (size_t)l*D*D, D, 0, 0,
                ptmp, D, 0, 0, 1, opb + (size_t)l*D, 1.f);
        k_add_ln<<<MT, 256>>>(px, ptmp, l1g + (size_t)l*D, l1b + (size_t)l*D, px, pxtf);

        // feed-forward: ff1 dual-M, ff2 single-M
        if (use_tc) {
            k_tc<true,false,true,true><<<dim3(F/TC_BN, MT/256), 256, TC_SMEM>>>(
                F, D, pxtf, D, w1_l, D, pff, F, b1 + (size_t)l*F);
            k_tc<false,false,false,false><<<dim3(D/TC_BN, MT/128), 256, TC_SMEM>>>(
                D, F, pff, F, w2_l, F, ptmp, D, b2 + (size_t)l*D);
        } else {
            k_mma<128,128,2,2,true,true,false,true><<<dim3(F/128, MT/128, 1), 128>>>(
                MT, F, D, pxtf, D, 0, 0, w1_l, D, 0, 0, pff, F, 0, 0, 1,
                b1 + (size_t)l*F, 1.f);
            k_mma<128,128,2,2,true,false,false,false><<<dim3(D/128, MT/128, 1), 128>>>(
                MT, D, F, pff, F, 0, 0, w2_l, F, 0, 0, ptmp, D, 0, 0, 1,
                b2 + (size_t)l*D, 1.f);
        }
        k_add_ln<<<MT, 256>>>(px, ptmp, l2g + (size_t)l*D, l2b + (size_t)l*D, px, pxtf);
    }

    // logits (dual-M, N guarded)
    if (use_tc)
        k_tc<false,true,false,true><<<dim3((V + TC_BN - 1)/TC_BN, MT/256), 256, TC_SMEM>>>(
            V, D, pxtf, D, powr, D, out, V, ob);
    else
        k_mma<128,128,2,2,true,false,true,false><<<dim3((V + 127) / 128, MT / 128, 1), 128>>>(
            MT, V, D, pxtf, D, 0, 0, powr, D, 0, 0, out, V, 0, 0, 1, ob, 1.f);
}

// round 12
// speedup vs baseline: 2.6871x; 1.2685x over previous
#include <cuda_runtime.h>
#include <cstdint>
#include <math.h>

// ---------------- constants ----------------
#define PI_F      3.14159265358979323846f
#define PI2_F     9.86960440108935861883f
#define THIRD_F   2.09439510239319549231f
#define DEVPI_F   0.003183098861837907f
#define SQRTD_F   22.62741699796952f

constexpr int S  = 512;
constexpr int D  = 512;
constexpr int H  = 8;
constexpr int DH = 64;
constexpr int L  = 6;
constexpr int F  = 2048;
constexpr int BB = 16;
constexpr int MT = BB * S;   // 8192 tokens
constexpr int BH = BB * H;   // 128
constexpr int NSLOT = 18;
constexpr size_t SLOT_STRIDE = 1048576;
constexpr int VMAX = 10240;

// Feature gate: tcgen05 only exists on arch-specific (sm_103a) / family (sm_103f) targets.
#if !defined(__CUDA_ARCH__) || defined(__CUDA_ARCH_FEAT_SM103_ALL) || defined(__CUDA_ARCH_SPECIFIC__) || defined(__CUDA_ARCH_FAMILY_SPECIFIC__)
#define TC_AVAIL 1
#else
#define TC_AVAIL 0
#endif

// ---------------- device scratch ----------------
__device__ __align__(128) float d_x   [MT * D];
__device__ __align__(128) float d_xtf [MT * D];
__device__ __align__(128) float d_qkv [MT * 3 * D];
__device__ __align__(128) float d_ao  [MT * D];
__device__ __align__(128) float d_ff  [MT * F];
__device__ __align__(128) float d_tmp [MT * D];
__device__ __align__(128) float d_wp  [NSLOT * SLOT_STRIDE];
__device__ __align__(128) float d_wr  [L * D * D];
__device__ __align__(128) float d_owr [VMAX * D];
__device__ __align__(128) float d_abs_all[NSLOT * SLOT_STRIDE];
__device__ unsigned d_h1g[NSLOT * 4096];
__device__ unsigned d_h2g[NSLOT * 2048];   // level2: 2 x 1024 bins (bits [10,20))
__device__ unsigned d_h3g[NSLOT * 2048];   // level3: 2 x 1024 bins (bits [0,10))
__device__ unsigned d_selg[NSLOT * 8];
__device__ float d_thrg[NSLOT];

// ---------------- helpers ----------------
__device__ __forceinline__ float tf32r(float f) {
    uint32_t u;
    asm("cvt.rna.tf32.f32 %0, %1;" : "=r"(u) : "f"(f));
    return __uint_as_float(u);
}

__device__ __forceinline__ void mma_tf32(float c[4],
    uint32_t a0, uint32_t a1, uint32_t a2, uint32_t a3,
    uint32_t b0, uint32_t b1)
{
    asm volatile(
        "mma.sync.aligned.m16n8k8.row.col.f32.tf32.tf32.f32 "
        "{%0,%1,%2,%3}, {%4,%5,%6,%7}, {%8,%9}, {%0,%1,%2,%3};"
        : "+f"(c[0]), "+f"(c[1]), "+f"(c[2]), "+f"(c[3])
        : "r"(a0), "r"(a1), "r"(a2), "r"(a3), "r"(b0), "r"(b1));
}

__device__ __forceinline__ void cp16(void* d, const void* s) {
    uint32_t a = (uint32_t)__cvta_generic_to_shared(d);
    asm volatile("cp.async.cg.shared.global [%0], [%1], 16;" :: "r"(a), "l"(s));
}
__device__ __forceinline__ void cp16p(void* d, const void* s, bool p) {
    uint32_t a = (uint32_t)__cvta_generic_to_shared(d);
    int sz = p ? 16 : 0;
    asm volatile("cp.async.cg.shared.global [%0], [%1], 16, %2;" :: "r"(a), "l"(s), "r"(sz));
}
#define CP_COMMIT() asm volatile("cp.async.commit_group;")
#define CP_WAIT0()  asm volatile("cp.async.wait_group 0;")
#define CP_WAIT1()  asm volatile("cp.async.wait_group 1;")
#define CP_WAIT2()  asm volatile("cp.async.wait_group 2;")

// ================= tcgen05 tf32 GEMM (guarded) =================
constexpr int TC_BN = 256;
constexpr int TC_BK = 32;
constexpr int TC_SMEM = 197632;

#if TC_AVAIL
__device__ __forceinline__ uint32_t elect1() {
    uint32_t pred;
    asm volatile("{\n\t.reg .pred p;\n\telect.sync _|p, 0xFFFFFFFF;\n\t"
                 "selp.b32 %0, 1, 0, p;\n\t}" : "=r"(pred));
    return pred;
}
#define MBAR_INIT(addr, cnt) \
    asm volatile("mbarrier.init.shared.b64 [%0], %1;" :: "r"(addr), "r"(cnt) : "memory")
#define MBAR_WAIT(addr, par) do { \
    asm volatile("{\n\t.reg .pred P1;\n\tWL%=:\n\t" \
        "mbarrier.try_wait.parity.acquire.cta.shared::cta.b64 P1, [%0], %1, 0x989680;\n\t" \
        "@P1 bra.uni WD%=;\n\tbra.uni WL%=;\n\tWD%=:\n\t}" \
        :: "r"(addr), "r"(par) : "memory"); \
} while (0)
#define TC_ALLOC(sm, n)   asm volatile("tcgen05.alloc.cta_group::1.sync.aligned.shared::cta.b32 [%0], %1;" :: "r"(sm), "r"(n) : "memory")
#define TC_DEALLOC(t, n)  asm volatile("tcgen05.dealloc.cta_group::1.sync.aligned.b32 %0, %1;" :: "r"(t), "r"(n))
#define TC_COMMIT(mb)     asm volatile("tcgen05.commit.cta_group::1.mbarrier::arrive::one.shared::cluster.b64 [%0];" :: "r"(mb) : "memory")
#define TC_FENCE_AFTER()  asm volatile("tcgen05.fence::after_thread_sync;" ::: "memory")
#define TC_FENCE_BEFORE() asm volatile("tcgen05.fence::before_thread_sync;" ::: "memory")
#define TC_WAIT_LD()      asm volatile("tcgen05.wait::ld.sync.aligned;" ::: "memory")
#define FENCE_PROXY()     asm volatile("fence.proxy.async.shared::cta;" ::: "memory")

#define TC_LD_X32(r, addr) \
    asm volatile("tcgen05.ld.sync.aligned.32x32b.x32.b32 " \
        "{%0, %1, %2, %3, %4, %5, %6, %7, %8, %9, %10, %11, %12, %13, %14, %15, " \
        " %16, %17, %18, %19, %20, %21, %22, %23, %24, %25, %26, %27, %28, %29, %30, %31}, [%32];" \
        : "=r"((r)[0]),  "=r"((r)[1]),  "=r"((r)[2]),  "=r"((r)[3]), \
          "=r"((r)[4]),  "=r"((r)[5]),  "=r"((r)[6]),  "=r"((r)[7]), \
          "=r"((r)[8]),  "=r"((r)[9]),  "=r"((r)[10]), "=r"((r)[11]), \
          "=r"((r)[12]), "=r"((r)[13]), "=r"((r)[14]), "=r"((r)[15]), \
          "=r"((r)[16]), "=r"((r)[17]), "=r"((r)[18]), "=r"((r)[19]), \
          "=r"((r)[20]), "=r"((r)[21]), "=r"((r)[22]), "=r"((r)[23]), \
          "=r"((r)[24]), "=r"((r)[25]), "=r"((r)[26]), "=r"((r)[27]), \
          "=r"((r)[28]), "=r"((r)[29]), "=r"((r)[30]), "=r"((r)[31]) \
        : "r"(addr))

static constexpr uint64_t SMEM_DESC_BASE =
    (uint64_t(2) << 61) | (uint64_t(1) << 46) | (uint64_t(64) << 32) | (uint64_t(1) << 16);
#define MK_DESC(a) (SMEM_DESC_BASE | ((uint64_t)((a) >> 4) & 0x3FFF))

__device__ __forceinline__ void mma_tc(uint32_t d, uint64_t ad, uint64_t bd,
                                       uint32_t idesc, bool en)
{
    uint32_t e = en ? 1 : 0;
    asm volatile(
        "{\n\t.reg .pred p;\n\tsetp.ne.u32 p, %4, 0;\n\t"
        "tcgen05.mma.cta_group::1.kind::tf32 [%0], %1, %2, %3, {%5,%5,%5,%5}, p;\n\t}"
        :: "r"(d), "l"(ad), "l"(bd), "r"(idesc), "r"(e), "r"(0u) : "memory");
}
#endif  // TC_AVAIL

constexpr uint32_t TC_IDESC =
    (1u << 4) | (2u << 7) | (2u << 10) | ((TC_BN / 8) << 17) | ((128 / 16) << 24);

// C[m,n] = sum_k A[m,k]*B[n,k] + bias[n]; operands pre-rounded to tf32 values.
// M2=false: grid (N/256, M/128).  M2=true: grid (N/256, M/256), B loaded once per 256 M-rows.
template<bool RELU, bool GN, bool TFO, bool M2>
__global__ void __launch_bounds__(256, 1)
k_tc(int N, int K,
     const float* __restrict__ A, int lda,
     const float* __restrict__ B, int ldb,
     float* __restrict__ C, int ldc,
     const float* __restrict__ bias)
{
#if TC_AVAIL
    constexpr int NS    = M2 ? 3 : 4;
    constexpr int AROWS = M2 ? 256 : 128;
    constexpr int ASZ   = AROWS * 128;
    constexpr int BSZ   = TC_BN * 128;
    constexpr int TCOLS = M2 ? 512 : 256;

    extern __shared__ char smem[];
    uint32_t sbase = (uint32_t)__cvta_generic_to_shared(smem);
    const int tid = threadIdx.x, lane = tid & 31, warp = tid >> 5;
    const int m0 = blockIdx.y * AROWS, n0 = blockIdx.x * TC_BN;

    if (warp == 0) TC_ALLOC(sbase, TCOLS);
    if (tid == 0) {
        #pragma unroll
        for (int s = 0; s < NS; s++) MBAR_INIT(sbase + 16 + 8 * s, 1);
    }
    __syncthreads();
    uint32_t tmem;
    asm volatile("ld.shared.b32 %0, [%1];" : "=r"(tmem) : "r"(sbase));

    const uint32_t aoff = 1024, boff = 1024 + NS * ASZ;

    auto loadStage = [&](int st, int k0) {
        char* pa = smem + aoff + st * ASZ;
        char* pb = smem + boff + st * BSZ;
        #pragma unroll
        for (int r = 0; r < AROWS / 32; r++) {
            int i = tid + r * 256;
            int m = i >> 3, c = i & 7;
            int cs = c ^ (m & 7);     // SW128
            cp16(pa + m * 128 + cs * 16, &A[(size_t)(m0 + m) * lda + k0 + c * 4]);
        }
        #pragma unroll
        for (int r = 0; r < 8; r++) {
            int i = tid + r * 256;
            int n = i >> 3, c = i & 7;
            int cs = c ^ (n & 7);
            int gn = n0 + n;
            if (GN) {
                bool ok = gn < N;
                cp16p(pb + n * 128 + cs * 16,
                      ok ? &B[(size_t)gn * ldb + k0 + c * 4] : (const float*)B, ok);
            } else {
                cp16(pb + n * 128 + cs * 16, &B[(size_t)gn * ldb + k0 + c * 4]);
            }
        }
    };

    const int nk = K / TC_BK;

    #pragma unroll
    for (int s = 0; s < NS - 1; s++) { loadStage(s, s * TC_BK); CP_COMMIT(); }

    for (int kt = 0; kt < nk; kt++) {
        int cur = kt % NS;
        if (M2) { CP_WAIT1(); } else { CP_WAIT2(); }
        __syncthreads();
        FENCE_PROXY();
        if (warp == 0 && elect1()) {
            uint64_t ad = MK_DESC(sbase + aoff + cur * ASZ);
            uint64_t bd = MK_DESC(sbase + boff + cur * BSZ);
            #pragma unroll
            for (int j = 0; j < 4; j++) {
                bool en = (kt > 0) || (j > 0);
                mma_tc(tmem, ad + j * 2, bd + j * 2, TC_IDESC, en);
                if (M2) {
                    uint64_t ad2 = MK_DESC(sbase + aoff + cur * ASZ + 128 * 128);
                    mma_tc(tmem + 256, ad2 + j * 2, bd + j * 2, TC_IDESC, en);
                }
            }
            TC_COMMIT(sbase + 16 + 8 * cur);
        }
        if (kt >= 1) MBAR_WAIT(sbase + 16 + 8 * ((kt - 1) % NS), ((kt - 1) / NS) & 1);
        int kn = kt + NS - 1;
        if (kn < nk) loadStage(kn % NS, kn * TC_BK);
        CP_COMMIT();
    }
    MBAR_WAIT(sbase + 16 + 8 * ((nk - 1) % NS), ((nk - 1) / NS) & 1);

    __syncthreads();
    TC_FENCE_AFTER();

    float* myep = (float*)(smem + 1024) + warp * (32 * 33);
    if (M2) {
        int half = warp >> 2;
        uint32_t tbase = tmem + half * 256;
        int rbase = m0 + half * 128 + (warp & 3) * 32;
        #pragma unroll
        for (int ch = 0; ch < 8; ch++) {
            int c0 = ch * 32;
            uint32_t regs[32];
            TC_LD_X32(regs, tbase + c0);
            TC_WAIT_LD();
            #pragma unroll
            for (int c = 0; c < 32; c++) {
                float v = __uint_as_float(regs[c]);
                if (!GN || (n0 + c0 + c) < N) {
                    v += bias[n0 + c0 + c];
                    if (RELU) v = fmaxf(v, 0.f);
                    if (TFO)  v = tf32r(v);
                }
                myep[lane * 33 + c] = v;
            }
            __syncwarp();
            int col = n0 + c0 + lane;
            #pragma unroll
            for (int i = 0; i < 32; i++) {
                if (!GN || col < N)
                    C[(size_t)(rbase + i) * ldc + col] = myep[i * 33 + lane];
            }
            __syncwarp();
        }
    } else {
        int rbase = m0 + (warp & 3) * 32;
        int cbase = (warp >> 2) * 128;
        #pragma unroll
        for (int ch = 0; ch < 4; ch++) {
            int c0 = cbase + ch * 32;
            uint32_t regs[32];
            TC_LD_X32(regs, tmem + c0);
            TC_WAIT_LD();
            #pragma unroll
            for (int c = 0; c < 32; c++) {
                float v = __uint_as_float(regs[c]);
                if (!GN || (n0 + c0 + c) < N) {
                    v += bias[n0 + c0 + c];
                    if (RELU) v = fmaxf(v, 0.f);
                    if (TFO)  v = tf32r(v);
                }
                myep[lane * 33 + c] = v;
            }
            __syncwarp();
            int col = n0 + c0 + lane;
            #pragma unroll
            for (int i = 0; i < 32; i++) {
                if (!GN || col < N)
                    C[(size_t)(rbase + i) * ldc + col] = myep[i * 33 + lane];
            }
            __syncwarp();
        }
    }

    __syncthreads();
    if (warp == 0) { TC_FENCE_BEFORE(); TC_DEALLOC(tmem, TCOLS); }
#endif  // TC_AVAIL
}

// ================= fused flash attention (mma.sync tf32, pipelined KV) =================
constexpr int AT_SMEM = 174080;

__global__ void __launch_bounds__(256, 1)
k_attn(const float* __restrict__ qkv, float* __restrict__ ao)
{
    extern __shared__ float sm_[];
    float* Qs   = sm_;               // [128][68]
    float* Ks   = Qs + 128 * 68;
    float* Vs   = Ks + 128 * 68;
    float* Ps   = Vs + 128 * 68;     // [128][132]
    float* rmx  = Ps + 128 * 132;
    float* rsm  = rmx + 256;

    const int tid = threadIdx.x, lane = tid & 31, warp = tid >> 5;
    const int wm = warp >> 1, wn = warp & 1;
    const int g = lane >> 2, t4 = lane & 3;
    const int bh = blockIdx.y, b = bh >> 3, h = bh & 7;
    const int qrow0 = b * 512 + blockIdx.x * 128;
    const int kvbase = b * 512;

    auto loadK = [&](int kc) {
        int kvrow0 = kvbase + kc * 128;
        #pragma unroll
        for (int r = 0; r < 8; r++) {
            int i = tid + r * 256;
            int row = i >> 4, c = (i & 15) << 2;
            cp16(&Ks[row * 68 + c], &qkv[(size_t)(kvrow0 + row) * 1536 + 512 + h * 64 + c]);
        }
    };
    auto loadV = [&](int kc) {
        int kvrow0 = kvbase + kc * 128;
        #pragma unroll
        for (int r = 0; r < 8; r++) {
            int i = tid + r * 256;
            int row = i >> 4, c = (i & 15) << 2;
            cp16(&Vs[row * 68 + c], &qkv[(size_t)(kvrow0 + row) * 1536 + 1024 + h * 64 + c]);
        }
    };

    loadK(0); CP_COMMIT();
    loadV(0); CP_COMMIT();

    #pragma unroll
    for (int r = 0; r < 8; r++) {
        int i = tid + r * 256;
        int row = i >> 4, c = (i & 15) << 2;
        float4 v = *(const float4*)&qkv[(size_t)(qrow0 + row) * 1536 + h * 64 + c];
        Qs[row * 68 + c]     = v.x * 0.125f;
        Qs[row * 68 + c + 1] = v.y * 0.125f;
        Qs[row * 68 + c + 2] = v.z * 0.125f;
        Qs[row * 68 + c + 3] = v.w * 0.125f;
    }

    float m_i[2][2], l_i[2][2];
    float oa[2][4][4];
    #pragma unroll
    for (int i = 0; i < 2; i++)
        #pragma unroll
        for (int hf = 0; hf < 2; hf++) { m_i[i][hf] = -1e30f; l_i[i][hf] = 0.f; }
    #pragma unroll
    for (int i = 0; i < 2; i++)
        #pragma unroll
        for (int j = 0; j < 4; j++)
            #pragma unroll
            for (int q = 0; q < 4; q++) oa[i][j][q] = 0.f;

    for (int kc = 0; kc < 4; kc++) {
        CP_WAIT1();
        __syncthreads();

        float s[2][8][4];
        #pragma unroll
        for (int i = 0; i < 2; i++)
            #pragma unroll
            for (int j = 0; j < 8; j++)
                #pragma unroll
                for (int q = 0; q < 4; q++) s[i][j][q] = 0.f;

        #pragma unroll
        for (int ks = 0; ks < 8; ks++) {
            uint32_t af[2][4], bf[8][2];
            #pragma unroll
            for (int i = 0; i < 2; i++) {
                int row = wm * 32 + i * 16 + g;
                af[i][0] = __float_as_uint(Qs[row * 68 + ks * 8 + t4]);
                af[i][1] = __float_as_uint(Qs[(row + 8) * 68 + ks * 8 + t4]);
                af[i][2] = __float_as_uint(Qs[row * 68 + ks * 8 + t4 + 4]);
                af[i][3] = __float_as_uint(Qs[(row + 8) * 68 + ks * 8 + t4 + 4]);
            }
            #pragma unroll
            for (int j = 0; j < 8; j++) {
                int nc = wn * 64 + j * 8 + g;
                bf[j][0] = __float_as_uint(Ks[nc * 68 + ks * 8 + t4]);
                bf[j][1] = __float_as_uint(Ks[nc * 68 + ks * 8 + t4 + 4]);
            }
            #pragma unroll
            for (int i = 0; i < 2; i++)
                #pragma unroll
                for (int j = 0; j < 8; j++)
                    mma_tf32(s[i][j], af[i][0], af[i][1], af[i][2], af[i][3],
                             bf[j][0], bf[j][1]);
        }

        float mn[2][2];
        #pragma unroll
        for (int i = 0; i < 2; i++)
            #pragma unroll
            for (int hf = 0; hf < 2; hf++) {
                float v = -1e30f;
                #pragma unroll
                for (int j = 0; j < 8; j++)
                    v = fmaxf(v, fmaxf(s[i][j][2 * hf], s[i][j][2 * hf + 1]));
                v = fmaxf(v, __shfl_xor_sync(0xFFFFFFFF, v, 1));
                v = fmaxf(v, __shfl_xor_sync(0xFFFFFFFF, v, 2));
                mn[i][hf] = v;
            }
        if (t4 == 0) {
            #pragma unroll
            for (int i = 0; i < 2; i++)
                #pragma unroll
                for (int hf = 0; hf < 2; hf++)
                    rmx[(wm * 32 + i * 16 + g + 8 * hf) * 2 + wn] = mn[i][hf];
        }
        __syncthreads();

        if (kc < 3) loadK(kc + 1);
        CP_COMMIT();

        float sc[2][2];
        #pragma unroll
        for (int i = 0; i < 2; i++)
            #pragma unroll
            for (int hf = 0; hf < 2; hf++) {
                int row = wm * 32 + i * 16 + g + 8 * hf;
                float cm = fmaxf(rmx[row * 2], rmx[row * 2 + 1]);
                float nm = fmaxf(m_i[i][hf], cm);
                sc[i][hf] = __expf(m_i[i][hf] - nm);
                mn[i][hf] = nm;
            }
        #pragma unroll
        for (int i = 0; i < 2; i++)
            #pragma unroll
            for (int j = 0; j < 4; j++) {
                oa[i][j][0] *= sc[i][0]; oa[i][j][1] *= sc[i][0];
                oa[i][j][2] *= sc[i][1]; oa[i][j][3] *= sc[i][1];
            }
        float smv[2][2] = {{0.f, 0.f}, {0.f, 0.f}};
        #pragma unroll
        for (int i = 0; i < 2; i++) {
            int row = wm * 32 + i * 16 + g;
            #pragma unroll
            for (int j = 0; j < 8; j++) {
                int col = wn * 64 + j * 8 + 2 * t4;
                float p0 = __expf(s[i][j][0] - mn[i][0]);
                float p1 = __expf(s[i][j][1] - mn[i][0]);
                float p2 = __expf(s[i][j][2] - mn[i][1]);
                float p3 = __expf(s[i][j][3] - mn[i][1]);
                smv[i][0] += p0 + p1;
                smv[i][1] += p2 + p3;
                Ps[row * 132 + col]           = tf32r(p0);
                Ps[row * 132 + col + 1]       = tf32r(p1);
                Ps[(row + 8) * 132 + col]     = tf32r(p2);
                Ps[(row + 8) * 132 + col + 1] = tf32r(p3);
            }
        }
        #pragma unroll
        for (int i = 0; i < 2; i++)
            #pragma unroll
            for (int hf = 0; hf < 2; hf++) {
                float v = smv[i][hf];
                v += __shfl_xor_sync(0xFFFFFFFF, v, 1);
                v += __shfl_xor_sync(0xFFFFFFFF, v, 2);
                smv[i][hf] = v;
            }
        if (t4 == 0) {
            #pragma unroll
            for (int i = 0; i < 2; i++)
                #pragma unroll
                for (int hf = 0; hf < 2; hf++)
                    rsm[(wm * 32 + i * 16 + g + 8 * hf) * 2 + wn] = smv[i][hf];
        }
        CP_WAIT1();
        __syncthreads();
        #pragma unroll
        for (int i = 0; i < 2; i++)
            #pragma unroll
            for (int hf = 0; hf < 2; hf++) {
                int row = wm * 32 + i * 16 + g + 8 * hf;
                l_i[i][hf] = l_i[i][hf] * sc[i][hf] + rsm[row * 2] + rsm[row * 2 + 1];
                m_i[i][hf] = mn[i][hf];
            }

        #pragma unroll
        for (int ks = 0; ks < 16; ks++) {
            uint32_t af[2][4], bf[4][2];
            #pragma unroll
            for (int i = 0; i < 2; i++) {
                int row = wm * 32 + i * 16 + g;
                af[i][0] = __float_as_uint(Ps[row * 132 + ks * 8 + t4]);
                af[i][1] = __float_as_uint(Ps[(row + 8) * 132 + ks * 8 + t4]);
                af[i][2] = __float_as_uint(Ps[row * 132 + ks * 8 + t4 + 4]);
                af[i][3] = __float_as_uint(Ps[(row + 8) * 132 + ks * 8 + t4 + 4]);
            }
            #pragma unroll
            for (int j = 0; j < 4; j++) {
                int nc = wn * 32 + j * 8 + g;
                bf[j][0] = __float_as_uint(Vs[(ks * 8 + t4) * 68 + nc]);
                bf[j][1] = __float_as_uint(Vs[(ks * 8 + t4 + 4) * 68 + nc]);
            }
            #pragma unroll
            for (int i = 0; i < 2; i++)
                #pragma unroll
                for (int j = 0; j < 4; j++)
                    mma_tf32(oa[i][j], af[i][0], af[i][1], af[i][2], af[i][3],
                             bf[j][0], bf[j][1]);
        }

        __syncthreads();
        if (kc < 3) loadV(kc + 1);
        CP_COMMIT();
    }

    #pragma unroll
    for (int i = 0; i < 2; i++) {
        float r0 = 1.f / l_i[i][0], r1 = 1.f / l_i[i][1];
        int row = qrow0 + wm * 32 + i * 16 + g;
        #pragma unroll
        for (int j = 0; j < 4; j++) {
            int col = h * 64 + wn * 32 + j * 8 + 2 * t4;
            *(float2*)&ao[(size_t)row * 512 + col] =
                make_float2(tf32r(oa[i][j][0] * r0), tf32r(oa[i][j][1] * r0));
            *(float2*)&ao[(size_t)(row + 8) * 512 + col] =
                make_float2(tf32r(oa[i][j][2] * r1), tf32r(oa[i][j][3] * r1));
        }
    }
}

// ================= mma.sync GEMM (fallback path) =================
template<int BM,int BN,int WARPS_M,int WARPS_N,bool TB,bool RELU,bool GN,bool TFO>
__global__ void __launch_bounds__(WARPS_M*WARPS_N*32)
k_mma(int M, int N, int K,
      const float* __restrict__ Ag, int lda, long long sA1, long long sA2,
      const float* __restrict__ Bg, int ldb, long long sB1, long long sB2,
      float* __restrict__ Cg, int ldc, long long sC1, long long sC2,
      int zdiv, const float* __restrict__ bias, float alpha)
{
    constexpr int BK = 16;
    constexpr int NT = WARPS_M * WARPS_N * 32;
    constexpr int WM = BM / WARPS_M, WN = BN / WARPS_N;
    constexpr int MI = WM / 16, NI = WN / 8;
    constexpr int AST = BK + 4;
    constexpr int BROWS = TB ? BN : BK;
    constexpr int BCOLS = TB ? (BK + 4) : (BN + 8);

    __shared__ __align__(16) float As[2][BM][AST];
    __shared__ __align__(16) float Bs[2][BROWS][BCOLS];

    const int bz = blockIdx.z;
    const int z1 = bz / zdiv, z2 = bz - z1 * zdiv;
    const float* A  = Ag + z1 * sA1 + z2 * sA2;
    const float* Bp = Bg + z1 * sB1 + z2 * sB2;
    float* C        = Cg + z1 * sC1 + z2 * sC2;

    const int m0 = blockIdx.y * BM, n0 = blockIdx.x * BN;
    const int tid  = threadIdx.x;
    const int lane = tid & 31, warp = tid >> 5;
    const int wm = warp / WARPS_N, wn = warp - wm * WARPS_N;
    const int g = lane >> 2, t4 = lane & 3;

    float acc[MI][NI][4];
    #pragma unroll
    for (int i = 0; i < MI; i++)
        #pragma unroll
        for (int j = 0; j < NI; j++)
            #pragma unroll
            for (int q = 0; q < 4; q++) acc[i][j][q] = 0.f;

    auto loadTiles = [&](int st, int k0) {
        #pragma unroll
        for (int r = 0; r < (BM * (BK/4)) / NT; r++) {
            int i = tid + r * NT;
            int m = i >> 2;
            int c = (i & 3) << 2;
            cp16(&As[st][m][c], &A[(size_t)(m0 + m) * lda + k0 + c]);
        }
        if (TB) {
            #pragma unroll
            for (int r = 0; r < (BN * (BK/4)) / NT; r++) {
                int i = tid + r * NT;
                int n = i >> 2;
                int c = (i & 3) << 2;
                int gn = n0 + n;
                if (GN) {
                    bool ok = gn < N;
                    cp16p(&Bs[st][n][c], ok ? &Bp[(size_t)gn * ldb + k0 + c] : (const float*)Bp, ok);
                } else {
                    cp16(&Bs[st][n][c], &Bp[(size_t)gn * ldb + k0 + c]);
                }
            }
        } else {
            #pragma unroll
            for (int r = 0; r < (BK * (BN/4)) / NT; r++) {
                int i = tid + r * NT;
                int kk = i / (BN/4);
                int c  = (i - kk * (BN/4)) << 2;
                cp16(&Bs[st][kk][c], &Bp[(size_t)(k0 + kk) * ldb + n0 + c]);
            }
        }
    };

    const int nk = K / BK;
    loadTiles(0, 0);
    CP_COMMIT();

    for (int kt = 0; kt < nk; kt++) {
        int cur = kt & 1;
        if (kt + 1 < nk) loadTiles(cur ^ 1, (kt + 1) * BK);
        CP_COMMIT();
        CP_WAIT1();
        __syncthreads();

        #pragma unroll
        for (int ks = 0; ks < 2; ks++) {
            uint32_t af[MI][4], bf[NI][2];
            #pragma unroll
            for (int i = 0; i < MI; i++) {
                int mr = wm * WM + i * 16 + g;
                af[i][0] = __float_as_uint(As[cur][mr    ][ks*8 + t4    ]);
                af[i][1] = __float_as_uint(As[cur][mr + 8][ks*8 + t4    ]);
                af[i][2] = __float_as_uint(As[cur][mr    ][ks*8 + t4 + 4]);
                af[i][3] = __float_as_uint(As[cur][mr + 8][ks*8 + t4 + 4]);
            }
            #pragma unroll
            for (int j = 0; j < NI; j++) {
                int nc = wn * WN + j * 8 + g;
                if (TB) {
                    bf[j][0] = __float_as_uint(Bs[cur][nc][ks*8 + t4    ]);
                    bf[j][1] = __float_as_uint(Bs[cur][nc][ks*8 + t4 + 4]);
                } else {
                    bf[j][0] = __float_as_uint(Bs[cur][ks*8 + t4    ][nc]);
                    bf[j][1] = __float_as_uint(Bs[cur][ks*8 + t4 + 4][nc]);
                }
            }
            #pragma unroll
            for (int i = 0; i < MI; i++)
                #pragma unroll
                for (int j = 0; j < NI; j++)
                    mma_tf32(acc[i][j], af[i][0], af[i][1], af[i][2], af[i][3],
                             bf[j][0], bf[j][1]);
        }
        __syncthreads();
    }

    #pragma unroll
    for (int i = 0; i < MI; i++) {
        int r0 = m0 + wm * WM + i * 16 + g;
        #pragma unroll
        for (int j = 0; j < NI; j++) {
            int col = n0 + wn * WN + j * 8 + t4 * 2;
            if (GN && col >= N) continue;
            float b0v = 0.f, b1v = 0.f;
            if (bias) { b0v = bias[col]; b1v = bias[col + 1]; }
            float v0 = acc[i][j][0] * alpha + b0v;
            float v1 = acc[i][j][1] * alpha + b1v;
            float v2 = acc[i][j][2] * alpha + b0v;
            float v3 = acc[i][j][3] * alpha + b1v;
            if (RELU) {
                v0 = fmaxf(v0, 0.f); v1 = fmaxf(v1, 0.f);
                v2 = fmaxf(v2, 0.f); v3 = fmaxf(v3, 0.f);
            }
            if (TFO) {
                v0 = tf32r(v0); v1 = tf32r(v1); v2 = tf32r(v2); v3 = tf32r(v3);
            }
            *reinterpret_cast<float2*>(&C[(size_t)r0 * ldc + col])       = make_float2(v0, v1);
            *reinterpret_cast<float2*>(&C[(size_t)(r0 + 8) * ldc + col]) = make_float2(v2, v3);
        }
    }
}

// ---------------- residual add + layernorm ----------------
__global__ void k_add_ln(const float* __restrict__ xin, const float* __restrict__ res,
                         const float* __restrict__ g, const float* __restrict__ b,
                         float* __restrict__ xout, float* __restrict__ xtf)
{
    int row = blockIdx.x, t = threadIdx.x;
    long long base = (long long)row * D;
    float v0 = xin[base + t]       + res[base + t];
    float v1 = xin[base + t + 256] + res[base + t + 256];
    __shared__ float red[256];
    red[t] = v0 + v1; __syncthreads();
    for (int o = 128; o > 0; o >>= 1) { if (t < o) red[t] += red[t+o]; __syncthreads(); }
    float mean = red[0] * (1.f / D); __syncthreads();
    red[t] = v0*v0 + v1*v1; __syncthreads();
    for (int o = 128; o > 0; o >>= 1) { if (t < o) red[t] += red[t+o]; __syncthreads(); }
    float var = red[0] * (1.f / D) - mean*mean;
    float rs = rsqrtf(var + 1e-5f);
    float o0 = (v0 - mean) * rs * g[t]       + b[t];
    float o1 = (v1 - mean) * rs * g[t + 256] + b[t + 256];
    xout[base + t]       = o0;
    xout[base + t + 256] = o1;
    xtf [base + t]       = tf32r(o0);
    xtf [base + t + 256] = tf32r(o1);
}

// ---------------- fused prep: embedding + weight rounding + histogram zero ----------------
__global__ void k_prep(const int* __restrict__ src, const float* __restrict__ emb,
                       const float* __restrict__ pos, float* __restrict__ x,
                       float* __restrict__ xtf, const float* __restrict__ opw,
                       const float* __restrict__ ow, int nOw)
{
    int idx = blockIdx.x * blockDim.x + threadIdx.x;
    if (idx < MT * D) {
        int t = idx >> 9, d = idx & 511;
        float v = emb[(long long)src[t] * D + d] * SQRTD_F + pos[(t & 511) * D + d];
        x[idx]   = v;
        xtf[idx] = tf32r(v);
    }
    if (idx < L * D * D) d_wr[idx] = tf32r(opw[idx]);
    if (idx < nOw)       d_owr[idx] = tf32r(ow[idx]);
    if (idx < NSLOT * 2048) { d_h2g[idx] = 0; d_h3g[idx] = 0; }
    if (idx < NSLOT * 4096) d_h1g[idx] = 0;
}

// ---------------- batched prune pipeline ----------------
__device__ __forceinline__ const float* slot_w(int slot, const float* ipw,
                                               const float* w1, const float* w2, int& n)
{
    int t = slot / 6, l = slot - t * 6;
    if (t == 0) { n = 3 * D * D; return ipw + (size_t)l * 3 * D * D; }
    n = F * D;
    return (t == 1) ? w1 + (size_t)l * F * D : w2 + (size_t)l * F * D;
}

__global__ void k_etch_all(const float* __restrict__ ipw, const float* __restrict__ w1,
                           const float* __restrict__ w2)
{
    int slot = blockIdx.y;
    int n;
    const float* w = slot_w(slot, ipw, w1, w2, n);
    float inv = 1.f / (float)(n - 1);
    float* aout = d_abs_all + (size_t)slot * SLOT_STRIDE;
    unsigned* h1 = d_h1g + slot * 4096;

    __shared__ unsigned h[4096];
    for (int j = threadIdx.x; j < 4096; j += blockDim.x) h[j] = 0;
    __syncthreads();
    int stride = gridDim.x * blockDim.x;
    for (int i = blockIdx.x * blockDim.x + threadIdx.x; i < n; i += stride) {
        float wv = w[i];
        float b0 = __sinf(wv * PI_F);
        b0 = fminf(fmaxf(b0, -1.f), 1.f);
        float bl = b0 + b0 * __cosf((float)i * inv + THIRD_F) * 1.5f;
        float e = __cosf(bl * PI2_F) + bl * bl * DEVPI_F;
        float a = fabsf(e);
        aout[i] = a;
        atomicAdd(&h[__float_as_uint(a) >> 20], 1u);
    }
    __syncthreads();
    for (int j = threadIdx.x; j < 4096; j += blockDim.x) {
        unsigned c = h[j];
        if (c) atomicAdd(&h1[j], c);
    }
}

__global__ void k_scan1_all(const float* ipw, const float* w1, const float* w2)
{
    int slot = blockIdx.x;
    int n; slot_w(slot, ipw, w1, w2, n);
    unsigned rA = (unsigned)((n - 1) >> 2);
    unsigned rB = rA + 1;
    const unsigned* h1 = d_h1g + slot * 4096;
    unsigned* sel = d_selg + slot * 8;

    __shared__ unsigned part[256];
    __shared__ unsigned pref[256];
    int t = threadIdx.x, base = t * 16;
    unsigned c[16]; unsigned s = 0;
    for (int j = 0; j < 16; j++) { c[j] = h1[base + j]; s += c[j]; }
    part[t] = s; __syncthreads();
    if (t == 0) { unsigned a = 0; for (int i = 0; i < 256; i++) { pref[i] = a; a += part[i]; } }
    __syncthreads();
    unsigned p = pref[t];
    for (int j = 0; j < 16; j++) {
        if (rA >= p && rA < p + c[j]) { sel[0] = base + j; sel[1] = rA - p; }
        if (rB >= p && rB < p + c[j]) { sel[2] = base + j; sel[3] = rB - p; }
        p += c[j];
    }
}

// level 2: bits [10,20), smem-privatized 2x1024 bins
__global__ void k_hist2_all(const float* ipw, const float* w1, const float* w2)
{
    int slot = blockIdx.y;
    int n; slot_w(slot, ipw, w1, w2, n);
    const uint4* ab = (const uint4*)(d_abs_all + (size_t)slot * SLOT_STRIDE);
    const unsigned* sel = d_selg + slot * 8;
    unsigned sA = sel[0], sB = sel[2];

    __shared__ unsigned hA[1024], hB[1024];
    for (int j = threadIdx.x; j < 1024; j += 256) { hA[j] = 0; hB[j] = 0; }
    __syncthreads();

    int n4 = n >> 2;
    int stride = gridDim.x * blockDim.x;
    for (int i = blockIdx.x * blockDim.x + threadIdx.x; i < n4; i += stride) {
        uint4 u = ab[i];
        #pragma unroll
        for (int q = 0; q < 4; q++) {
            unsigned v = (q == 0) ? u.x : (q == 1) ? u.y : (q == 2) ? u.z : u.w;
            unsigned hi = v >> 20, m = (v >> 10) & 1023u;
            if (hi == sA) atomicAdd(&hA[m], 1u);
            if (hi == sB) atomicAdd(&hB[m], 1u);
        }
    }
    __syncthreads();
    unsigned* g2 = d_h2g + slot * 2048;
    for (int j = threadIdx.x; j < 1024; j += 256) {
        if (hA[j]) atomicAdd(&g2[j], hA[j]);
        if (hB[j]) atomicAdd(&g2[1024 + j], hB[j]);
    }
}

__global__ void k_scan2_all()
{
    int slot = blockIdx.x;
    unsigned* sel = d_selg + slot * 8;
    __shared__ unsigned part[256];
    __shared__ unsigned pref[256];
    int t = threadIdx.x;
    for (int sidx = 0; sidx < 2; sidx++) {
        unsigned rank = sel[1 + sidx * 2];
        const unsigned* hb = d_h2g + slot * 2048 + sidx * 1024;
        int base = t * 4;
        unsigned c[4]; unsigned s = 0;
        for (int j = 0; j < 4; j++) { c[j] = hb[base + j]; s += c[j]; }
        part[t] = s; __syncthreads();
        if (t == 0) { unsigned a = 0; for (int i = 0; i < 256; i++) { pref[i] = a; a += part[i]; } }
        __syncthreads();
        unsigned p = pref[t];
        for (int j = 0; j < 4; j++) {
            if (rank >= p && rank < p + c[j]) { sel[4 + sidx*2] = base + j; sel[5 + sidx*2] = rank - p; }
            p += c[j];
        }
        __syncthreads();
    }
}

// level 3: match 22-bit prefix, bins = bits [0,10) (global atomics, few matches)
__global__ void k_hist3_all(const float* ipw, const float* w1, const float* w2)
{
    int slot = blockIdx.y;
    int n; slot_w(slot, ipw, w1, w2, n);
    const uint4* ab = (const uint4*)(d_abs_all + (size_t)slot * SLOT_STRIDE);
    const unsigned* sel = d_selg + slot * 8;
    unsigned* h3 = d_h3g + slot * 2048;
    unsigned kA = (sel[0] << 10) | sel[4];
    unsigned kB = (sel[2] << 10) | sel[6];
    int n4 = n >> 2;
    int stride = gridDim.x * blockDim.x;
    for (int i = blockIdx.x * blockDim.x + threadIdx.x; i < n4; i += stride) {
        uint4 u = ab[i];
        #pragma unroll
        for (int q = 0; q < 4; q++) {
            unsigned v = (q == 0) ? u.x : (q == 1) ? u.y : (q == 2) ? u.z : u.w;
            unsigned top = v >> 10;
            if (top == kA) atomicAdd(&h3[v & 1023u], 1u);
            if (top == kB) atomicAdd(&h3[1024 + (v & 1023u)], 1u);
        }
    }
}

// resolve last 10 bits: one warp per slot walks the 1024-bin L3 histogram
__global__ void k_thr_all(const float* ipw, const float* w1, const float* w2)
{
    int slot = blockIdx.x;
    int lane = threadIdx.x;
    int n; slot_w(slot, ipw, w1, w2, n);
    float frac = 0.25f * (float)((n - 1) & 3);
    const unsigned* sel = d_selg + slot * 8;
    __shared__ unsigned fnd[2];

    for (int sidx = 0; sidx < 2; sidx++) {
        unsigned rank = sel[5 + sidx * 2];
        const unsigned* hb = d_h3g + slot * 2048 + sidx * 1024;
        unsigned s = 0;
        unsigned c[32];
        for (int j = 0; j < 32; j++) { c[j] = hb[lane * 32 + j]; s += c[j]; }
        // exclusive prefix across lanes
        unsigned p = s;
        for (int o = 1; o < 32; o <<= 1) {
            unsigned t2 = __shfl_up_sync(0xFFFFFFFF, p, o);
            if (lane >= o) p += t2;
        }
        p -= s;
        for (int j = 0; j < 32; j++) {
            if (rank >= p && rank < p + c[j]) fnd[sidx] = lane * 32 + j;
            p += c[j];
        }
        __syncthreads();
    }
    if (lane == 0) {
        float vA = __uint_as_float((sel[0] << 20) | (sel[4] << 10) | fnd[0]);
        float vB = __uint_as_float((sel[2] << 20) | (sel[6] << 10) | fnd[1]);
        d_thrg[slot] = vA + frac * (vB - vA);
    }
}

__global__ void k_mask_all(const float* __restrict__ ipw, const float* __restrict__ w1,
                           const float* __restrict__ w2)
{
    int slot = blockIdx.y;
    int n;
    const float* w = slot_w(slot, ipw, w1, w2, n);
    const uint4*  av4 = (const uint4*)(d_abs_all + (size_t)slot * SLOT_STRIDE);
    const float4* wv4 = (const float4*)w;
    float4* ov4 = (float4*)(d_wp + (size_t)slot * SLOT_STRIDE);
    float thr = d_thrg[slot];
    int n4 = n >> 2;
    int stride = gridDim.x * blockDim.x;
    for (int i = blockIdx.x * blockDim.x + threadIdx.x; i < n4; i += stride) {
        uint4 a = av4[i];
        float4 wv = wv4[i];
        float4 o;
        o.x = (__uint_as_float(a.x) > thr) ? tf32r(wv.x) : 0.f;
        o.y = (__uint_as_float(a.y) > thr) ? tf32r(wv.y) : 0.f;
        o.z = (__uint_as_float(a.z) > thr) ? tf32r(wv.z) : 0.f;
        o.w = (__uint_as_float(a.w) > thr) ? tf32r(wv.w) : 0.f;
        ov4[i] = o;
    }
}

// ---------------- entry point ----------------
extern "C" void kernel_launch(void* const* d_in, const int* in_sizes, int n_in,
                              void* d_out, int out_size)
{
    const int*   src = (const int*)  d_in[0];
    const float* emb = (const float*)d_in[1];
    const float* pos = (const float*)d_in[2];
    const float* ipw = (const float*)d_in[3];
    const float* ipb = (const float*)d_in[4];
    const float* opw = (const float*)d_in[5];
    const float* opb = (const float*)d_in[6];
    const float* l1g = (const float*)d_in[7];
    const float* l1b = (const float*)d_in[8];
    const float* l2g = (const float*)d_in[9];
    const float* l2b = (const float*)d_in[10];
    const float* w1  = (const float*)d_in[11];
    const float* b1  = (const float*)d_in[12];
    const float* w2  = (const float*)d_in[13];
    const float* b2  = (const float*)d_in[14];
    const float* ow  = (const float*)d_in[15];
    const float* ob  = (const float*)d_in[16];
    const int V = in_sizes[16];
    float* out = (float*)d_out;

    float *px, *pxtf, *pqkv, *pao, *pff, *ptmp, *pwp, *pwr, *powr;
    cudaGetSymbolAddress((void**)&px,   d_x);
    cudaGetSymbolAddress((void**)&pxtf, d_xtf);
    cudaGetSymbolAddress((void**)&pqkv, d_qkv);
    cudaGetSymbolAddress((void**)&pao,  d_ao);
    cudaGetSymbolAddress((void**)&pff,  d_ff);
    cudaGetSymbolAddress((void**)&ptmp, d_tmp);
    cudaGetSymbolAddress((void**)&pwp,  d_wp);
    cudaGetSymbolAddress((void**)&pwr,  d_wr);
    cudaGetSymbolAddress((void**)&powr, d_owr);

    cudaFuncAttributes fa{};
    cudaFuncGetAttributes(&fa, k_tc<false,false,false,false>);
    const bool use_tc = fa.numRegs > 40;

    if (use_tc) {
        cudaFuncSetAttribute(k_tc<false,false,false,false>, cudaFuncAttributeMaxDynamicSharedMemorySize, TC_SMEM);
        cudaFuncSetAttribute(k_tc<false,false,true ,true >, cudaFuncAttributeMaxDynamicSharedMemorySize, TC_SMEM);
        cudaFuncSetAttribute(k_tc<true ,false,true ,true >, cudaFuncAttributeMaxDynamicSharedMemorySize, TC_SMEM);
        cudaFuncSetAttribute(k_tc<false,true ,false,true >, cudaFuncAttributeMaxDynamicSharedMemorySize, TC_SMEM);
    }
    cudaFuncSetAttribute(k_attn, cudaFuncAttributeMaxDynamicSharedMemorySize, AT_SMEM);

    // fused prep: embed + round static weights + zero histograms
    int prepN = MT * D;
    if (V * D > prepN) prepN = V * D;
    k_prep<<<(prepN + 255) / 256, 256>>>(src, emb, pos, px, pxtf, opw, ow, V * D);

    k_etch_all <<<dim3(128, NSLOT), 256>>>(ipw, w1, w2);
    k_scan1_all<<<NSLOT, 256>>>(ipw, w1, w2);
    k_hist2_all<<<dim3(64, NSLOT), 256>>>(ipw, w1, w2);
    k_scan2_all<<<NSLOT, 256>>>();
    k_hist3_all<<<dim3(128, NSLOT), 256>>>(ipw, w1, w2);
    k_thr_all  <<<NSLOT, 32>>>(ipw, w1, w2);
    k_mask_all <<<dim3(512, NSLOT), 256>>>(ipw, w1, w2);

    for (int l = 0; l < L; l++) {
        const float* wi_l = pwp + (size_t)(0 * 6 + l) * SLOT_STRIDE;
        const float* w1_l = pwp + (size_t)(1 * 6 + l) * SLOT_STRIDE;
        const float* w2_l = pwp + (size_t)(2 * 6 + l) * SLOT_STRIDE;

        // qkv = x @ wi^T + b (dual-M, output tf32-rounded: feeds attention)
        if (use_tc)
            k_tc<false,false,true,true><<<dim3((3*D)/TC_BN, MT/256), 256, TC_SMEM>>>(
                3*D, D, pxtf, D, wi_l, D, pqkv, 3*D, ipb + (size_t)l * 3 * D);
        else
            k_mma<128,128,2,2,true,false,false,true><<<dim3((3*D)/128, MT/128, 1), 128>>>(
                MT, 3*D, D, pxtf, D, 0, 0, wi_l, D, 0, 0, pqkv, 3*D, 0, 0, 1,
                ipb + (size_t)l * 3 * D, 1.f);

        // fused flash attention
        k_attn<<<dim3(4, BH), 256, AT_SMEM>>>(pqkv, pao);

        // out projection (single-M: keeps grid at 128 CTAs)
        if (use_tc)
            k_tc<false,false,false,false><<<dim3(D/TC_BN, MT/128), 256, TC_SMEM>>>(
                D, D, pao, D, pwr + (size_t)l*D*D, D, ptmp, D, opb + (size_t)l*D);
        else
            k_mma<128,128,2,2,true,false,false,false><<<dim3(D/128, MT/128, 1), 128>>>(
                MT, D, D, pao, D, 0, 0, pwr + (size_t)l*D*D, D, 0, 0,
                ptmp, D, 0, 0, 1, opb + (size_t)l*D, 1.f);
        k_add_ln<<<MT, 256>>>(px, ptmp, l1g + (size_t)l*D, l1b + (size_t)l*D, px, pxtf);

        // feed-forward: ff1 dual-M, ff2 single-M
        if (use_tc) {
            k_tc<true,false,true,true><<<dim3(F/TC_BN, MT/256), 256, TC_SMEM>>>(
                F, D, pxtf, D, w1_l, D, pff, F, b1 + (size_t)l*F);
            k_tc<false,false,false,false><<<dim3(D/TC_BN, MT/128), 256, TC_SMEM>>>(
                D, F, pff, F, w2_l, F, ptmp, D, b2 + (size_t)l*D);
        } else {
            k_mma<128,128,2,2,true,true,false,true><<<dim3(F/128, MT/128, 1), 128>>>(
                MT, F, D, pxtf, D, 0, 0, w1_l, D, 0, 0, pff, F, 0, 0, 1,
                b1 + (size_t)l*F, 1.f);
            k_mma<128,128,2,2,true,false,false,false><<<dim3(D/128, MT/128, 1), 128>>>(
                MT, D, F, pff, F, 0, 0, w2_l, F, 0, 0, ptmp, D, 0, 0, 1,
                b2 + (size_t)l*D, 1.f);
        }
        k_add_ln<<<MT, 256>>>(px, ptmp, l2g + (size_t)l*D, l2b + (size_t)l*D, px, pxtf);
    }

    // logits (dual-M, N guarded)
    if (use_tc)
        k_tc<false,true,false,true><<<dim3((V + TC_BN - 1)/TC_BN, MT/256), 256, TC_SMEM>>>(
            V, D, pxtf, D, powr, D, out, V, ob);
    else
        k_mma<128,128,2,2,true,false,true,false><<<dim3((V + 127) / 128, MT / 128, 1), 128>>>(
            MT, V, D, pxtf, D, 0, 0, powr, D, 0, 0, out, V, 0, 0, 1, ob, 1.f);
}

// round 13
// speedup vs baseline: 2.8838x; 1.0732x over previous
#include <cuda_runtime.h>
#include <cstdint>
#include <math.h>

// ---------------- constants ----------------
#define PI_F      3.14159265358979323846f
#define PI2_F     9.86960440108935861883f
#define THIRD_F   2.09439510239319549231f
#define DEVPI_F   0.003183098861837907f
#define SQRTD_F   22.62741699796952f

constexpr int S  = 512;
constexpr int D  = 512;
constexpr int H  = 8;
constexpr int DH = 64;
constexpr int L  = 6;
constexpr int F  = 2048;
constexpr int BB = 16;
constexpr int MT = BB * S;   // 8192 tokens
constexpr int BH = BB * H;   // 128
constexpr int NSLOT = 18;
constexpr size_t SLOT_STRIDE = 1048576;
constexpr int VMAX = 10240;

// Feature gate: tcgen05 only exists on arch-specific (sm_103a) / family (sm_103f) targets.
#if !defined(__CUDA_ARCH__) || defined(__CUDA_ARCH_FEAT_SM103_ALL) || defined(__CUDA_ARCH_SPECIFIC__) || defined(__CUDA_ARCH_FAMILY_SPECIFIC__)
#define TC_AVAIL 1
#else
#define TC_AVAIL 0
#endif

// ---------------- device scratch ----------------
__device__ __align__(128) float d_x   [MT * D];
__device__ __align__(128) float d_xtf [MT * D];
__device__ __align__(128) float d_qkv [MT * 3 * D];
__device__ __align__(128) float d_ao  [MT * D];
__device__ __align__(128) float d_ff  [MT * F];
__device__ __align__(128) float d_tmp [MT * D];
__device__ __align__(128) float d_wp  [NSLOT * SLOT_STRIDE];
__device__ __align__(128) float d_wr  [L * D * D];
__device__ __align__(128) float d_owr [VMAX * D];
__device__ __align__(128) float d_abs_all[NSLOT * SLOT_STRIDE];
__device__ unsigned d_h1g[NSLOT * 4096];
__device__ unsigned d_h2g[NSLOT * 2048];   // level2: 2 x 1024 bins (bits [10,20))
__device__ unsigned d_h3g[NSLOT * 2048];   // level3: 2 x 1024 bins (bits [0,10))
__device__ unsigned d_selg[NSLOT * 8];
__device__ float d_thrg[NSLOT];

// ---------------- helpers ----------------
__device__ __forceinline__ float tf32r(float f) {
    uint32_t u;
    asm("cvt.rna.tf32.f32 %0, %1;" : "=r"(u) : "f"(f));
    return __uint_as_float(u);
}

__device__ __forceinline__ void mma_tf32(float c[4],
    uint32_t a0, uint32_t a1, uint32_t a2, uint32_t a3,
    uint32_t b0, uint32_t b1)
{
    asm volatile(
        "mma.sync.aligned.m16n8k8.row.col.f32.tf32.tf32.f32 "
        "{%0,%1,%2,%3}, {%4,%5,%6,%7}, {%8,%9}, {%0,%1,%2,%3};"
        : "+f"(c[0]), "+f"(c[1]), "+f"(c[2]), "+f"(c[3])
        : "r"(a0), "r"(a1), "r"(a2), "r"(a3), "r"(b0), "r"(b1));
}

__device__ __forceinline__ void cp16(void* d, const void* s) {
    uint32_t a = (uint32_t)__cvta_generic_to_shared(d);
    asm volatile("cp.async.cg.shared.global [%0], [%1], 16;" :: "r"(a), "l"(s));
}
__device__ __forceinline__ void cp16p(void* d, const void* s, bool p) {
    uint32_t a = (uint32_t)__cvta_generic_to_shared(d);
    int sz = p ? 16 : 0;
    asm volatile("cp.async.cg.shared.global [%0], [%1], 16, %2;" :: "r"(a), "l"(s), "r"(sz));
}
#define CP_COMMIT() asm volatile("cp.async.commit_group;")
#define CP_WAIT0()  asm volatile("cp.async.wait_group 0;")
#define CP_WAIT1()  asm volatile("cp.async.wait_group 1;")
#define CP_WAIT2()  asm volatile("cp.async.wait_group 2;")

// ================= tcgen05 tf32 GEMM (guarded) =================
constexpr int TC_BN = 256;
constexpr int TC_BK = 32;
constexpr int TC_SMEM = 197632;
constexpr int TC_NT = 512;   // threads per CTA

#if TC_AVAIL
__device__ __forceinline__ uint32_t elect1() {
    uint32_t pred;
    asm volatile("{\n\t.reg .pred p;\n\telect.sync _|p, 0xFFFFFFFF;\n\t"
                 "selp.b32 %0, 1, 0, p;\n\t}" : "=r"(pred));
    return pred;
}
#define MBAR_INIT(addr, cnt) \
    asm volatile("mbarrier.init.shared.b64 [%0], %1;" :: "r"(addr), "r"(cnt) : "memory")
#define MBAR_WAIT(addr, par) do { \
    asm volatile("{\n\t.reg .pred P1;\n\tWL%=:\n\t" \
        "mbarrier.try_wait.parity.acquire.cta.shared::cta.b64 P1, [%0], %1, 0x989680;\n\t" \
        "@P1 bra.uni WD%=;\n\tbra.uni WL%=;\n\tWD%=:\n\t}" \
        :: "r"(addr), "r"(par) : "memory"); \
} while (0)
#define TC_ALLOC(sm, n)   asm volatile("tcgen05.alloc.cta_group::1.sync.aligned.shared::cta.b32 [%0], %1;" :: "r"(sm), "r"(n) : "memory")
#define TC_DEALLOC(t, n)  asm volatile("tcgen05.dealloc.cta_group::1.sync.aligned.b32 %0, %1;" :: "r"(t), "r"(n))
#define TC_COMMIT(mb)     asm volatile("tcgen05.commit.cta_group::1.mbarrier::arrive::one.shared::cluster.b64 [%0];" :: "r"(mb) : "memory")
#define TC_FENCE_AFTER()  asm volatile("tcgen05.fence::after_thread_sync;" ::: "memory")
#define TC_FENCE_BEFORE() asm volatile("tcgen05.fence::before_thread_sync;" ::: "memory")
#define TC_WAIT_LD()      asm volatile("tcgen05.wait::ld.sync.aligned;" ::: "memory")
#define FENCE_PROXY()     asm volatile("fence.proxy.async.shared::cta;" ::: "memory")

#define TC_LD_X32(r, addr) \
    asm volatile("tcgen05.ld.sync.aligned.32x32b.x32.b32 " \
        "{%0, %1, %2, %3, %4, %5, %6, %7, %8, %9, %10, %11, %12, %13, %14, %15, " \
        " %16, %17, %18, %19, %20, %21, %22, %23, %24, %25, %26, %27, %28, %29, %30, %31}, [%32];" \
        : "=r"((r)[0]),  "=r"((r)[1]),  "=r"((r)[2]),  "=r"((r)[3]), \
          "=r"((r)[4]),  "=r"((r)[5]),  "=r"((r)[6]),  "=r"((r)[7]), \
          "=r"((r)[8]),  "=r"((r)[9]),  "=r"((r)[10]), "=r"((r)[11]), \
          "=r"((r)[12]), "=r"((r)[13]), "=r"((r)[14]), "=r"((r)[15]), \
          "=r"((r)[16]), "=r"((r)[17]), "=r"((r)[18]), "=r"((r)[19]), \
          "=r"((r)[20]), "=r"((r)[21]), "=r"((r)[22]), "=r"((r)[23]), \
          "=r"((r)[24]), "=r"((r)[25]), "=r"((r)[26]), "=r"((r)[27]), \
          "=r"((r)[28]), "=r"((r)[29]), "=r"((r)[30]), "=r"((r)[31]) \
        : "r"(addr))

static constexpr uint64_t SMEM_DESC_BASE =
    (uint64_t(2) << 61) | (uint64_t(1) << 46) | (uint64_t(64) << 32) | (uint64_t(1) << 16);
#define MK_DESC(a) (SMEM_DESC_BASE | ((uint64_t)((a) >> 4) & 0x3FFF))

__device__ __forceinline__ void mma_tc(uint32_t d, uint64_t ad, uint64_t bd,
                                       uint32_t idesc, bool en)
{
    uint32_t e = en ? 1 : 0;
    asm volatile(
        "{\n\t.reg .pred p;\n\tsetp.ne.u32 p, %4, 0;\n\t"
        "tcgen05.mma.cta_group::1.kind::tf32 [%0], %1, %2, %3, {%5,%5,%5,%5}, p;\n\t}"
        :: "r"(d), "l"(ad), "l"(bd), "r"(idesc), "r"(e), "r"(0u) : "memory");
}
#endif  // TC_AVAIL

constexpr uint32_t TC_IDESC =
    (1u << 4) | (2u << 7) | (2u << 10) | ((TC_BN / 8) << 17) | ((128 / 16) << 24);

// C[m,n] = sum_k A[m,k]*B[n,k] + bias[n]; operands pre-rounded to tf32 values.
// M2=false: grid (N/256, M/128).  M2=true: grid (N/256, M/256), B loaded once per 256 M-rows.
template<bool RELU, bool GN, bool TFO, bool M2>
__global__ void __launch_bounds__(TC_NT, 1)
k_tc(int N, int K,
     const float* __restrict__ A, int lda,
     const float* __restrict__ B, int ldb,
     float* __restrict__ C, int ldc,
     const float* __restrict__ bias)
{
#if TC_AVAIL
    constexpr int NS    = M2 ? 3 : 4;
    constexpr int AROWS = M2 ? 256 : 128;
    constexpr int ASZ   = AROWS * 128;
    constexpr int BSZ   = TC_BN * 128;
    constexpr int TCOLS = M2 ? 512 : 256;

    extern __shared__ char smem[];
    uint32_t sbase = (uint32_t)__cvta_generic_to_shared(smem);
    const int tid = threadIdx.x, lane = tid & 31, warp = tid >> 5;
    const int m0 = blockIdx.y * AROWS, n0 = blockIdx.x * TC_BN;

    if (warp == 0) TC_ALLOC(sbase, TCOLS);
    if (tid == 0) {
        #pragma unroll
        for (int s = 0; s < NS; s++) MBAR_INIT(sbase + 16 + 8 * s, 1);
    }
    __syncthreads();
    uint32_t tmem;
    asm volatile("ld.shared.b32 %0, [%1];" : "=r"(tmem) : "r"(sbase));

    const uint32_t aoff = 1024, boff = 1024 + NS * ASZ;

    auto loadStage = [&](int st, int k0) {
        char* pa = smem + aoff + st * ASZ;
        char* pb = smem + boff + st * BSZ;
        #pragma unroll
        for (int r = 0; r < AROWS / 64; r++) {   // AROWS*8 chunks / 512 threads
            int i = tid + r * TC_NT;
            int m = i >> 3, c = i & 7;
            int cs = c ^ (m & 7);     // SW128
            cp16(pa + m * 128 + cs * 16, &A[(size_t)(m0 + m) * lda + k0 + c * 4]);
        }
        #pragma unroll
        for (int r = 0; r < 4; r++) {            // 2048 chunks / 512 threads
            int i = tid + r * TC_NT;
            int n = i >> 3, c = i & 7;
            int cs = c ^ (n & 7);
            int gn = n0 + n;
            if (GN) {
                bool ok = gn < N;
                cp16p(pb + n * 128 + cs * 16,
                      ok ? &B[(size_t)gn * ldb + k0 + c * 4] : (const float*)B, ok);
            } else {
                cp16(pb + n * 128 + cs * 16, &B[(size_t)gn * ldb + k0 + c * 4]);
            }
        }
    };

    const int nk = K / TC_BK;

    #pragma unroll
    for (int s = 0; s < NS - 1; s++) { loadStage(s, s * TC_BK); CP_COMMIT(); }

    for (int kt = 0; kt < nk; kt++) {
        int cur = kt % NS;
        if (M2) { CP_WAIT1(); } else { CP_WAIT2(); }
        __syncthreads();
        FENCE_PROXY();
        if (warp == 0 && elect1()) {
            uint64_t ad = MK_DESC(sbase + aoff + cur * ASZ);
            uint64_t bd = MK_DESC(sbase + boff + cur * BSZ);
            #pragma unroll
            for (int j = 0; j < 4; j++) {
                bool en = (kt > 0) || (j > 0);
                mma_tc(tmem, ad + j * 2, bd + j * 2, TC_IDESC, en);
                if (M2) {
                    uint64_t ad2 = MK_DESC(sbase + aoff + cur * ASZ + 128 * 128);
                    mma_tc(tmem + 256, ad2 + j * 2, bd + j * 2, TC_IDESC, en);
                }
            }
            TC_COMMIT(sbase + 16 + 8 * cur);
        }
        if (kt >= 1) MBAR_WAIT(sbase + 16 + 8 * ((kt - 1) % NS), ((kt - 1) / NS) & 1);
        int kn = kt + NS - 1;
        if (kn < nk) loadStage(kn % NS, kn * TC_BK);
        CP_COMMIT();
    }
    MBAR_WAIT(sbase + 16 + 8 * ((nk - 1) % NS), ((nk - 1) / NS) & 1);

    __syncthreads();
    TC_FENCE_AFTER();

    // epilogue (16 warps): TMEM row subpartition = warp&3
    float* myep = (float*)(smem + 1024) + warp * (32 * 33);
    if (M2) {
        int half = warp >> 3;                      // warps 0-7 -> m-tile0, 8-15 -> m-tile1
        uint32_t tbase = tmem + half * 256;
        int rbase = m0 + half * 128 + (warp & 3) * 32;
        int cbase = ((warp >> 2) & 1) * 128;       // two col groups per half
        #pragma unroll
        for (int ch = 0; ch < 4; ch++) {
            int c0 = cbase + ch * 32;
            uint32_t regs[32];
            TC_LD_X32(regs, tbase + c0);
            TC_WAIT_LD();
            #pragma unroll
            for (int c = 0; c < 32; c++) {
                float v = __uint_as_float(regs[c]);
                if (!GN || (n0 + c0 + c) < N) {
                    v += bias[n0 + c0 + c];
                    if (RELU) v = fmaxf(v, 0.f);
                    if (TFO)  v = tf32r(v);
                }
                myep[lane * 33 + c] = v;
            }
            __syncwarp();
            int col = n0 + c0 + lane;
            #pragma unroll
            for (int i = 0; i < 32; i++) {
                if (!GN || col < N)
                    C[(size_t)(rbase + i) * ldc + col] = myep[i * 33 + lane];
            }
            __syncwarp();
        }
    } else {
        int rbase = m0 + (warp & 3) * 32;
        int cbase = (warp >> 2) * 64;              // 4 col groups of 64
        #pragma unroll
        for (int ch = 0; ch < 2; ch++) {
            int c0 = cbase + ch * 32;
            uint32_t regs[32];
            TC_LD_X32(regs, tmem + c0);
            TC_WAIT_LD();
            #pragma unroll
            for (int c = 0; c < 32; c++) {
                float v = __uint_as_float(regs[c]);
                if (!GN || (n0 + c0 + c) < N) {
                    v += bias[n0 + c0 + c];
                    if (RELU) v = fmaxf(v, 0.f);
                    if (TFO)  v = tf32r(v);
                }
                myep[lane * 33 + c] = v;
            }
            __syncwarp();
            int col = n0 + c0 + lane;
            #pragma unroll
            for (int i = 0; i < 32; i++) {
                if (!GN || col < N)
                    C[(size_t)(rbase + i) * ldc + col] = myep[i * 33 + lane];
            }
            __syncwarp();
        }
    }

    __syncthreads();
    if (warp == 0) { TC_FENCE_BEFORE(); TC_DEALLOC(tmem, TCOLS); }
#endif  // TC_AVAIL
}

// ================= fused flash attention (mma.sync tf32, pipelined KV) =================
constexpr int AT_SMEM = 174080;

__global__ void __launch_bounds__(256, 1)
k_attn(const float* __restrict__ qkv, float* __restrict__ ao)
{
    extern __shared__ float sm_[];
    float* Qs   = sm_;               // [128][68]
    float* Ks   = Qs + 128 * 68;
    float* Vs   = Ks + 128 * 68;
    float* Ps   = Vs + 128 * 68;     // [128][132]
    float* rmx  = Ps + 128 * 132;
    float* rsm  = rmx + 256;

    const int tid = threadIdx.x, lane = tid & 31, warp = tid >> 5;
    const int wm = warp >> 1, wn = warp & 1;
    const int g = lane >> 2, t4 = lane & 3;
    const int bh = blockIdx.y, b = bh >> 3, h = bh & 7;
    const int qrow0 = b * 512 + blockIdx.x * 128;
    const int kvbase = b * 512;

    auto loadK = [&](int kc) {
        int kvrow0 = kvbase + kc * 128;
        #pragma unroll
        for (int r = 0; r < 8; r++) {
            int i = tid + r * 256;
            int row = i >> 4, c = (i & 15) << 2;
            cp16(&Ks[row * 68 + c], &qkv[(size_t)(kvrow0 + row) * 1536 + 512 + h * 64 + c]);
        }
    };
    auto loadV = [&](int kc) {
        int kvrow0 = kvbase + kc * 128;
        #pragma unroll
        for (int r = 0; r < 8; r++) {
            int i = tid + r * 256;
            int row = i >> 4, c = (i & 15) << 2;
            cp16(&Vs[row * 68 + c], &qkv[(size_t)(kvrow0 + row) * 1536 + 1024 + h * 64 + c]);
        }
    };

    loadK(0); CP_COMMIT();
    loadV(0); CP_COMMIT();

    #pragma unroll
    for (int r = 0; r < 8; r++) {
        int i = tid + r * 256;
        int row = i >> 4, c = (i & 15) << 2;
        float4 v = *(const float4*)&qkv[(size_t)(qrow0 + row) * 1536 + h * 64 + c];
        Qs[row * 68 + c]     = v.x * 0.125f;
        Qs[row * 68 + c + 1] = v.y * 0.125f;
        Qs[row * 68 + c + 2] = v.z * 0.125f;
        Qs[row * 68 + c + 3] = v.w * 0.125f;
    }

    float m_i[2][2], l_i[2][2];
    float oa[2][4][4];
    #pragma unroll
    for (int i = 0; i < 2; i++)
        #pragma unroll
        for (int hf = 0; hf < 2; hf++) { m_i[i][hf] = -1e30f; l_i[i][hf] = 0.f; }
    #pragma unroll
    for (int i = 0; i < 2; i++)
        #pragma unroll
        for (int j = 0; j < 4; j++)
            #pragma unroll
            for (int q = 0; q < 4; q++) oa[i][j][q] = 0.f;

    for (int kc = 0; kc < 4; kc++) {
        CP_WAIT1();
        __syncthreads();

        float s[2][8][4];
        #pragma unroll
        for (int i = 0; i < 2; i++)
            #pragma unroll
            for (int j = 0; j < 8; j++)
                #pragma unroll
                for (int q = 0; q < 4; q++) s[i][j][q] = 0.f;

        #pragma unroll
        for (int ks = 0; ks < 8; ks++) {
            uint32_t af[2][4], bf[8][2];
            #pragma unroll
            for (int i = 0; i < 2; i++) {
                int row = wm * 32 + i * 16 + g;
                af[i][0] = __float_as_uint(Qs[row * 68 + ks * 8 + t4]);
                af[i][1] = __float_as_uint(Qs[(row + 8) * 68 + ks * 8 + t4]);
                af[i][2] = __float_as_uint(Qs[row * 68 + ks * 8 + t4 + 4]);
                af[i][3] = __float_as_uint(Qs[(row + 8) * 68 + ks * 8 + t4 + 4]);
            }
            #pragma unroll
            for (int j = 0; j < 8; j++) {
                int nc = wn * 64 + j * 8 + g;
                bf[j][0] = __float_as_uint(Ks[nc * 68 + ks * 8 + t4]);
                bf[j][1] = __float_as_uint(Ks[nc * 68 + ks * 8 + t4 + 4]);
            }
            #pragma unroll
            for (int i = 0; i < 2; i++)
                #pragma unroll
                for (int j = 0; j < 8; j++)
                    mma_tf32(s[i][j], af[i][0], af[i][1], af[i][2], af[i][3],
                             bf[j][0], bf[j][1]);
        }

        float mn[2][2];
        #pragma unroll
        for (int i = 0; i < 2; i++)
            #pragma unroll
            for (int hf = 0; hf < 2; hf++) {
                float v = -1e30f;
                #pragma unroll
                for (int j = 0; j < 8; j++)
                    v = fmaxf(v, fmaxf(s[i][j][2 * hf], s[i][j][2 * hf + 1]));
                v = fmaxf(v, __shfl_xor_sync(0xFFFFFFFF, v, 1));
                v = fmaxf(v, __shfl_xor_sync(0xFFFFFFFF, v, 2));
                mn[i][hf] = v;
            }
        if (t4 == 0) {
            #pragma unroll
            for (int i = 0; i < 2; i++)
                #pragma unroll
                for (int hf = 0; hf < 2; hf++)
                    rmx[(wm * 32 + i * 16 + g + 8 * hf) * 2 + wn] = mn[i][hf];
        }
        __syncthreads();

        if (kc < 3) loadK(kc + 1);
        CP_COMMIT();

        float sc[2][2];
        #pragma unroll
        for (int i = 0; i < 2; i++)
            #pragma unroll
            for (int hf = 0; hf < 2; hf++) {
                int row = wm * 32 + i * 16 + g + 8 * hf;
                float cm = fmaxf(rmx[row * 2], rmx[row * 2 + 1]);
                float nm = fmaxf(m_i[i][hf], cm);
                sc[i][hf] = __expf(m_i[i][hf] - nm);
                mn[i][hf] = nm;
            }
        #pragma unroll
        for (int i = 0; i < 2; i++)
            #pragma unroll
            for (int j = 0; j < 4; j++) {
                oa[i][j][0] *= sc[i][0]; oa[i][j][1] *= sc[i][0];
                oa[i][j][2] *= sc[i][1]; oa[i][j][3] *= sc[i][1];
            }
        float smv[2][2] = {{0.f, 0.f}, {0.f, 0.f}};
        #pragma unroll
        for (int i = 0; i < 2; i++) {
            int row = wm * 32 + i * 16 + g;
            #pragma unroll
            for (int j = 0; j < 8; j++) {
                int col = wn * 64 + j * 8 + 2 * t4;
                float p0 = __expf(s[i][j][0] - mn[i][0]);
                float p1 = __expf(s[i][j][1] - mn[i][0]);
                float p2 = __expf(s[i][j][2] - mn[i][1]);
                float p3 = __expf(s[i][j][3] - mn[i][1]);
                smv[i][0] += p0 + p1;
                smv[i][1] += p2 + p3;
                Ps[row * 132 + col]           = tf32r(p0);
                Ps[row * 132 + col + 1]       = tf32r(p1);
                Ps[(row + 8) * 132 + col]     = tf32r(p2);
                Ps[(row + 8) * 132 + col + 1] = tf32r(p3);
            }
        }
        #pragma unroll
        for (int i = 0; i < 2; i++)
            #pragma unroll
            for (int hf = 0; hf < 2; hf++) {
                float v = smv[i][hf];
                v += __shfl_xor_sync(0xFFFFFFFF, v, 1);
                v += __shfl_xor_sync(0xFFFFFFFF, v, 2);
                smv[i][hf] = v;
            }
        if (t4 == 0) {
            #pragma unroll
            for (int i = 0; i < 2; i++)
                #pragma unroll
                for (int hf = 0; hf < 2; hf++)
                    rsm[(wm * 32 + i * 16 + g + 8 * hf) * 2 + wn] = smv[i][hf];
        }
        CP_WAIT1();
        __syncthreads();
        #pragma unroll
        for (int i = 0; i < 2; i++)
            #pragma unroll
            for (int hf = 0; hf < 2; hf++) {
                int row = wm * 32 + i * 16 + g + 8 * hf;
                l_i[i][hf] = l_i[i][hf] * sc[i][hf] + rsm[row * 2] + rsm[row * 2 + 1];
                m_i[i][hf] = mn[i][hf];
            }

        #pragma unroll
        for (int ks = 0; ks < 16; ks++) {
            uint32_t af[2][4], bf[4][2];
            #pragma unroll
            for (int i = 0; i < 2; i++) {
                int row = wm * 32 + i * 16 + g;
                af[i][0] = __float_as_uint(Ps[row * 132 + ks * 8 + t4]);
                af[i][1] = __float_as_uint(Ps[(row + 8) * 132 + ks * 8 + t4]);
                af[i][2] = __float_as_uint(Ps[row * 132 + ks * 8 + t4 + 4]);
                af[i][3] = __float_as_uint(Ps[(row + 8) * 132 + ks * 8 + t4 + 4]);
            }
            #pragma unroll
            for (int j = 0; j < 4; j++) {
                int nc = wn * 32 + j * 8 + g;
                bf[j][0] = __float_as_uint(Vs[(ks * 8 + t4) * 68 + nc]);
                bf[j][1] = __float_as_uint(Vs[(ks * 8 + t4 + 4) * 68 + nc]);
            }
            #pragma unroll
            for (int i = 0; i < 2; i++)
                #pragma unroll
                for (int j = 0; j < 4; j++)
                    mma_tf32(oa[i][j], af[i][0], af[i][1], af[i][2], af[i][3],
                             bf[j][0], bf[j][1]);
        }

        __syncthreads();
        if (kc < 3) loadV(kc + 1);
        CP_COMMIT();
    }

    #pragma unroll
    for (int i = 0; i < 2; i++) {
        float r0 = 1.f / l_i[i][0], r1 = 1.f / l_i[i][1];
        int row = qrow0 + wm * 32 + i * 16 + g;
        #pragma unroll
        for (int j = 0; j < 4; j++) {
            int col = h * 64 + wn * 32 + j * 8 + 2 * t4;
            *(float2*)&ao[(size_t)row * 512 + col] =
                make_float2(tf32r(oa[i][j][0] * r0), tf32r(oa[i][j][1] * r0));
            *(float2*)&ao[(size_t)(row + 8) * 512 + col] =
                make_float2(tf32r(oa[i][j][2] * r1), tf32r(oa[i][j][3] * r1));
        }
    }
}

// ================= mma.sync GEMM (fallback path) =================
template<int BM,int BN,int WARPS_M,int WARPS_N,bool TB,bool RELU,bool GN,bool TFO>
__global__ void __launch_bounds__(WARPS_M*WARPS_N*32)
k_mma(int M, int N, int K,
      const float* __restrict__ Ag, int lda, long long sA1, long long sA2,
      const float* __restrict__ Bg, int ldb, long long sB1, long long sB2,
      float* __restrict__ Cg, int ldc, long long sC1, long long sC2,
      int zdiv, const float* __restrict__ bias, float alpha)
{
    constexpr int BK = 16;
    constexpr int NT = WARPS_M * WARPS_N * 32;
    constexpr int WM = BM / WARPS_M, WN = BN / WARPS_N;
    constexpr int MI = WM / 16, NI = WN / 8;
    constexpr int AST = BK + 4;
    constexpr int BROWS = TB ? BN : BK;
    constexpr int BCOLS = TB ? (BK + 4) : (BN + 8);

    __shared__ __align__(16) float As[2][BM][AST];
    __shared__ __align__(16) float Bs[2][BROWS][BCOLS];

    const int bz = blockIdx.z;
    const int z1 = bz / zdiv, z2 = bz - z1 * zdiv;
    const float* A  = Ag + z1 * sA1 + z2 * sA2;
    const float* Bp = Bg + z1 * sB1 + z2 * sB2;
    float* C        = Cg + z1 * sC1 + z2 * sC2;

    const int m0 = blockIdx.y * BM, n0 = blockIdx.x * BN;
    const int tid  = threadIdx.x;
    const int lane = tid & 31, warp = tid >> 5;
    const int wm = warp / WARPS_N, wn = warp - wm * WARPS_N;
    const int g = lane >> 2, t4 = lane & 3;

    float acc[MI][NI][4];
    #pragma unroll
    for (int i = 0; i < MI; i++)
        #pragma unroll
        for (int j = 0; j < NI; j++)
            #pragma unroll
            for (int q = 0; q < 4; q++) acc[i][j][q] = 0.f;

    auto loadTiles = [&](int st, int k0) {
        #pragma unroll
        for (int r = 0; r < (BM * (BK/4)) / NT; r++) {
            int i = tid + r * NT;
            int m = i >> 2;
            int c = (i & 3) << 2;
            cp16(&As[st][m][c], &A[(size_t)(m0 + m) * lda + k0 + c]);
        }
        if (TB) {
            #pragma unroll
            for (int r = 0; r < (BN * (BK/4)) / NT; r++) {
                int i = tid + r * NT;
                int n = i >> 2;
                int c = (i & 3) << 2;
                int gn = n0 + n;
                if (GN) {
                    bool ok = gn < N;
                    cp16p(&Bs[st][n][c], ok ? &Bp[(size_t)gn * ldb + k0 + c] : (const float*)Bp, ok);
                } else {
                    cp16(&Bs[st][n][c], &Bp[(size_t)gn * ldb + k0 + c]);
                }
            }
        } else {
            #pragma unroll
            for (int r = 0; r < (BK * (BN/4)) / NT; r++) {
                int i = tid + r * NT;
                int kk = i / (BN/4);
                int c  = (i - kk * (BN/4)) << 2;
                cp16(&Bs[st][kk][c], &Bp[(size_t)(k0 + kk) * ldb + n0 + c]);
            }
        }
    };

    const int nk = K / BK;
    loadTiles(0, 0);
    CP_COMMIT();

    for (int kt = 0; kt < nk; kt++) {
        int cur = kt & 1;
        if (kt + 1 < nk) loadTiles(cur ^ 1, (kt + 1) * BK);
        CP_COMMIT();
        CP_WAIT1();
        __syncthreads();

        #pragma unroll
        for (int ks = 0; ks < 2; ks++) {
            uint32_t af[MI][4], bf[NI][2];
            #pragma unroll
            for (int i = 0; i < MI; i++) {
                int mr = wm * WM + i * 16 + g;
                af[i][0] = __float_as_uint(As[cur][mr    ][ks*8 + t4    ]);
                af[i][1] = __float_as_uint(As[cur][mr + 8][ks*8 + t4    ]);
                af[i][2] = __float_as_uint(As[cur][mr    ][ks*8 + t4 + 4]);
                af[i][3] = __float_as_uint(As[cur][mr + 8][ks*8 + t4 + 4]);
            }
            #pragma unroll
            for (int j = 0; j < NI; j++) {
                int nc = wn * WN + j * 8 + g;
                if (TB) {
                    bf[j][0] = __float_as_uint(Bs[cur][nc][ks*8 + t4    ]);
                    bf[j][1] = __float_as_uint(Bs[cur][nc][ks*8 + t4 + 4]);
                } else {
                    bf[j][0] = __float_as_uint(Bs[cur][ks*8 + t4    ][nc]);
                    bf[j][1] = __float_as_uint(Bs[cur][ks*8 + t4 + 4][nc]);
                }
            }
            #pragma unroll
            for (int i = 0; i < MI; i++)
                #pragma unroll
                for (int j = 0; j < NI; j++)
                    mma_tf32(acc[i][j], af[i][0], af[i][1], af[i][2], af[i][3],
                             bf[j][0], bf[j][1]);
        }
        __syncthreads();
    }

    #pragma unroll
    for (int i = 0; i < MI; i++) {
        int r0 = m0 + wm * WM + i * 16 + g;
        #pragma unroll
        for (int j = 0; j < NI; j++) {
            int col = n0 + wn * WN + j * 8 + t4 * 2;
            if (GN && col >= N) continue;
            float b0v = 0.f, b1v = 0.f;
            if (bias) { b0v = bias[col]; b1v = bias[col + 1]; }
            float v0 = acc[i][j][0] * alpha + b0v;
            float v1 = acc[i][j][1] * alpha + b1v;
            float v2 = acc[i][j][2] * alpha + b0v;
            float v3 = acc[i][j][3] * alpha + b1v;
            if (RELU) {
                v0 = fmaxf(v0, 0.f); v1 = fmaxf(v1, 0.f);
                v2 = fmaxf(v2, 0.f); v3 = fmaxf(v3, 0.f);
            }
            if (TFO) {
                v0 = tf32r(v0); v1 = tf32r(v1); v2 = tf32r(v2); v3 = tf32r(v3);
            }
            *reinterpret_cast<float2*>(&C[(size_t)r0 * ldc + col])       = make_float2(v0, v1);
            *reinterpret_cast<float2*>(&C[(size_t)(r0 + 8) * ldc + col]) = make_float2(v2, v3);
        }
    }
}

// ---------------- residual add + layernorm (warp-per-row, no block barriers) ----------------
__global__ void __launch_bounds__(256)
k_add_ln(const float* __restrict__ xin, const float* __restrict__ res,
         const float* __restrict__ g, const float* __restrict__ b,
         float* __restrict__ xout, float* __restrict__ xtf)
{
    const int warp = threadIdx.x >> 5, lane = threadIdx.x & 31;
    const int row = blockIdx.x * 8 + warp;
    const long long base = (long long)row * D;

    float4 v[4];
    float sum = 0.f, sq = 0.f;
    #pragma unroll
    for (int i = 0; i < 4; i++) {
        int c = lane * 4 + i * 128;
        float4 a = *(const float4*)&xin[base + c];
        float4 r = *(const float4*)&res[base + c];
        a.x += r.x; a.y += r.y; a.z += r.z; a.w += r.w;
        v[i] = a;
        sum += (a.x + a.y) + (a.z + a.w);
        sq  += (a.x * a.x + a.y * a.y) + (a.z * a.z + a.w * a.w);
    }
    #pragma unroll
    for (int o = 16; o > 0; o >>= 1) {
        sum += __shfl_xor_sync(0xFFFFFFFF, sum, o);
        sq  += __shfl_xor_sync(0xFFFFFFFF, sq, o);
    }
    float mean = sum * (1.f / D);
    float var  = sq * (1.f / D) - mean * mean;
    float rs   = rsqrtf(var + 1e-5f);

    #pragma unroll
    for (int i = 0; i < 4; i++) {
        int c = lane * 4 + i * 128;
        float4 gg = *(const float4*)&g[c];
        float4 bb = *(const float4*)&b[c];
        float4 o_, ot;
        o_.x = (v[i].x - mean) * rs * gg.x + bb.x;
        o_.y = (v[i].y - mean) * rs * gg.y + bb.y;
        o_.z = (v[i].z - mean) * rs * gg.z + bb.z;
        o_.w = (v[i].w - mean) * rs * gg.w + bb.w;
        ot.x = tf32r(o_.x); ot.y = tf32r(o_.y); ot.z = tf32r(o_.z); ot.w = tf32r(o_.w);
        *(float4*)&xout[base + c] = o_;
        *(float4*)&xtf [base + c] = ot;
    }
}

// ---------------- fused prep: embedding + weight rounding + histogram zero ----------------
__global__ void k_prep(const int* __restrict__ src, const float* __restrict__ emb,
                       const float* __restrict__ pos, float* __restrict__ x,
                       float* __restrict__ xtf, const float* __restrict__ opw,
                       const float* __restrict__ ow, int nOw)
{
    int idx = blockIdx.x * blockDim.x + threadIdx.x;
    if (idx < MT * D) {
        int t = idx >> 9, d = idx & 511;
        float v = emb[(long long)src[t] * D + d] * SQRTD_F + pos[(t & 511) * D + d];
        x[idx]   = v;
        xtf[idx] = tf32r(v);
    }
    if (idx < L * D * D) d_wr[idx] = tf32r(opw[idx]);
    if (idx < nOw)       d_owr[idx] = tf32r(ow[idx]);
    if (idx < NSLOT * 2048) { d_h2g[idx] = 0; d_h3g[idx] = 0; }
    if (idx < NSLOT * 4096) d_h1g[idx] = 0;
}

// ---------------- batched prune pipeline ----------------
__device__ __forceinline__ const float* slot_w(int slot, const float* ipw,
                                               const float* w1, const float* w2, int& n)
{
    int t = slot / 6, l = slot - t * 6;
    if (t == 0) { n = 3 * D * D; return ipw + (size_t)l * 3 * D * D; }
    n = F * D;
    return (t == 1) ? w1 + (size_t)l * F * D : w2 + (size_t)l * F * D;
}

__global__ void k_etch_all(const float* __restrict__ ipw, const float* __restrict__ w1,
                           const float* __restrict__ w2)
{
    int slot = blockIdx.y;
    int n;
    const float* w = slot_w(slot, ipw, w1, w2, n);
    float inv = 1.f / (float)(n - 1);
    float* aout = d_abs_all + (size_t)slot * SLOT_STRIDE;
    unsigned* h1 = d_h1g + slot * 4096;

    __shared__ unsigned h[4096];
    for (int j = threadIdx.x; j < 4096; j += blockDim.x) h[j] = 0;
    __syncthreads();
    int stride = gridDim.x * blockDim.x;
    for (int i = blockIdx.x * blockDim.x + threadIdx.x; i < n; i += stride) {
        float wv = w[i];
        float b0 = __sinf(wv * PI_F);
        b0 = fminf(fmaxf(b0, -1.f), 1.f);
        float bl = b0 + b0 * __cosf((float)i * inv + THIRD_F) * 1.5f;
        float e = __cosf(bl * PI2_F) + bl * bl * DEVPI_F;
        float a = fabsf(e);
        aout[i] = a;
        atomicAdd(&h[__float_as_uint(a) >> 20], 1u);
    }
    __syncthreads();
    for (int j = threadIdx.x; j < 4096; j += blockDim.x) {
        unsigned c = h[j];
        if (c) atomicAdd(&h1[j], c);
    }
}

__global__ void k_scan1_all(const float* ipw, const float* w1, const float* w2)
{
    int slot = blockIdx.x;
    int n; slot_w(slot, ipw, w1, w2, n);
    unsigned rA = (unsigned)((n - 1) >> 2);
    unsigned rB = rA + 1;
    const unsigned* h1 = d_h1g + slot * 4096;
    unsigned* sel = d_selg + slot * 8;

    __shared__ unsigned part[256];
    __shared__ unsigned pref[256];
    int t = threadIdx.x, base = t * 16;
    unsigned c[16]; unsigned s = 0;
    for (int j = 0; j < 16; j++) { c[j] = h1[base + j]; s += c[j]; }
    part[t] = s; __syncthreads();
    if (t == 0) { unsigned a = 0; for (int i = 0; i < 256; i++) { pref[i] = a; a += part[i]; } }
    __syncthreads();
    unsigned p = pref[t];
    for (int j = 0; j < 16; j++) {
        if (rA >= p && rA < p + c[j]) { sel[0] = base + j; sel[1] = rA - p; }
        if (rB >= p && rB < p + c[j]) { sel[2] = base + j; sel[3] = rB - p; }
        p += c[j];
    }
}

// level 2: bits [10,20), smem-privatized 2x1024 bins
__global__ void k_hist2_all(const float* ipw, const float* w1, const float* w2)
{
    int slot = blockIdx.y;
    int n; slot_w(slot, ipw, w1, w2, n);
    const uint4* ab = (const uint4*)(d_abs_all + (size_t)slot * SLOT_STRIDE);
    const unsigned* sel = d_selg + slot * 8;
    unsigned sA = sel[0], sB = sel[2];

    __shared__ unsigned hA[1024], hB[1024];
    for (int j = threadIdx.x; j < 1024; j += 256) { hA[j] = 0; hB[j] = 0; }
    __syncthreads();

    int n4 = n >> 2;
    int stride = gridDim.x * blockDim.x;
    for (int i = blockIdx.x * blockDim.x + threadIdx.x; i < n4; i += stride) {
        uint4 u = ab[i];
        #pragma unroll
        for (int q = 0; q < 4; q++) {
            unsigned v = (q == 0) ? u.x : (q == 1) ? u.y : (q == 2) ? u.z : u.w;
            unsigned hi = v >> 20, m = (v >> 10) & 1023u;
            if (hi == sA) atomicAdd(&hA[m], 1u);
            if (hi == sB) atomicAdd(&hB[m], 1u);
        }
    }
    __syncthreads();
    unsigned* g2 = d_h2g + slot * 2048;
    for (int j = threadIdx.x; j < 1024; j += 256) {
        if (hA[j]) atomicAdd(&g2[j], hA[j]);
        if (hB[j]) atomicAdd(&g2[1024 + j], hB[j]);
    }
}

__global__ void k_scan2_all()
{
    int slot = blockIdx.x;
    unsigned* sel = d_selg + slot * 8;
    __shared__ unsigned part[256];
    __shared__ unsigned pref[256];
    int t = threadIdx.x;
    for (int sidx = 0; sidx < 2; sidx++) {
        unsigned rank = sel[1 + sidx * 2];
        const unsigned* hb = d_h2g + slot * 2048 + sidx * 1024;
        int base = t * 4;
        unsigned c[4]; unsigned s = 0;
        for (int j = 0; j < 4; j++) { c[j] = hb[base + j]; s += c[j]; }
        part[t] = s; __syncthreads();
        if (t == 0) { unsigned a = 0; for (int i = 0; i < 256; i++) { pref[i] = a; a += part[i]; } }
        __syncthreads();
        unsigned p = pref[t];
        for (int j = 0; j < 4; j++) {
            if (rank >= p && rank < p + c[j]) { sel[4 + sidx*2] = base + j; sel[5 + sidx*2] = rank - p; }
            p += c[j];
        }
        __syncthreads();
    }
}

// level 3: match 22-bit prefix, bins = bits [0,10) (global atomics, few matches)
__global__ void k_hist3_all(const float* ipw, const float* w1, const float* w2)
{
    int slot = blockIdx.y;
    int n; slot_w(slot, ipw, w1, w2, n);
    const uint4* ab = (const uint4*)(d_abs_all + (size_t)slot * SLOT_STRIDE);
    const unsigned* sel = d_selg + slot * 8;
    unsigned* h3 = d_h3g + slot * 2048;
    unsigned kA = (sel[0] << 10) | sel[4];
    unsigned kB = (sel[2] << 10) | sel[6];
    int n4 = n >> 2;
    int stride = gridDim.x * blockDim.x;
    for (int i = blockIdx.x * blockDim.x + threadIdx.x; i < n4; i += stride) {
        uint4 u = ab[i];
        #pragma unroll
        for (int q = 0; q < 4; q++) {
            unsigned v = (q == 0) ? u.x : (q == 1) ? u.y : (q == 2) ? u.z : u.w;
            unsigned top = v >> 10;
            if (top == kA) atomicAdd(&h3[v & 1023u], 1u);
            if (top == kB) atomicAdd(&h3[1024 + (v & 1023u)], 1u);
        }
    }
}

// resolve last 10 bits: one warp per slot walks the 1024-bin L3 histogram
__global__ void k_thr_all(const float* ipw, const float* w1, const float* w2)
{
    int slot = blockIdx.x;
    int lane = threadIdx.x;
    int n; slot_w(slot, ipw, w1, w2, n);
    float frac = 0.25f * (float)((n - 1) & 3);
    const unsigned* sel = d_selg + slot * 8;
    __shared__ unsigned fnd[2];

    for (int sidx = 0; sidx < 2; sidx++) {
        unsigned rank = sel[5 + sidx * 2];
        const unsigned* hb = d_h3g + slot * 2048 + sidx * 1024;
        unsigned s = 0;
        unsigned c[32];
        for (int j = 0; j < 32; j++) { c[j] = hb[lane * 32 + j]; s += c[j]; }
        unsigned p = s;
        for (int o = 1; o < 32; o <<= 1) {
            unsigned t2 = __shfl_up_sync(0xFFFFFFFF, p, o);
            if (lane >= o) p += t2;
        }
        p -= s;
        for (int j = 0; j < 32; j++) {
            if (rank >= p && rank < p + c[j]) fnd[sidx] = lane * 32 + j;
            p += c[j];
        }
        __syncthreads();
    }
    if (lane == 0) {
        float vA = __uint_as_float((sel[0] << 20) | (sel[4] << 10) | fnd[0]);
        float vB = __uint_as_float((sel[2] << 20) | (sel[6] << 10) | fnd[1]);
        d_thrg[slot] = vA + frac * (vB - vA);
    }
}

__global__ void k_mask_all(const float* __restrict__ ipw, const float* __restrict__ w1,
                           const float* __restrict__ w2)
{
    int slot = blockIdx.y;
    int n;
    const float* w = slot_w(slot, ipw, w1, w2, n);
    const uint4*  av4 = (const uint4*)(d_abs_all + (size_t)slot * SLOT_STRIDE);
    const float4* wv4 = (const float4*)w;
    float4* ov4 = (float4*)(d_wp + (size_t)slot * SLOT_STRIDE);
    float thr = d_thrg[slot];
    int n4 = n >> 2;
    int stride = gridDim.x * blockDim.x;
    for (int i = blockIdx.x * blockDim.x + threadIdx.x; i < n4; i += stride) {
        uint4 a = av4[i];
        float4 wv = wv4[i];
        float4 o;
        o.x = (__uint_as_float(a.x) > thr) ? tf32r(wv.x) : 0.f;
        o.y = (__uint_as_float(a.y) > thr) ? tf32r(wv.y) : 0.f;
        o.z = (__uint_as_float(a.z) > thr) ? tf32r(wv.z) : 0.f;
        o.w = (__uint_as_float(a.w) > thr) ? tf32r(wv.w) : 0.f;
        ov4[i] = o;
    }
}

// ---------------- entry point ----------------
extern "C" void kernel_launch(void* const* d_in, const int* in_sizes, int n_in,
                              void* d_out, int out_size)
{
    const int*   src = (const int*)  d_in[0];
    const float* emb = (const float*)d_in[1];
    const float* pos = (const float*)d_in[2];
    const float* ipw = (const float*)d_in[3];
    const float* ipb = (const float*)d_in[4];
    const float* opw = (const float*)d_in[5];
    const float* opb = (const float*)d_in[6];
    const float* l1g = (const float*)d_in[7];
    const float* l1b = (const float*)d_in[8];
    const float* l2g = (const float*)d_in[9];
    const float* l2b = (const float*)d_in[10];
    const float* w1  = (const float*)d_in[11];
    const float* b1  = (const float*)d_in[12];
    const float* w2  = (const float*)d_in[13];
    const float* b2  = (const float*)d_in[14];
    const float* ow  = (const float*)d_in[15];
    const float* ob  = (const float*)d_in[16];
    const int V = in_sizes[16];
    float* out = (float*)d_out;

    float *px, *pxtf, *pqkv, *pao, *pff, *ptmp, *pwp, *pwr, *powr;
    cudaGetSymbolAddress((void**)&px,   d_x);
    cudaGetSymbolAddress((void**)&pxtf, d_xtf);
    cudaGetSymbolAddress((void**)&pqkv, d_qkv);
    cudaGetSymbolAddress((void**)&pao,  d_ao);
    cudaGetSymbolAddress((void**)&pff,  d_ff);
    cudaGetSymbolAddress((void**)&ptmp, d_tmp);
    cudaGetSymbolAddress((void**)&pwp,  d_wp);
    cudaGetSymbolAddress((void**)&pwr,  d_wr);
    cudaGetSymbolAddress((void**)&powr, d_owr);

    cudaFuncAttributes fa{};
    cudaFuncGetAttributes(&fa, k_tc<false,false,false,false>);
    const bool use_tc = fa.numRegs > 40;

    if (use_tc) {
        cudaFuncSetAttribute(k_tc<false,false,false,false>, cudaFuncAttributeMaxDynamicSharedMemorySize, TC_SMEM);
        cudaFuncSetAttribute(k_tc<false,false,true ,true >, cudaFuncAttributeMaxDynamicSharedMemorySize, TC_SMEM);
        cudaFuncSetAttribute(k_tc<true ,false,true ,true >, cudaFuncAttributeMaxDynamicSharedMemorySize, TC_SMEM);
        cudaFuncSetAttribute(k_tc<false,true ,false,true >, cudaFuncAttributeMaxDynamicSharedMemorySize, TC_SMEM);
    }
    cudaFuncSetAttribute(k_attn, cudaFuncAttributeMaxDynamicSharedMemorySize, AT_SMEM);

    // fused prep: embed + round static weights + zero histograms
    int prepN = MT * D;
    if (V * D > prepN) prepN = V * D;
    k_prep<<<(prepN + 255) / 256, 256>>>(src, emb, pos, px, pxtf, opw, ow, V * D);

    k_etch_all <<<dim3(128, NSLOT), 256>>>(ipw, w1, w2);
    k_scan1_all<<<NSLOT, 256>>>(ipw, w1, w2);
    k_hist2_all<<<dim3(64, NSLOT), 256>>>(ipw, w1, w2);
    k_scan2_all<<<NSLOT, 256>>>();
    k_hist3_all<<<dim3(128, NSLOT), 256>>>(ipw, w1, w2);
    k_thr_all  <<<NSLOT, 32>>>(ipw, w1, w2);
    k_mask_all <<<dim3(512, NSLOT), 256>>>(ipw, w1, w2);

    for (int l = 0; l < L; l++) {
        const float* wi_l = pwp + (size_t)(0 * 6 + l) * SLOT_STRIDE;
        const float* w1_l = pwp + (size_t)(1 * 6 + l) * SLOT_STRIDE;
        const float* w2_l = pwp + (size_t)(2 * 6 + l) * SLOT_STRIDE;

        // qkv = x @ wi^T + b (dual-M, output tf32-rounded: feeds attention)
        if (use_tc)
            k_tc<false,false,true,true><<<dim3((3*D)/TC_BN, MT/256), TC_NT, TC_SMEM>>>(
                3*D, D, pxtf, D, wi_l, D, pqkv, 3*D, ipb + (size_t)l * 3 * D);
        else
            k_mma<128,128,2,2,true,false,false,true><<<dim3((3*D)/128, MT/128, 1), 128>>>(
                MT, 3*D, D, pxtf, D, 0, 0, wi_l, D, 0, 0, pqkv, 3*D, 0, 0, 1,
                ipb + (size_t)l * 3 * D, 1.f);

        // fused flash attention
        k_attn<<<dim3(4, BH), 256, AT_SMEM>>>(pqkv, pao);

        // out projection (single-M: keeps grid at 128 CTAs)
        if (use_tc)
            k_tc<false,false,false,false><<<dim3(D/TC_BN, MT/128), TC_NT, TC_SMEM>>>(
                D, D, pao, D, pwr + (size_t)l*D*D, D, ptmp, D, opb + (size_t)l*D);
        else
            k_mma<128,128,2,2,true,false,false,false><<<dim3(D/128, MT/128, 1), 128>>>(
                MT, D, D, pao, D, 0, 0, pwr + (size_t)l*D*D, D, 0, 0,
                ptmp, D, 0, 0, 1, opb + (size_t)l*D, 1.f);
        k_add_ln<<<MT / 8, 256>>>(px, ptmp, l1g + (size_t)l*D, l1b + (size_t)l*D, px, pxtf);

        // feed-forward: ff1 dual-M, ff2 single-M
        if (use_tc) {
            k_tc<true,false,true,true><<<dim3(F/TC_BN, MT/256), TC_NT, TC_SMEM>>>(
                F, D, pxtf, D, w1_l, D, pff, F, b1 + (size_t)l*F);
            k_tc<false,false,false,false><<<dim3(D/TC_BN, MT/128), TC_NT, TC_SMEM>>>(
                D, F, pff, F, w2_l, F, ptmp, D, b2 + (size_t)l*D);
        } else {
            k_mma<128,128,2,2,true,true,false,true><<<dim3(F/128, MT/128, 1), 128>>>(
                MT, F, D, pxtf, D, 0, 0, w1_l, D, 0, 0, pff, F, 0, 0, 1,
                b1 + (size_t)l*F, 1.f);
            k_mma<128,128,2,2,true,false,false,false><<<dim3(D/128, MT/128, 1), 128>>>(
                MT, D, F, pff, F, 0, 0, w2_l, F, 0, 0, ptmp, D, 0, 0, 1,
                b2 + (size_t)l*D, 1.f);
        }
        k_add_ln<<<MT / 8, 256>>>(px, ptmp, l2g + (size_t)l*D, l2b + (size_t)l*D, px, pxtf);
    }

    // logits (dual-M, N guarded)
    if (use_tc)
        k_tc<false,true,false,true><<<dim3((V + TC_BN - 1)/TC_BN, MT/256), TC_NT, TC_SMEM>>>(
            V, D, pxtf, D, powr, D, out, V, ob);
    else
        k_mma<128,128,2,2,true,false,true,false><<<dim3((V + 127) / 128, MT / 128, 1), 128>>>(
            MT, V, D, pxtf, D, 0, 0, powr, D, 0, 0, out, V, 0, 0, 1, ob, 1.f);
}